// round 8
// baseline (speedup 1.0000x reference)
#include <cuda_runtime.h>
#include <cuda_bf16.h>
#include <cuda_fp16.h>
#include <math.h>
#include <stdint.h>

#define NROWS 131072
#define ACT_D 12
#define COND_D 256
#define KCB 256
#define ED 16
#define H1D 512
#define H2D 256

// encoder (fp16 single-pass) K layouts
#define KE1 288      // enc1 input K=268 padded
#define KE2 512      // enc2 input
// decoder (bf16 [hi|lo] 3-term) layouts
#define KP1 288
#define KA1 576      // dec1 input (K=272 padded)
#define KP4 256
#define KA4 512      // dec2 input (K=256)

#define GAP_TAU 8e-3f

// ---------------- scratch (static device globals; no allocs) ----------------
__device__ __half         g_A1 [(size_t)NROWS * KE1];
__device__ __half         g_Ah1[(size_t)NROWS * KE2];
__device__ __half         g_B1h[(size_t)H1D * KE1];
__device__ __half         g_B2h[(size_t)H2D * KE2];
__device__ __nv_bfloat16 g_A3 [(size_t)NROWS * KA1];
__device__ __nv_bfloat16 g_Ad1[(size_t)NROWS * KA4];
__device__ __nv_bfloat16 g_B3 [(size_t)H2D * KA1];
__device__ __nv_bfloat16 g_B4 [(size_t)H1D * KA4];
__device__ float g_h2  [(size_t)NROWS * H2D];
__device__ float g_z   [(size_t)NROWS * ED];
__device__ float g_dist[(size_t)KCB * NROWS];   // transposed: [k][n]
__device__ float g_d2  [(size_t)NROWS * H1D];
__device__ double g_qlat, g_contra, g_recon;
__device__ int    g_counts[KCB];
__device__ int    g_ncand;
__device__ int    g_cand[NROWS];

// ---------------- helpers ----------------
__device__ __forceinline__ uint32_t smem_u32(const void* p) {
    uint32_t a;
    asm("{ .reg .u64 t; cvta.to.shared.u64 t, %1; cvt.u32.u64 %0, t; }"
        : "=r"(a) : "l"(p));
    return a;
}
__device__ __forceinline__ void cp_async16(uint32_t s, const void* g) {
    asm volatile("cp.async.cg.shared.global [%0], [%1], 16;" :: "r"(s), "l"(g) : "memory");
}
__device__ __forceinline__ void cp_commit() {
    asm volatile("cp.async.commit_group;" ::: "memory");
}
template <int N>
__device__ __forceinline__ void cp_wait() {
    asm volatile("cp.async.wait_group %0;" :: "n"(N) : "memory");
}
__device__ __forceinline__ void ldmx4(uint32_t& r0, uint32_t& r1, uint32_t& r2, uint32_t& r3,
                                      uint32_t addr) {
    asm volatile("ldmatrix.sync.aligned.m8n8.x4.shared.b16 {%0,%1,%2,%3}, [%4];"
                 : "=r"(r0), "=r"(r1), "=r"(r2), "=r"(r3) : "r"(addr));
}
template <int F16>
__device__ __forceinline__ void mma_any(float* c, const uint32_t* a, const uint32_t* b) {
    if (F16)
        asm volatile("mma.sync.aligned.m16n8k16.row.col.f32.f16.f16.f32 "
                     "{%0,%1,%2,%3}, {%4,%5,%6,%7}, {%8,%9}, {%0,%1,%2,%3};"
                     : "+f"(c[0]), "+f"(c[1]), "+f"(c[2]), "+f"(c[3])
                     : "r"(a[0]), "r"(a[1]), "r"(a[2]), "r"(a[3]), "r"(b[0]), "r"(b[1]));
    else
        asm volatile("mma.sync.aligned.m16n8k16.row.col.f32.bf16.bf16.f32 "
                     "{%0,%1,%2,%3}, {%4,%5,%6,%7}, {%8,%9}, {%0,%1,%2,%3};"
                     : "+f"(c[0]), "+f"(c[1]), "+f"(c[2]), "+f"(c[3])
                     : "r"(a[0]), "r"(a[1]), "r"(a[2]), "r"(a[3]), "r"(b[0]), "r"(b[1]));
}
__device__ __forceinline__ unsigned fkey(float x) {
    unsigned u = __float_as_uint(x);
    return (u & 0x80000000u) ? ~u : (u | 0x80000000u);
}
__device__ __forceinline__ float finv(unsigned k) {
    return (k & 0x80000000u) ? __uint_as_float(k & 0x7fffffffu)
                             : __uint_as_float(~k);
}

// ---------------- init ----------------
__global__ void init_kernel(int* counts, double* a, double* b, double* c, int* ncand) {
    int t = threadIdx.x;
    counts[t] = 0;
    if (t == 0) { *a = 0.0; *b = 0.0; *c = 0.0; *ncand = 0; }
}

// ---------------- conversions ----------------
// fp16 concat (no split): out[row][KP] = fp16(concat(a, b)) padded
__global__ void conv_cat_f16(const float* __restrict__ a, int ad,
                             const float* __restrict__ b, int bd,
                             __half* __restrict__ o, int KP)
{
    int pairs = KP >> 1;
    size_t t = (size_t)blockIdx.x * 256 + threadIdx.x;
    size_t row = t / pairs;
    if (row >= NROWS) return;
    int p = (int)(t % pairs);
    int j = p * 2;
    float v0, v1;
    if (j + 1 < ad)           { v0 = a[row * ad + j];        v1 = a[row * ad + j + 1]; }
    else if (j + 1 < ad + bd) { v0 = b[row * bd + (j - ad)]; v1 = b[row * bd + (j - ad) + 1]; }
    else                      { v0 = 0.f; v1 = 0.f; }
    ((__half2*)(o + row * (size_t)KP))[p] = __floats2half2_rn(v0, v1);
}
// fp16 weights: W[K][Nn] -> o[n][KP]
__global__ void conv_w_f16(const float* __restrict__ W, int K, int Nn,
                           __half* __restrict__ o, int KP)
{
    size_t t = (size_t)blockIdx.x * 256 + threadIdx.x;
    if (t >= (size_t)Nn * KP) return;
    int n = (int)(t / KP);
    int k = (int)(t % KP);
    float v = (k < K) ? W[(size_t)k * Nn + n] : 0.f;
    o[(size_t)n * KP + k] = __float2half(v);
}
// bf16 split concat: out[row][2KP] = [hi | lo]
__global__ void conv_cat_kernel(const float* __restrict__ a, int ad,
                                const float* __restrict__ b, int bd,
                                __nv_bfloat16* __restrict__ o, int KP, int KA)
{
    int pairs = KP >> 1;
    size_t t = (size_t)blockIdx.x * 256 + threadIdx.x;
    size_t row = t / pairs;
    if (row >= NROWS) return;
    int p = (int)(t % pairs);
    int j = p * 2;
    float v0, v1;
    if (j + 1 < ad)           { v0 = a[row * ad + j];        v1 = a[row * ad + j + 1]; }
    else if (j + 1 < ad + bd) { v0 = b[row * bd + (j - ad)]; v1 = b[row * bd + (j - ad) + 1]; }
    else if (j < ad + bd)     { v0 = b[row * bd + (j - ad)]; v1 = 0.f; }
    else                      { v0 = 0.f; v1 = 0.f; }
    __nv_bfloat162 hh, ll;
    hh.x = __float2bfloat16(v0); hh.y = __float2bfloat16(v1);
    ll.x = __float2bfloat16(v0 - __bfloat162float(hh.x));
    ll.y = __float2bfloat16(v1 - __bfloat162float(hh.y));
    __nv_bfloat16* base = o + row * (size_t)KA;
    ((__nv_bfloat162*)(base))[p]      = hh;
    ((__nv_bfloat162*)(base + KP))[p] = ll;
}
// bf16 split weights: W[K][Nn] -> o[n][KA] = [hi | lo]
__global__ void conv_w_kernel(const float* __restrict__ W, int K, int Nn,
                              __nv_bfloat16* __restrict__ o, int KP, int KA)
{
    size_t t = (size_t)blockIdx.x * 256 + threadIdx.x;
    if (t >= (size_t)Nn * KA) return;
    int n  = (int)(t / KA);
    int kt = (int)(t % KA);
    int s  = kt < KP ? 0 : 1;
    int k  = kt - s * KP;
    float v = (k < K) ? W[(size_t)k * Nn + n] : 0.f;
    __nv_bfloat16 h = __float2bfloat16(v);
    __nv_bfloat16 r = s ? __float2bfloat16(v - __bfloat162float(h)) : h;
    o[(size_t)n * KA + kt] = r;
}

// ---------------- tensor-core GEMM: 128x256 CTA tile, 16 warps ----------------
// NT=3: bf16 [hi|lo] operands, 3-term compensated. NT=1: single-pass (fp16).
// OUTM 0: fp32 out (bias+ELU); 1: bf16 [hi|lo] out (seg KPn); 2: fp16 out (row KPn)
#define SROW 80
#define S_AHI 0
#define S_ALO 10240
#define S_BHI 20480
#define S_BLO 40960
#define STAGE 61440
#define TG_SMEM (2 * STAGE)

template <int KP, int OUTM, int NT, int F16>
__global__ __launch_bounds__(512, 1) void tgemm(
    const uint16_t* __restrict__ Ap,
    const uint16_t* __restrict__ Bp,
    const float* __restrict__ bias,
    float* __restrict__ Cf,
    uint16_t* __restrict__ Cb,
    int Nfull, int KPn)
{
    extern __shared__ __align__(16) uint8_t smem[];
    const uint32_t sm = smem_u32(smem);
    constexpr int KA = (NT == 3) ? 2 * KP : KP;

    const int tid = threadIdx.x;
    const int wid = tid >> 5, lane = tid & 31;
    const int wr = wid >> 3, wc = wid & 7;          // warps 2 x 8
    const size_t row0 = (size_t)blockIdx.y * 128;
    const int    col0 = blockIdx.x * 256;

    const int NCH = KP / 32;

    float acc[4][4][4];
#pragma unroll
    for (int i = 0; i < 4; i++)
#pragma unroll
        for (int j = 0; j < 4; j++)
#pragma unroll
            for (int e = 0; e < 4; e++) acc[i][j][e] = 0.f;

    auto load_chunk = [&](int c, int buf) {
        const int kc = c * 32;
        const uint32_t base = sm + buf * STAGE;
        {
            int row = tid >> 2, seg = tid & 3;
            const uint16_t* ga = Ap + (row0 + row) * (size_t)KA + kc + seg * 8;
            uint32_t so = row * SROW + seg * 16;
            cp_async16(base + S_AHI + so, ga);
            if (NT == 3) cp_async16(base + S_ALO + so, ga + KP);
        }
#pragma unroll
        for (int l = 0; l < 2; l++) {
            int L = tid + l * 512;
            int row = L >> 2, seg = L & 3;
            const uint16_t* gb = Bp + (size_t)(col0 + row) * KA + kc + seg * 8;
            uint32_t so = row * SROW + seg * 16;
            cp_async16(base + S_BHI + so, gb);
            if (NT == 3) cp_async16(base + S_BLO + so, gb + KP);
        }
        cp_commit();
    };

    load_chunk(0, 0);

    for (int c = 0; c < NCH; c++) {
        if (c + 1 < NCH) load_chunk(c + 1, (c + 1) & 1);
        if (c + 1 < NCH) cp_wait<1>(); else cp_wait<0>();
        __syncthreads();

        const uint32_t st = sm + (c & 1) * STAGE;
        const int g = lane >> 3, lr = lane & 7;

#pragma unroll
        for (int ks = 0; ks < 2; ks++) {
            const uint32_t acolo = (ks * 16 + (g >> 1) * 8) * 2;
            const uint32_t bcolo = (ks * 16 + (g & 1) * 8) * 2;
            uint32_t afh[4][4];
#pragma unroll
            for (int mt = 0; mt < 4; mt++) {
                int r = wr * 64 + mt * 16 + (g & 1) * 8 + lr;
                ldmx4(afh[mt][0], afh[mt][1], afh[mt][2], afh[mt][3],
                      st + S_AHI + r * SROW + acolo);
            }
            uint32_t bfh[4][2];
#pragma unroll
            for (int bt = 0; bt < 2; bt++) {
                int r = wc * 32 + bt * 16 + (g >> 1) * 8 + lr;
                uint32_t r0, r1, r2, r3;
                ldmx4(r0, r1, r2, r3, st + S_BHI + r * SROW + bcolo);
                bfh[bt * 2][0] = r0;     bfh[bt * 2][1] = r1;
                bfh[bt * 2 + 1][0] = r2; bfh[bt * 2 + 1][1] = r3;
            }
#pragma unroll
            for (int mt = 0; mt < 4; mt++)
#pragma unroll
                for (int nt = 0; nt < 4; nt++)
                    mma_any<F16>(acc[mt][nt], afh[mt], bfh[nt]);
            if (NT == 3) {
                // A-lo x B-hi
#pragma unroll
                for (int mt = 0; mt < 4; mt++) {
                    int r = wr * 64 + mt * 16 + (g & 1) * 8 + lr;
                    uint32_t al[4];
                    ldmx4(al[0], al[1], al[2], al[3], st + S_ALO + r * SROW + acolo);
#pragma unroll
                    for (int nt = 0; nt < 4; nt++)
                        mma_any<F16>(acc[mt][nt], al, bfh[nt]);
                }
                // A-hi x B-lo
#pragma unroll
                for (int bt = 0; bt < 2; bt++) {
                    int r = wc * 32 + bt * 16 + (g >> 1) * 8 + lr;
                    uint32_t r0, r1, r2, r3;
                    ldmx4(r0, r1, r2, r3, st + S_BLO + r * SROW + bcolo);
                    uint32_t bl0[2] = {r0, r1}, bl1[2] = {r2, r3};
#pragma unroll
                    for (int mt = 0; mt < 4; mt++) {
                        mma_any<F16>(acc[mt][bt * 2],     afh[mt], bl0);
                        mma_any<F16>(acc[mt][bt * 2 + 1], afh[mt], bl1);
                    }
                }
            }
        }
        __syncthreads();
    }

    // epilogue
#pragma unroll
    for (int mt = 0; mt < 4; mt++) {
        size_t ra = row0 + wr * 64 + mt * 16 + (lane >> 2);
        size_t rb = ra + 8;
#pragma unroll
        for (int nt = 0; nt < 4; nt++) {
            int colg = col0 + wc * 32 + nt * 8 + (lane & 3) * 2;
            float b0 = bias[colg], b1 = bias[colg + 1];
            float v00 = acc[mt][nt][0] + b0, v01 = acc[mt][nt][1] + b1;
            float v10 = acc[mt][nt][2] + b0, v11 = acc[mt][nt][3] + b1;
            v00 = (v00 > 0.f) ? v00 : expm1f(v00);
            v01 = (v01 > 0.f) ? v01 : expm1f(v01);
            v10 = (v10 > 0.f) ? v10 : expm1f(v10);
            v11 = (v11 > 0.f) ? v11 : expm1f(v11);
            if (OUTM == 0) {
                *(float2*)(Cf + ra * (size_t)Nfull + colg) = make_float2(v00, v01);
                *(float2*)(Cf + rb * (size_t)Nfull + colg) = make_float2(v10, v11);
            } else if (OUTM == 1) {
                const size_t KTn = 2 * (size_t)KPn;
                __nv_bfloat162 hh, ll;
                uint16_t* pa = Cb + ra * KTn;
                hh.x = __float2bfloat16(v00); hh.y = __float2bfloat16(v01);
                ll.x = __float2bfloat16(v00 - __bfloat162float(hh.x));
                ll.y = __float2bfloat16(v01 - __bfloat162float(hh.y));
                *(__nv_bfloat162*)(pa + colg)       = hh;
                *(__nv_bfloat162*)(pa + KPn + colg) = ll;
                uint16_t* pb = Cb + rb * KTn;
                hh.x = __float2bfloat16(v10); hh.y = __float2bfloat16(v11);
                ll.x = __float2bfloat16(v10 - __bfloat162float(hh.x));
                ll.y = __float2bfloat16(v11 - __bfloat162float(hh.y));
                *(__nv_bfloat162*)(pb + colg)       = hh;
                *(__nv_bfloat162*)(pb + KPn + colg) = ll;
            } else {
                uint16_t* pa = Cb + ra * (size_t)KPn;
                uint16_t* pb = Cb + rb * (size_t)KPn;
                *(__half2*)(pa + colg) = __floats2half2_rn(v00, v01);
                *(__half2*)(pb + colg) = __floats2half2_rn(v10, v11);
            }
        }
    }
}

// ---------------- narrow GEMM (N=16 or 12), fp32 SIMT ----------------
template <int NO, int KK, bool RLOSS>
__global__ __launch_bounds__(128) void ngemm_kernel(
    const float* __restrict__ A, const float* __restrict__ B,
    const float* __restrict__ bias, float* __restrict__ C,
    const float* __restrict__ ref, double* __restrict__ rloss)
{
    __shared__ float Bs[KK][NO];
    __shared__ float As[128][33];
    int tid = threadIdx.x;
    size_t row0 = (size_t)blockIdx.x * 128;
    for (int e = tid; e < KK * NO; e += 128) Bs[e / NO][e % NO] = B[e];
    float acc[NO];
#pragma unroll
    for (int j = 0; j < NO; j++) acc[j] = 0.f;

    for (int k0 = 0; k0 < KK; k0 += 32) {
        __syncthreads();
#pragma unroll
        for (int l = 0; l < 32; l++) {
            int e = tid + l * 128;
            int r = e >> 5, c = e & 31;
            As[r][c] = A[(row0 + r) * KK + k0 + c];
        }
        __syncthreads();
#pragma unroll
        for (int kk = 0; kk < 32; kk++) {
            float a = As[tid][kk];
#pragma unroll
            for (int j = 0; j < NO; j++) acc[j] = fmaf(a, Bs[k0 + kk][j], acc[j]);
        }
    }
    float rl = 0.f;
    size_t r = row0 + tid;
#pragma unroll
    for (int j = 0; j < NO; j++) {
        float v = acc[j] + bias[j];
        C[r * NO + j] = v;
        if (RLOSS) { float d = v - ref[r * NO + j]; rl += d * d; }
    }
    if (RLOSS) {
#pragma unroll
        for (int o = 16; o > 0; o >>= 1) rl += __shfl_down_sync(0xffffffffu, rl, o);
        __shared__ float ws[4];
        if ((tid & 31) == 0) ws[tid >> 5] = rl;
        __syncthreads();
        if (tid == 0) atomicAdd(rloss, (double)(ws[0] + ws[1] + ws[2] + ws[3]));
    }
}

// ---------------- quantize (+ near-tie candidate collection) ----------------
__global__ __launch_bounds__(256) void quantize_kernel(
    const float* __restrict__ z, const float* __restrict__ emb,
    float* __restrict__ out_q, float* __restrict__ out_idx,
    float* __restrict__ dist,
    int* __restrict__ counts, double* __restrict__ qlat,
    int* __restrict__ ncand, int* __restrict__ cand)
{
    __shared__ float embn[KCB][ED];
    __shared__ float zt[16][ED + 1];
    __shared__ float rinv[16];
    __shared__ float n2[16];
    __shared__ float sd[KCB][17];
    __shared__ int   shist[KCB];
    __shared__ float sq;
    int tid = threadIdx.x;
    size_t row0 = (size_t)blockIdx.x * 16;
    shist[tid] = 0;
    if (tid == 0) sq = 0.f;
    {
        float e[ED], s = 0.f;
#pragma unroll
        for (int j = 0; j < ED; j++) { e[j] = emb[tid * ED + j]; s += e[j] * e[j]; }
        float inv = 1.f / fmaxf(sqrtf(s), 1e-12f);
#pragma unroll
        for (int j = 0; j < ED; j++) embn[tid][j] = e[j] * inv;
    }
    { int r = tid >> 4, j = tid & 15; zt[r][j] = z[(row0 + r) * ED + j]; }
    __syncthreads();
    if (tid < 16) {
        float s = 0.f;
#pragma unroll
        for (int j = 0; j < ED; j++) s += zt[tid][j] * zt[tid][j];
        n2[tid] = s;
        rinv[tid] = 1.f / fmaxf(sqrtf(s), 1e-12f);
    }
    __syncthreads();
    for (int r = 0; r < 16; r++) {
        float s = 0.f;
#pragma unroll
        for (int j = 0; j < ED; j++) s += zt[r][j] * embn[tid][j];
        sd[tid][r] = s * rinv[r];
    }
    __syncthreads();
    int w = tid >> 5, lane = tid & 31;
    for (int c = 0; c < 32; c++) {
        int k = w * 32 + c;
        if (lane < 16) dist[(size_t)k * NROWS + row0 + lane] = sd[k][lane];
    }
    for (int rr = 0; rr < 2; rr++) {
        int r = w * 2 + rr;
        float best = -2.f; int bi = 0;
        for (int kk = lane; kk < KCB; kk += 32) {
            float v = sd[kk][r];
            if (v > best) { best = v; bi = kk; }
        }
#pragma unroll
        for (int o = 16; o > 0; o >>= 1) {
            float ov = __shfl_down_sync(0xffffffffu, best, o);
            int   oi = __shfl_down_sync(0xffffffffu, bi, o);
            if (ov > best || (ov == best && oi < bi)) { best = ov; bi = oi; }
        }
        bi   = __shfl_sync(0xffffffffu, bi, 0);
        best = __shfl_sync(0xffffffffu, best, 0);
        float sec = -2.f;
        for (int kk = lane; kk < KCB; kk += 32)
            if (kk != bi) sec = fmaxf(sec, sd[kk][r]);
#pragma unroll
        for (int o = 16; o > 0; o >>= 1)
            sec = fmaxf(sec, __shfl_down_sync(0xffffffffu, sec, o));
        float dd = 0.f;
        if (lane < ED) {
            float qv = emb[bi * ED + lane];
            float d = qv - zt[r][lane];
            out_q[(row0 + r) * ED + lane] = qv;
            dd = d * d;
        }
#pragma unroll
        for (int o = 16; o > 0; o >>= 1) dd += __shfl_down_sync(0xffffffffu, dd, o);
        if (lane == 0) {
            atomicAdd(&sq, dd);
            atomicAdd(&shist[bi], 1);
            out_idx[row0 + r] = (float)bi;
            if (best - sec < GAP_TAU || n2[r] < 4e-3f) {
                int s = atomicAdd(ncand, 1);
                cand[s] = (int)(row0 + r);
            }
        }
    }
    __syncthreads();
    if (shist[tid]) atomicAdd(&counts[tid], shist[tid]);
    if (tid == 0) atomicAdd(qlat, (double)sq);
}

// ---------------- exact fp32 re-check of near-tie rows ----------------
__global__ __launch_bounds__(128) void refine_kernel(
    const float* __restrict__ actions, const float* __restrict__ conditions,
    const float* __restrict__ ew1, const float* __restrict__ eb1,
    const float* __restrict__ ew2, const float* __restrict__ eb2,
    const float* __restrict__ ew3, const float* __restrict__ eb3,
    const float* __restrict__ emb,
    const float* __restrict__ zbf,
    float* __restrict__ out_q, float* __restrict__ out_idx,
    int* __restrict__ counts, double* __restrict__ qlat,
    const int* __restrict__ ncand, const int* __restrict__ cand)
{
    __shared__ float x[272];
    __shared__ float h1s[H1D];
    __shared__ float h2s[H2D];
    __shared__ float zs[ED];
    __shared__ float ds[KCB];
    __shared__ float zinv;
    __shared__ int   newidx;
    int tid = threadIdx.x;
    int n = *ncand;
    for (int ci = blockIdx.x; ci < n; ci += gridDim.x) {
        int row = cand[ci];
        for (int j = tid; j < 268; j += 128)
            x[j] = (j < ACT_D) ? actions[(size_t)row * ACT_D + j]
                               : conditions[(size_t)row * COND_D + (j - ACT_D)];
        __syncthreads();
        for (int c = tid; c < H1D; c += 128) {
            float s = eb1[c];
            for (int k = 0; k < 268; k++) s = fmaf(x[k], ew1[(size_t)k * H1D + c], s);
            h1s[c] = (s > 0.f) ? s : expm1f(s);
        }
        __syncthreads();
        for (int c = tid; c < H2D; c += 128) {
            float s = eb2[c];
            for (int k = 0; k < H1D; k++) s = fmaf(h1s[k], ew2[(size_t)k * H2D + c], s);
            h2s[c] = (s > 0.f) ? s : expm1f(s);
        }
        __syncthreads();
        if (tid < ED) {
            float s = eb3[tid];
            for (int k = 0; k < H2D; k++) s = fmaf(h2s[k], ew3[(size_t)k * ED + tid], s);
            zs[tid] = s;
        }
        __syncthreads();
        if (tid == 0) {
            float s = 0.f;
            for (int j = 0; j < ED; j++) s += zs[j] * zs[j];
            zinv = 1.f / fmaxf(sqrtf(s), 1e-12f);
        }
        __syncthreads();
        for (int c = tid; c < KCB; c += 128) {
            float e[ED], s = 0.f, dot = 0.f;
#pragma unroll
            for (int j = 0; j < ED; j++) { e[j] = emb[c * ED + j]; s += e[j] * e[j]; }
            float inv = 1.f / fmaxf(sqrtf(s), 1e-12f);
#pragma unroll
            for (int j = 0; j < ED; j++) dot += (zs[j] * zinv) * (e[j] * inv);
            ds[c] = dot;
        }
        __syncthreads();
        if (tid == 0) {
            float best = ds[0]; int bi = 0;
            for (int c = 1; c < KCB; c++)
                if (ds[c] > best) { best = ds[c]; bi = c; }
            newidx = bi;
        }
        __syncthreads();
        int oldidx = (int)out_idx[row];
        if (newidx != oldidx) {
            if (tid == 0) {
                out_idx[row] = (float)newidx;
                atomicSub(counts + oldidx, 1);
                atomicAdd(counts + newidx, 1);
                float dq = 0.f;
                for (int j = 0; j < ED; j++) {
                    float zb = zbf[(size_t)row * ED + j];
                    float dn = emb[newidx * ED + j] - zb;
                    float dl = emb[oldidx * ED + j] - zb;
                    dq += dn * dn - dl * dl;
                }
                atomicAdd(qlat, (double)dq);
            }
            if (tid < ED) out_q[(size_t)row * ED + tid] = emb[newidx * ED + tid];
        }
        __syncthreads();
    }
}

// ---------------- per-column order statistics + contra loss ----------------
__global__ __launch_bounds__(256) void select_kernel(
    const float* __restrict__ dist, double* __restrict__ contra)
{
    __shared__ unsigned ha[2048], hb[2048];
    __shared__ unsigned s_bin[2], s_rem[2];
    __shared__ float rf[256];
    int tid = threadIdx.x;
    const float* col = dist + (size_t)blockIdx.x * NROWS;
    const unsigned RA = NROWS / 2 - 1;
    const unsigned RB = NROWS - 512;

    for (int i = tid; i < 2048; i += 256) ha[i] = 0;
    __syncthreads();
    for (int i = tid; i < NROWS; i += 256) atomicAdd(&ha[fkey(col[i]) >> 21], 1u);
    __syncthreads();
    if (tid == 0) {
        unsigned c = 0;
        for (unsigned b = 0; b < 2048; b++) {
            unsigned h = ha[b];
            if (c <= RA && c + h > RA) { s_bin[0] = b; s_rem[0] = RA - c; }
            if (c <= RB && c + h > RB) { s_bin[1] = b; s_rem[1] = RB - c; }
            c += h;
        }
    }
    __syncthreads();
    unsigned p0a = s_bin[0], p0b = s_bin[1];
    unsigned rema = s_rem[0], remb = s_rem[1];
    __syncthreads();

    for (int i = tid; i < 2048; i += 256) { ha[i] = 0; hb[i] = 0; }
    __syncthreads();
    for (int i = tid; i < NROWS; i += 256) {
        unsigned u = fkey(col[i]);
        unsigned t = u >> 21, m = (u >> 10) & 2047u;
        if (t == p0a) atomicAdd(&ha[m], 1u);
        if (t == p0b) atomicAdd(&hb[m], 1u);
    }
    __syncthreads();
    if (tid == 0) { unsigned c = 0; for (unsigned b = 0; b < 2048; b++) { unsigned h = ha[b];
        if (c + h > rema) { s_bin[0] = b; s_rem[0] = rema - c; break; } c += h; } }
    if (tid == 1) { unsigned c = 0; for (unsigned b = 0; b < 2048; b++) { unsigned h = hb[b];
        if (c + h > remb) { s_bin[1] = b; s_rem[1] = remb - c; break; } c += h; } }
    __syncthreads();
    unsigned p1a = (p0a << 11) | s_bin[0], p1b = (p0b << 11) | s_bin[1];
    rema = s_rem[0]; remb = s_rem[1];
    __syncthreads();

    for (int i = tid; i < 1024; i += 256) { ha[i] = 0; hb[i] = 0; }
    __syncthreads();
    for (int i = tid; i < NROWS; i += 256) {
        unsigned u = fkey(col[i]);
        if ((u >> 10) == p1a) atomicAdd(&ha[u & 1023u], 1u);
        if ((u >> 10) == p1b) atomicAdd(&hb[u & 1023u], 1u);
    }
    __syncthreads();
    if (tid == 0) { unsigned c = 0; for (unsigned b = 0; b < 1024; b++) { unsigned h = ha[b];
        if (c + h > rema) { s_bin[0] = b; break; } c += h; } }
    if (tid == 1) { unsigned c = 0; for (unsigned b = 0; b < 1024; b++) { unsigned h = hb[b];
        if (c + h > remb) { s_bin[1] = b; break; } c += h; } }
    __syncthreads();
    unsigned km = (p1a << 10) | s_bin[0];
    unsigned kt = (p1b << 10) | s_bin[1];

    float Tmed = finv(km);
    const float INV_TAU = 1.0f / 0.07f;
    int cgt = 0, clt = 0;
    float sgt = 0.f, sexp = 0.f;
    for (int i = tid; i < NROWS; i += 256) {
        float x = col[i];
        unsigned u = fkey(x);
        if (u > kt) { cgt++; sgt += x; }
        if (u < km) { clt++; sexp += expf((x - Tmed) * INV_TAU); }
    }
    float CGT, SGT, CLT, SEXP;
    rf[tid] = (float)cgt; __syncthreads();
    for (int s = 128; s; s >>= 1) { if (tid < s) rf[tid] += rf[tid + s]; __syncthreads(); }
    CGT = rf[0]; __syncthreads();
    rf[tid] = sgt; __syncthreads();
    for (int s = 128; s; s >>= 1) { if (tid < s) rf[tid] += rf[tid + s]; __syncthreads(); }
    SGT = rf[0]; __syncthreads();
    rf[tid] = (float)clt; __syncthreads();
    for (int s = 128; s; s >>= 1) { if (tid < s) rf[tid] += rf[tid + s]; __syncthreads(); }
    CLT = rf[0]; __syncthreads();
    rf[tid] = sexp; __syncthreads();
    for (int s = 128; s; s >>= 1) { if (tid < s) rf[tid] += rf[tid + s]; __syncthreads(); }
    SEXP = rf[0];

    if (tid == 0) {
        float Ttop = finv(kt);
        float dis_pos = (SGT + (512.0f - CGT) * Ttop) * (1.0f / 512.0f);
        float Sx = SEXP + ((float)(NROWS / 2) - CLT);
        float a = dis_pos * INV_TAU, b = Tmed * INV_TAU;
        float m = fmaxf(a, b);
        float lse = m + logf(expf(a - m) + Sx * expf(b - m));
        atomicAdd(contra, (double)(lse - a));
    }
}

// ---------------- finalize scalars ----------------
__global__ void finalize_kernel(const int* __restrict__ counts,
                                const double* __restrict__ qlat,
                                const double* __restrict__ contra,
                                const double* __restrict__ recon,
                                float* __restrict__ out_sc)
{
    __shared__ float rr[256];
    int t = threadIdx.x;
    float p = (float)counts[t] / (float)NROWS;
    rr[t] = p * logf(p + 1e-10f);
    __syncthreads();
    for (int s = 128; s; s >>= 1) { if (t < s) rr[t] += rr[t + s]; __syncthreads(); }
    if (t == 0) {
        float q = (float)(*qlat / ((double)NROWS * ED));
        out_sc[0] = q;
        out_sc[1] = 0.25f * q;
        out_sc[2] = (float)(*contra / (double)KCB);
        out_sc[3] = expf(-rr[0]);
        out_sc[4] = (float)(*recon / ((double)NROWS * ACT_D));
    }
}

// ---------------- launch ----------------
extern "C" void kernel_launch(void* const* d_in, const int* in_sizes, int n_in,
                              void* d_out, int out_size)
{
    const float* actions    = (const float*)d_in[0];
    const float* conditions = (const float*)d_in[1];
    const float* enc_w1 = (const float*)d_in[2];  const float* enc_b1 = (const float*)d_in[3];
    const float* enc_w2 = (const float*)d_in[4];  const float* enc_b2 = (const float*)d_in[5];
    const float* enc_w3 = (const float*)d_in[6];  const float* enc_b3 = (const float*)d_in[7];
    const float* dec_w1 = (const float*)d_in[8];  const float* dec_b1 = (const float*)d_in[9];
    const float* dec_w2 = (const float*)d_in[10]; const float* dec_b2 = (const float*)d_in[11];
    const float* dec_w3 = (const float*)d_in[12]; const float* dec_b3 = (const float*)d_in[13];
    const float* embedding = (const float*)d_in[14];

    float* out = (float*)d_out;
    float* out_rec = out;
    float* out_q   = out + (size_t)NROWS * ACT_D;
    float* out_idx = out_q + (size_t)NROWS * ED;
    float* out_sc  = out_idx + NROWS;

    __half *A1, *Ah1, *B1h, *B2h;
    __nv_bfloat16 *A3, *Ad1, *B3, *B4;
    float *h2, *z, *dist, *d2;
    double *qlat, *contra, *recon; int *counts, *ncand, *cand;
    cudaGetSymbolAddress((void**)&A1,  g_A1);
    cudaGetSymbolAddress((void**)&Ah1, g_Ah1);
    cudaGetSymbolAddress((void**)&B1h, g_B1h);
    cudaGetSymbolAddress((void**)&B2h, g_B2h);
    cudaGetSymbolAddress((void**)&A3,  g_A3);
    cudaGetSymbolAddress((void**)&Ad1, g_Ad1);
    cudaGetSymbolAddress((void**)&B3,  g_B3);
    cudaGetSymbolAddress((void**)&B4,  g_B4);
    cudaGetSymbolAddress((void**)&h2,  g_h2);
    cudaGetSymbolAddress((void**)&z,   g_z);
    cudaGetSymbolAddress((void**)&dist,g_dist);
    cudaGetSymbolAddress((void**)&d2,  g_d2);
    cudaGetSymbolAddress((void**)&qlat,  g_qlat);
    cudaGetSymbolAddress((void**)&contra,g_contra);
    cudaGetSymbolAddress((void**)&recon, g_recon);
    cudaGetSymbolAddress((void**)&counts,g_counts);
    cudaGetSymbolAddress((void**)&ncand, g_ncand);
    cudaGetSymbolAddress((void**)&cand,  g_cand);

    cudaFuncSetAttribute((const void*)tgemm<KE1, 2, 1, 1>, cudaFuncAttributeMaxDynamicSharedMemorySize, TG_SMEM);
    cudaFuncSetAttribute((const void*)tgemm<KE2, 0, 1, 1>, cudaFuncAttributeMaxDynamicSharedMemorySize, TG_SMEM);
    cudaFuncSetAttribute((const void*)tgemm<KP1, 1, 3, 0>, cudaFuncAttributeMaxDynamicSharedMemorySize, TG_SMEM);
    cudaFuncSetAttribute((const void*)tgemm<KP4, 0, 3, 0>, cudaFuncAttributeMaxDynamicSharedMemorySize, TG_SMEM);

    init_kernel<<<1, 256>>>(counts, qlat, contra, recon, ncand);

    // weight conversions
    conv_w_f16<<<((size_t)H1D * KE1 + 255) / 256, 256>>>(enc_w1, 268, H1D, B1h, KE1);
    conv_w_f16<<<((size_t)H2D * KE2 + 255) / 256, 256>>>(enc_w2, 512, H2D, B2h, KE2);
    conv_w_kernel<<<((size_t)H2D * KA1 + 255) / 256, 256>>>(dec_w1, 272, H2D, B3, KP1, KA1);
    conv_w_kernel<<<((size_t)H1D * KA4 + 255) / 256, 256>>>(dec_w2, 256, H1D, B4, KP4, KA4);

    // encoder input (fp16, no split)
    conv_cat_f16<<<((size_t)NROWS * (KE1 / 2) + 255) / 256, 256>>>(
        actions, ACT_D, conditions, COND_D, A1, KE1);

    // enc1: 268 -> 512 (fp16 single-pass, fp16 out)
    tgemm<KE1, 2, 1, 1><<<dim3(2, NROWS / 128), 512, TG_SMEM>>>(
        (const uint16_t*)A1, (const uint16_t*)B1h, enc_b1, nullptr, (uint16_t*)Ah1, H1D, KE2);
    // enc2: 512 -> 256 (fp16 single-pass, fp32 out)
    tgemm<KE2, 0, 1, 1><<<dim3(1, NROWS / 128), 512, TG_SMEM>>>(
        (const uint16_t*)Ah1, (const uint16_t*)B2h, enc_b2, h2, nullptr, H2D, 0);
    // enc3: 256 -> 16 (fp32 SIMT, no ELU)
    ngemm_kernel<ED, H2D, false><<<NROWS / 128, 128>>>(h2, enc_w3, enc_b3, z, nullptr, nullptr);

    quantize_kernel<<<NROWS / 16, 256>>>(z, embedding, out_q, out_idx, dist, counts, qlat,
                                         ncand, cand);
    refine_kernel<<<1024, 128>>>(actions, conditions,
                                 enc_w1, enc_b1, enc_w2, enc_b2, enc_w3, enc_b3,
                                 embedding, z, out_q, out_idx, counts, qlat, ncand, cand);
    select_kernel<<<KCB, 256>>>(dist, contra);

    // decoder input (bf16 split) — after refine
    conv_cat_kernel<<<((size_t)NROWS * (KP1 / 2) + 255) / 256, 256>>>(
        out_q, ED, conditions, COND_D, A3, KP1, KA1);

    // dec1: 272 -> 256 (bf16 3-term, [hi|lo] out)
    tgemm<KP1, 1, 3, 0><<<dim3(1, NROWS / 128), 512, TG_SMEM>>>(
        (const uint16_t*)A3, (const uint16_t*)B3, dec_b1, nullptr, (uint16_t*)Ad1, H2D, KP4);
    // dec2: 256 -> 512 (bf16 3-term, fp32 out)
    tgemm<KP4, 0, 3, 0><<<dim3(2, NROWS / 128), 512, TG_SMEM>>>(
        (const uint16_t*)Ad1, (const uint16_t*)B4, dec_b2, d2, nullptr, H1D, 0);
    // dec3: 512 -> 12 + reconstruction loss
    ngemm_kernel<ACT_D, H1D, true><<<NROWS / 128, 128>>>(d2, dec_w3, dec_b3, out_rec, actions, recon);

    finalize_kernel<<<1, 256>>>(counts, qlat, contra, recon, out_sc);
}

// round 9
// speedup vs baseline: 1.0955x; 1.0955x over previous
#include <cuda_runtime.h>
#include <cuda_bf16.h>
#include <cuda_fp16.h>
#include <math.h>
#include <stdint.h>

#define NROWS 131072
#define ACT_D 12
#define COND_D 256
#define KCB 256
#define ED 16
#define H1D 512
#define H2D 256

// encoder (fp16 single-pass) K layouts
#define KE1 288      // enc1 input K=268 padded
#define KE2 512      // enc2 input
// decoder (bf16 [hi|lo] 3-term) layouts
#define KP1 288
#define KA1 576      // dec1 input (K=272 padded)
#define KP4 256
#define KA4 512      // dec2 input (K=256)

#define GAP_TAU 8e-3f
#define RB 16        // refine batch rows per block

// ---------------- scratch (static device globals; no allocs) ----------------
__device__ __half         g_A1 [(size_t)NROWS * KE1];
__device__ __half         g_Ah1[(size_t)NROWS * KE2];
__device__ __half         g_B1h[(size_t)H1D * KE1];
__device__ __half         g_B2h[(size_t)H2D * KE2];
__device__ __nv_bfloat16 g_A3 [(size_t)NROWS * KA1];
__device__ __nv_bfloat16 g_Ad1[(size_t)NROWS * KA4];
__device__ __nv_bfloat16 g_B3 [(size_t)H2D * KA1];
__device__ __nv_bfloat16 g_B4 [(size_t)H1D * KA4];
__device__ float g_h2  [(size_t)NROWS * H2D];
__device__ float g_z   [(size_t)NROWS * ED];
__device__ float g_dist[(size_t)KCB * NROWS];   // transposed: [k][n]
__device__ float g_d2  [(size_t)NROWS * H1D];
__device__ double g_qlat, g_contra, g_recon;
__device__ int    g_counts[KCB];
__device__ int    g_ncand;
__device__ int    g_cand[NROWS];

// ---------------- helpers ----------------
__device__ __forceinline__ uint32_t smem_u32(const void* p) {
    uint32_t a;
    asm("{ .reg .u64 t; cvta.to.shared.u64 t, %1; cvt.u32.u64 %0, t; }"
        : "=r"(a) : "l"(p));
    return a;
}
__device__ __forceinline__ void cp_async16(uint32_t s, const void* g) {
    asm volatile("cp.async.cg.shared.global [%0], [%1], 16;" :: "r"(s), "l"(g) : "memory");
}
__device__ __forceinline__ void cp_commit() {
    asm volatile("cp.async.commit_group;" ::: "memory");
}
template <int N>
__device__ __forceinline__ void cp_wait() {
    asm volatile("cp.async.wait_group %0;" :: "n"(N) : "memory");
}
__device__ __forceinline__ void ldmx4(uint32_t& r0, uint32_t& r1, uint32_t& r2, uint32_t& r3,
                                      uint32_t addr) {
    asm volatile("ldmatrix.sync.aligned.m8n8.x4.shared.b16 {%0,%1,%2,%3}, [%4];"
                 : "=r"(r0), "=r"(r1), "=r"(r2), "=r"(r3) : "r"(addr));
}
template <int F16>
__device__ __forceinline__ void mma_any(float* c, const uint32_t* a, const uint32_t* b) {
    if (F16)
        asm volatile("mma.sync.aligned.m16n8k16.row.col.f32.f16.f16.f32 "
                     "{%0,%1,%2,%3}, {%4,%5,%6,%7}, {%8,%9}, {%0,%1,%2,%3};"
                     : "+f"(c[0]), "+f"(c[1]), "+f"(c[2]), "+f"(c[3])
                     : "r"(a[0]), "r"(a[1]), "r"(a[2]), "r"(a[3]), "r"(b[0]), "r"(b[1]));
    else
        asm volatile("mma.sync.aligned.m16n8k16.row.col.f32.bf16.bf16.f32 "
                     "{%0,%1,%2,%3}, {%4,%5,%6,%7}, {%8,%9}, {%0,%1,%2,%3};"
                     : "+f"(c[0]), "+f"(c[1]), "+f"(c[2]), "+f"(c[3])
                     : "r"(a[0]), "r"(a[1]), "r"(a[2]), "r"(a[3]), "r"(b[0]), "r"(b[1]));
}
__device__ __forceinline__ unsigned fkey(float x) {
    unsigned u = __float_as_uint(x);
    return (u & 0x80000000u) ? ~u : (u | 0x80000000u);
}
__device__ __forceinline__ float finv(unsigned k) {
    return (k & 0x80000000u) ? __uint_as_float(k & 0x7fffffffu)
                             : __uint_as_float(~k);
}

// ---------------- init ----------------
__global__ void init_kernel(int* counts, double* a, double* b, double* c, int* ncand) {
    int t = threadIdx.x;
    counts[t] = 0;
    if (t == 0) { *a = 0.0; *b = 0.0; *c = 0.0; *ncand = 0; }
}

// ---------------- conversions ----------------
__global__ void conv_cat_f16(const float* __restrict__ a, int ad,
                             const float* __restrict__ b, int bd,
                             __half* __restrict__ o, int KP)
{
    int pairs = KP >> 1;
    size_t t = (size_t)blockIdx.x * 256 + threadIdx.x;
    size_t row = t / pairs;
    if (row >= NROWS) return;
    int p = (int)(t % pairs);
    int j = p * 2;
    float v0, v1;
    if (j + 1 < ad)           { v0 = a[row * ad + j];        v1 = a[row * ad + j + 1]; }
    else if (j + 1 < ad + bd) { v0 = b[row * bd + (j - ad)]; v1 = b[row * bd + (j - ad) + 1]; }
    else                      { v0 = 0.f; v1 = 0.f; }
    ((__half2*)(o + row * (size_t)KP))[p] = __floats2half2_rn(v0, v1);
}
__global__ void conv_w_f16(const float* __restrict__ W, int K, int Nn,
                           __half* __restrict__ o, int KP)
{
    size_t t = (size_t)blockIdx.x * 256 + threadIdx.x;
    if (t >= (size_t)Nn * KP) return;
    int n = (int)(t / KP);
    int k = (int)(t % KP);
    float v = (k < K) ? W[(size_t)k * Nn + n] : 0.f;
    o[(size_t)n * KP + k] = __float2half(v);
}
__global__ void conv_cat_kernel(const float* __restrict__ a, int ad,
                                const float* __restrict__ b, int bd,
                                __nv_bfloat16* __restrict__ o, int KP, int KA)
{
    int pairs = KP >> 1;
    size_t t = (size_t)blockIdx.x * 256 + threadIdx.x;
    size_t row = t / pairs;
    if (row >= NROWS) return;
    int p = (int)(t % pairs);
    int j = p * 2;
    float v0, v1;
    if (j + 1 < ad)           { v0 = a[row * ad + j];        v1 = a[row * ad + j + 1]; }
    else if (j + 1 < ad + bd) { v0 = b[row * bd + (j - ad)]; v1 = b[row * bd + (j - ad) + 1]; }
    else if (j < ad + bd)     { v0 = b[row * bd + (j - ad)]; v1 = 0.f; }
    else                      { v0 = 0.f; v1 = 0.f; }
    __nv_bfloat162 hh, ll;
    hh.x = __float2bfloat16(v0); hh.y = __float2bfloat16(v1);
    ll.x = __float2bfloat16(v0 - __bfloat162float(hh.x));
    ll.y = __float2bfloat16(v1 - __bfloat162float(hh.y));
    __nv_bfloat16* base = o + row * (size_t)KA;
    ((__nv_bfloat162*)(base))[p]      = hh;
    ((__nv_bfloat162*)(base + KP))[p] = ll;
}
__global__ void conv_w_kernel(const float* __restrict__ W, int K, int Nn,
                              __nv_bfloat16* __restrict__ o, int KP, int KA)
{
    size_t t = (size_t)blockIdx.x * 256 + threadIdx.x;
    if (t >= (size_t)Nn * KA) return;
    int n  = (int)(t / KA);
    int kt = (int)(t % KA);
    int s  = kt < KP ? 0 : 1;
    int k  = kt - s * KP;
    float v = (k < K) ? W[(size_t)k * Nn + n] : 0.f;
    __nv_bfloat16 h = __float2bfloat16(v);
    __nv_bfloat16 r = s ? __float2bfloat16(v - __bfloat162float(h)) : h;
    o[(size_t)n * KA + kt] = r;
}

// ---------------- tensor-core GEMM: 128x256 CTA tile, 16 warps ----------------
#define SROW 80
#define S_AHI 0
#define S_ALO 10240
#define S_BHI 20480
#define S_BLO 40960
#define STAGE 61440
#define TG_SMEM (2 * STAGE)

template <int KP, int OUTM, int NT, int F16>
__global__ __launch_bounds__(512, 1) void tgemm(
    const uint16_t* __restrict__ Ap,
    const uint16_t* __restrict__ Bp,
    const float* __restrict__ bias,
    float* __restrict__ Cf,
    uint16_t* __restrict__ Cb,
    int Nfull, int KPn)
{
    extern __shared__ __align__(16) uint8_t smem[];
    const uint32_t sm = smem_u32(smem);
    constexpr int KA = (NT == 3) ? 2 * KP : KP;

    const int tid = threadIdx.x;
    const int wid = tid >> 5, lane = tid & 31;
    const int wr = wid >> 3, wc = wid & 7;
    const size_t row0 = (size_t)blockIdx.y * 128;
    const int    col0 = blockIdx.x * 256;

    const int NCH = KP / 32;

    float acc[4][4][4];
#pragma unroll
    for (int i = 0; i < 4; i++)
#pragma unroll
        for (int j = 0; j < 4; j++)
#pragma unroll
            for (int e = 0; e < 4; e++) acc[i][j][e] = 0.f;

    auto load_chunk = [&](int c, int buf) {
        const int kc = c * 32;
        const uint32_t base = sm + buf * STAGE;
        {
            int row = tid >> 2, seg = tid & 3;
            const uint16_t* ga = Ap + (row0 + row) * (size_t)KA + kc + seg * 8;
            uint32_t so = row * SROW + seg * 16;
            cp_async16(base + S_AHI + so, ga);
            if (NT == 3) cp_async16(base + S_ALO + so, ga + KP);
        }
#pragma unroll
        for (int l = 0; l < 2; l++) {
            int L = tid + l * 512;
            int row = L >> 2, seg = L & 3;
            const uint16_t* gb = Bp + (size_t)(col0 + row) * KA + kc + seg * 8;
            uint32_t so = row * SROW + seg * 16;
            cp_async16(base + S_BHI + so, gb);
            if (NT == 3) cp_async16(base + S_BLO + so, gb + KP);
        }
        cp_commit();
    };

    load_chunk(0, 0);

    for (int c = 0; c < NCH; c++) {
        if (c + 1 < NCH) load_chunk(c + 1, (c + 1) & 1);
        if (c + 1 < NCH) cp_wait<1>(); else cp_wait<0>();
        __syncthreads();

        const uint32_t st = sm + (c & 1) * STAGE;
        const int g = lane >> 3, lr = lane & 7;

#pragma unroll
        for (int ks = 0; ks < 2; ks++) {
            const uint32_t acolo = (ks * 16 + (g >> 1) * 8) * 2;
            const uint32_t bcolo = (ks * 16 + (g & 1) * 8) * 2;
            uint32_t afh[4][4];
#pragma unroll
            for (int mt = 0; mt < 4; mt++) {
                int r = wr * 64 + mt * 16 + (g & 1) * 8 + lr;
                ldmx4(afh[mt][0], afh[mt][1], afh[mt][2], afh[mt][3],
                      st + S_AHI + r * SROW + acolo);
            }
            uint32_t bfh[4][2];
#pragma unroll
            for (int bt = 0; bt < 2; bt++) {
                int r = wc * 32 + bt * 16 + (g >> 1) * 8 + lr;
                uint32_t r0, r1, r2, r3;
                ldmx4(r0, r1, r2, r3, st + S_BHI + r * SROW + bcolo);
                bfh[bt * 2][0] = r0;     bfh[bt * 2][1] = r1;
                bfh[bt * 2 + 1][0] = r2; bfh[bt * 2 + 1][1] = r3;
            }
#pragma unroll
            for (int mt = 0; mt < 4; mt++)
#pragma unroll
                for (int nt = 0; nt < 4; nt++)
                    mma_any<F16>(acc[mt][nt], afh[mt], bfh[nt]);
            if (NT == 3) {
#pragma unroll
                for (int mt = 0; mt < 4; mt++) {
                    int r = wr * 64 + mt * 16 + (g & 1) * 8 + lr;
                    uint32_t al[4];
                    ldmx4(al[0], al[1], al[2], al[3], st + S_ALO + r * SROW + acolo);
#pragma unroll
                    for (int nt = 0; nt < 4; nt++)
                        mma_any<F16>(acc[mt][nt], al, bfh[nt]);
                }
#pragma unroll
                for (int bt = 0; bt < 2; bt++) {
                    int r = wc * 32 + bt * 16 + (g >> 1) * 8 + lr;
                    uint32_t r0, r1, r2, r3;
                    ldmx4(r0, r1, r2, r3, st + S_BLO + r * SROW + bcolo);
                    uint32_t bl0[2] = {r0, r1}, bl1[2] = {r2, r3};
#pragma unroll
                    for (int mt = 0; mt < 4; mt++) {
                        mma_any<F16>(acc[mt][bt * 2],     afh[mt], bl0);
                        mma_any<F16>(acc[mt][bt * 2 + 1], afh[mt], bl1);
                    }
                }
            }
        }
        __syncthreads();
    }

#pragma unroll
    for (int mt = 0; mt < 4; mt++) {
        size_t ra = row0 + wr * 64 + mt * 16 + (lane >> 2);
        size_t rb = ra + 8;
#pragma unroll
        for (int nt = 0; nt < 4; nt++) {
            int colg = col0 + wc * 32 + nt * 8 + (lane & 3) * 2;
            float b0 = bias[colg], b1 = bias[colg + 1];
            float v00 = acc[mt][nt][0] + b0, v01 = acc[mt][nt][1] + b1;
            float v10 = acc[mt][nt][2] + b0, v11 = acc[mt][nt][3] + b1;
            v00 = (v00 > 0.f) ? v00 : expm1f(v00);
            v01 = (v01 > 0.f) ? v01 : expm1f(v01);
            v10 = (v10 > 0.f) ? v10 : expm1f(v10);
            v11 = (v11 > 0.f) ? v11 : expm1f(v11);
            if (OUTM == 0) {
                *(float2*)(Cf + ra * (size_t)Nfull + colg) = make_float2(v00, v01);
                *(float2*)(Cf + rb * (size_t)Nfull + colg) = make_float2(v10, v11);
            } else if (OUTM == 1) {
                const size_t KTn = 2 * (size_t)KPn;
                __nv_bfloat162 hh, ll;
                uint16_t* pa = Cb + ra * KTn;
                hh.x = __float2bfloat16(v00); hh.y = __float2bfloat16(v01);
                ll.x = __float2bfloat16(v00 - __bfloat162float(hh.x));
                ll.y = __float2bfloat16(v01 - __bfloat162float(hh.y));
                *(__nv_bfloat162*)(pa + colg)       = hh;
                *(__nv_bfloat162*)(pa + KPn + colg) = ll;
                uint16_t* pb = Cb + rb * KTn;
                hh.x = __float2bfloat16(v10); hh.y = __float2bfloat16(v11);
                ll.x = __float2bfloat16(v10 - __bfloat162float(hh.x));
                ll.y = __float2bfloat16(v11 - __bfloat162float(hh.y));
                *(__nv_bfloat162*)(pb + colg)       = hh;
                *(__nv_bfloat162*)(pb + KPn + colg) = ll;
            } else {
                uint16_t* pa = Cb + ra * (size_t)KPn;
                uint16_t* pb = Cb + rb * (size_t)KPn;
                *(__half2*)(pa + colg) = __floats2half2_rn(v00, v01);
                *(__half2*)(pb + colg) = __floats2half2_rn(v10, v11);
            }
        }
    }
}

// ---------------- narrow GEMM (N=16 or 12), fp32 SIMT ----------------
template <int NO, int KK, bool RLOSS>
__global__ __launch_bounds__(128) void ngemm_kernel(
    const float* __restrict__ A, const float* __restrict__ B,
    const float* __restrict__ bias, float* __restrict__ C,
    const float* __restrict__ ref, double* __restrict__ rloss)
{
    __shared__ float Bs[KK][NO];
    __shared__ float As[128][33];
    int tid = threadIdx.x;
    size_t row0 = (size_t)blockIdx.x * 128;
    for (int e = tid; e < KK * NO; e += 128) Bs[e / NO][e % NO] = B[e];
    float acc[NO];
#pragma unroll
    for (int j = 0; j < NO; j++) acc[j] = 0.f;

    for (int k0 = 0; k0 < KK; k0 += 32) {
        __syncthreads();
#pragma unroll
        for (int l = 0; l < 32; l++) {
            int e = tid + l * 128;
            int r = e >> 5, c = e & 31;
            As[r][c] = A[(row0 + r) * KK + k0 + c];
        }
        __syncthreads();
#pragma unroll
        for (int kk = 0; kk < 32; kk++) {
            float a = As[tid][kk];
#pragma unroll
            for (int j = 0; j < NO; j++) acc[j] = fmaf(a, Bs[k0 + kk][j], acc[j]);
        }
    }
    float rl = 0.f;
    size_t r = row0 + tid;
#pragma unroll
    for (int j = 0; j < NO; j++) {
        float v = acc[j] + bias[j];
        C[r * NO + j] = v;
        if (RLOSS) { float d = v - ref[r * NO + j]; rl += d * d; }
    }
    if (RLOSS) {
#pragma unroll
        for (int o = 16; o > 0; o >>= 1) rl += __shfl_down_sync(0xffffffffu, rl, o);
        __shared__ float ws[4];
        if ((tid & 31) == 0) ws[tid >> 5] = rl;
        __syncthreads();
        if (tid == 0) atomicAdd(rloss, (double)(ws[0] + ws[1] + ws[2] + ws[3]));
    }
}

// ---------------- quantize (+ near-tie candidate collection) ----------------
__global__ __launch_bounds__(256) void quantize_kernel(
    const float* __restrict__ z, const float* __restrict__ emb,
    float* __restrict__ out_q, float* __restrict__ out_idx,
    float* __restrict__ dist,
    int* __restrict__ counts, double* __restrict__ qlat,
    int* __restrict__ ncand, int* __restrict__ cand)
{
    __shared__ float embn[KCB][ED];
    __shared__ float zt[16][ED + 1];
    __shared__ float rinv[16];
    __shared__ float n2[16];
    __shared__ float sd[KCB][17];
    __shared__ int   shist[KCB];
    __shared__ float sq;
    int tid = threadIdx.x;
    size_t row0 = (size_t)blockIdx.x * 16;
    shist[tid] = 0;
    if (tid == 0) sq = 0.f;
    {
        float e[ED], s = 0.f;
#pragma unroll
        for (int j = 0; j < ED; j++) { e[j] = emb[tid * ED + j]; s += e[j] * e[j]; }
        float inv = 1.f / fmaxf(sqrtf(s), 1e-12f);
#pragma unroll
        for (int j = 0; j < ED; j++) embn[tid][j] = e[j] * inv;
    }
    { int r = tid >> 4, j = tid & 15; zt[r][j] = z[(row0 + r) * ED + j]; }
    __syncthreads();
    if (tid < 16) {
        float s = 0.f;
#pragma unroll
        for (int j = 0; j < ED; j++) s += zt[tid][j] * zt[tid][j];
        n2[tid] = s;
        rinv[tid] = 1.f / fmaxf(sqrtf(s), 1e-12f);
    }
    __syncthreads();
    for (int r = 0; r < 16; r++) {
        float s = 0.f;
#pragma unroll
        for (int j = 0; j < ED; j++) s += zt[r][j] * embn[tid][j];
        sd[tid][r] = s * rinv[r];
    }
    __syncthreads();
    int w = tid >> 5, lane = tid & 31;
    for (int c = 0; c < 32; c++) {
        int k = w * 32 + c;
        if (lane < 16) dist[(size_t)k * NROWS + row0 + lane] = sd[k][lane];
    }
    for (int rr = 0; rr < 2; rr++) {
        int r = w * 2 + rr;
        float best = -2.f; int bi = 0;
        for (int kk = lane; kk < KCB; kk += 32) {
            float v = sd[kk][r];
            if (v > best) { best = v; bi = kk; }
        }
#pragma unroll
        for (int o = 16; o > 0; o >>= 1) {
            float ov = __shfl_down_sync(0xffffffffu, best, o);
            int   oi = __shfl_down_sync(0xffffffffu, bi, o);
            if (ov > best || (ov == best && oi < bi)) { best = ov; bi = oi; }
        }
        bi   = __shfl_sync(0xffffffffu, bi, 0);
        best = __shfl_sync(0xffffffffu, best, 0);
        float sec = -2.f;
        for (int kk = lane; kk < KCB; kk += 32)
            if (kk != bi) sec = fmaxf(sec, sd[kk][r]);
#pragma unroll
        for (int o = 16; o > 0; o >>= 1)
            sec = fmaxf(sec, __shfl_down_sync(0xffffffffu, sec, o));
        float dd = 0.f;
        if (lane < ED) {
            float qv = emb[bi * ED + lane];
            float d = qv - zt[r][lane];
            out_q[(row0 + r) * ED + lane] = qv;
            dd = d * d;
        }
#pragma unroll
        for (int o = 16; o > 0; o >>= 1) dd += __shfl_down_sync(0xffffffffu, dd, o);
        if (lane == 0) {
            atomicAdd(&sq, dd);
            atomicAdd(&shist[bi], 1);
            out_idx[row0 + r] = (float)bi;
            if (best - sec < GAP_TAU || n2[r] < 4e-3f) {
                int s = atomicAdd(ncand, 1);
                cand[s] = (int)(row0 + r);
            }
        }
    }
    __syncthreads();
    if (shist[tid]) atomicAdd(&counts[tid], shist[tid]);
    if (tid == 0) atomicAdd(qlat, (double)sq);
}

// ---------------- batched exact fp32 re-check of near-tie rows ----------------
// 16 rows per block: weights loaded once per batch (coalesced), 16 row-accumulators
// in registers. 16x less weight traffic than per-row refine.
#define RF_SMEM ((RB * 272 + RB * 512 + RB * 256 + RB * 16 + RB + RB * 256) * 4 + RB * 12)
__global__ __launch_bounds__(256) void refine_kernel(
    const float* __restrict__ actions, const float* __restrict__ conditions,
    const float* __restrict__ ew1, const float* __restrict__ eb1,
    const float* __restrict__ ew2, const float* __restrict__ eb2,
    const float* __restrict__ ew3, const float* __restrict__ eb3,
    const float* __restrict__ emb,
    const float* __restrict__ zbf,
    float* __restrict__ out_q, float* __restrict__ out_idx,
    int* __restrict__ counts, double* __restrict__ qlat,
    const int* __restrict__ ncand, const int* __restrict__ cand)
{
    extern __shared__ float sh[];
    float* xs   = sh;                        // RB*272
    float* h1s  = xs + RB * 272;             // RB*512
    float* h2s  = h1s + RB * 512;            // RB*256
    float* zs   = h2s + RB * 256;            // RB*16
    float* zinv = zs + RB * 16;              // RB
    float* ds   = zinv + RB;                 // RB*256
    int*   ri   = (int*)(ds + RB * 256);     // RB
    int*   vl   = ri + RB;                   // RB
    int*   ni   = vl + RB;                   // RB

    int tid = threadIdx.x;
    int n = *ncand;
    for (int bi = blockIdx.x; bi * RB < n; bi += gridDim.x) {
        if (tid < RB) {
            int idx = bi * RB + tid;
            vl[tid] = (idx < n);
            ri[tid] = cand[(idx < n) ? idx : (n - 1)];
        }
        __syncthreads();
        for (int e = tid; e < RB * 268; e += 256) {
            int r = e / 268, j = e % 268;
            size_t row = (size_t)ri[r];
            xs[r * 272 + j] = (j < ACT_D) ? actions[row * ACT_D + j]
                                          : conditions[row * COND_D + (j - ACT_D)];
        }
        __syncthreads();
        // layer1: 2 columns per thread, 16 rows each
#pragma unroll
        for (int cc = 0; cc < 2; cc++) {
            int c = tid + cc * 256;
            float a0[RB];
            float b = eb1[c];
#pragma unroll
            for (int r = 0; r < RB; r++) a0[r] = b;
            for (int k = 0; k < 268; k++) {
                float w = ew1[(size_t)k * H1D + c];
#pragma unroll
                for (int r = 0; r < RB; r++) a0[r] = fmaf(xs[r * 272 + k], w, a0[r]);
            }
#pragma unroll
            for (int r = 0; r < RB; r++)
                h1s[r * 512 + c] = (a0[r] > 0.f) ? a0[r] : expm1f(a0[r]);
        }
        __syncthreads();
        // layer2: 1 column per thread
        {
            int c = tid;
            float a0[RB];
            float b = eb2[c];
#pragma unroll
            for (int r = 0; r < RB; r++) a0[r] = b;
            for (int k = 0; k < 512; k++) {
                float w = ew2[(size_t)k * H2D + c];
#pragma unroll
                for (int r = 0; r < RB; r++) a0[r] = fmaf(h1s[r * 512 + k], w, a0[r]);
            }
#pragma unroll
            for (int r = 0; r < RB; r++)
                h2s[r * 256 + c] = (a0[r] > 0.f) ? a0[r] : expm1f(a0[r]);
        }
        __syncthreads();
        // layer3: one (row, col) per thread
        {
            int r = tid >> 4, c = tid & 15;
            float s = eb3[c];
            for (int k = 0; k < 256; k++)
                s = fmaf(h2s[r * 256 + k], ew3[(size_t)k * ED + c], s);
            zs[r * 16 + c] = s;
        }
        __syncthreads();
        if (tid < RB) {
            float s = 0.f;
#pragma unroll
            for (int j = 0; j < ED; j++) s += zs[tid * 16 + j] * zs[tid * 16 + j];
            zinv[tid] = 1.f / fmaxf(sqrtf(s), 1e-12f);
        }
        __syncthreads();
        // distances: one code per thread
        {
            int c = tid;
            float e[ED], s = 0.f;
#pragma unroll
            for (int j = 0; j < ED; j++) { e[j] = emb[c * ED + j]; s += e[j] * e[j]; }
            float inv = 1.f / fmaxf(sqrtf(s), 1e-12f);
#pragma unroll
            for (int r = 0; r < RB; r++) {
                float dot = 0.f;
#pragma unroll
                for (int j = 0; j < ED; j++)
                    dot += (zs[r * 16 + j] * zinv[r]) * (e[j] * inv);
                ds[r * 256 + c] = dot;
            }
        }
        __syncthreads();
        // argmax per row (warp w handles rows 2w, 2w+1)
        {
            int w = tid >> 5, lane = tid & 31;
#pragma unroll
            for (int rr = 0; rr < 2; rr++) {
                int r = w * 2 + rr;
                float best = -2.f; int bidx = 0;
                for (int kk = lane; kk < KCB; kk += 32) {
                    float v = ds[r * 256 + kk];
                    if (v > best) { best = v; bidx = kk; }
                }
#pragma unroll
                for (int o = 16; o > 0; o >>= 1) {
                    float ov = __shfl_down_sync(0xffffffffu, best, o);
                    int   oi = __shfl_down_sync(0xffffffffu, bidx, o);
                    if (ov > best || (ov == best && oi < bidx)) { best = ov; bidx = oi; }
                }
                if (lane == 0) ni[r] = bidx;
            }
        }
        __syncthreads();
        // patch
        if (tid < RB && vl[tid]) {
            size_t row = (size_t)ri[tid];
            int oldidx = (int)out_idx[row];
            int newidx = ni[tid];
            if (newidx != oldidx) {
                out_idx[row] = (float)newidx;
                atomicSub(counts + oldidx, 1);
                atomicAdd(counts + newidx, 1);
                float dq = 0.f;
#pragma unroll
                for (int j = 0; j < ED; j++) {
                    float zb = zbf[row * ED + j];
                    float dn = emb[newidx * ED + j] - zb;
                    float dl = emb[oldidx * ED + j] - zb;
                    dq += dn * dn - dl * dl;
                }
                atomicAdd(qlat, (double)dq);
#pragma unroll
                for (int j = 0; j < ED; j++)
                    out_q[row * ED + j] = emb[newidx * ED + j];
            }
        }
        __syncthreads();
    }
}

// ---------------- per-column order statistics + contra loss ----------------
__global__ __launch_bounds__(256) void select_kernel(
    const float* __restrict__ dist, double* __restrict__ contra)
{
    __shared__ unsigned ha[2048], hb[2048];
    __shared__ unsigned s_bin[2], s_rem[2];
    __shared__ float rf[256];
    int tid = threadIdx.x;
    const float* col = dist + (size_t)blockIdx.x * NROWS;
    const unsigned RA = NROWS / 2 - 1;
    const unsigned RBK = NROWS - 512;

    for (int i = tid; i < 2048; i += 256) ha[i] = 0;
    __syncthreads();
    for (int i = tid; i < NROWS; i += 256) atomicAdd(&ha[fkey(col[i]) >> 21], 1u);
    __syncthreads();
    if (tid == 0) {
        unsigned c = 0;
        for (unsigned b = 0; b < 2048; b++) {
            unsigned h = ha[b];
            if (c <= RA && c + h > RA) { s_bin[0] = b; s_rem[0] = RA - c; }
            if (c <= RBK && c + h > RBK) { s_bin[1] = b; s_rem[1] = RBK - c; }
            c += h;
        }
    }
    __syncthreads();
    unsigned p0a = s_bin[0], p0b = s_bin[1];
    unsigned rema = s_rem[0], remb = s_rem[1];
    __syncthreads();

    for (int i = tid; i < 2048; i += 256) { ha[i] = 0; hb[i] = 0; }
    __syncthreads();
    for (int i = tid; i < NROWS; i += 256) {
        unsigned u = fkey(col[i]);
        unsigned t = u >> 21, m = (u >> 10) & 2047u;
        if (t == p0a) atomicAdd(&ha[m], 1u);
        if (t == p0b) atomicAdd(&hb[m], 1u);
    }
    __syncthreads();
    if (tid == 0) { unsigned c = 0; for (unsigned b = 0; b < 2048; b++) { unsigned h = ha[b];
        if (c + h > rema) { s_bin[0] = b; s_rem[0] = rema - c; break; } c += h; } }
    if (tid == 1) { unsigned c = 0; for (unsigned b = 0; b < 2048; b++) { unsigned h = hb[b];
        if (c + h > remb) { s_bin[1] = b; s_rem[1] = remb - c; break; } c += h; } }
    __syncthreads();
    unsigned p1a = (p0a << 11) | s_bin[0], p1b = (p0b << 11) | s_bin[1];
    rema = s_rem[0]; remb = s_rem[1];
    __syncthreads();

    for (int i = tid; i < 1024; i += 256) { ha[i] = 0; hb[i] = 0; }
    __syncthreads();
    for (int i = tid; i < NROWS; i += 256) {
        unsigned u = fkey(col[i]);
        if ((u >> 10) == p1a) atomicAdd(&ha[u & 1023u], 1u);
        if ((u >> 10) == p1b) atomicAdd(&hb[u & 1023u], 1u);
    }
    __syncthreads();
    if (tid == 0) { unsigned c = 0; for (unsigned b = 0; b < 1024; b++) { unsigned h = ha[b];
        if (c + h > rema) { s_bin[0] = b; break; } c += h; } }
    if (tid == 1) { unsigned c = 0; for (unsigned b = 0; b < 1024; b++) { unsigned h = hb[b];
        if (c + h > remb) { s_bin[1] = b; break; } c += h; } }
    __syncthreads();
    unsigned km = (p1a << 10) | s_bin[0];
    unsigned kt = (p1b << 10) | s_bin[1];

    float Tmed = finv(km);
    const float INV_TAU = 1.0f / 0.07f;
    int cgt = 0, clt = 0;
    float sgt = 0.f, sexp = 0.f;
    for (int i = tid; i < NROWS; i += 256) {
        float x = col[i];
        unsigned u = fkey(x);
        if (u > kt) { cgt++; sgt += x; }
        if (u < km) { clt++; sexp += expf((x - Tmed) * INV_TAU); }
    }
    float CGT, SGT, CLT, SEXP;
    rf[tid] = (float)cgt; __syncthreads();
    for (int s = 128; s; s >>= 1) { if (tid < s) rf[tid] += rf[tid + s]; __syncthreads(); }
    CGT = rf[0]; __syncthreads();
    rf[tid] = sgt; __syncthreads();
    for (int s = 128; s; s >>= 1) { if (tid < s) rf[tid] += rf[tid + s]; __syncthreads(); }
    SGT = rf[0]; __syncthreads();
    rf[tid] = (float)clt; __syncthreads();
    for (int s = 128; s; s >>= 1) { if (tid < s) rf[tid] += rf[tid + s]; __syncthreads(); }
    CLT = rf[0]; __syncthreads();
    rf[tid] = sexp; __syncthreads();
    for (int s = 128; s; s >>= 1) { if (tid < s) rf[tid] += rf[tid + s]; __syncthreads(); }
    SEXP = rf[0];

    if (tid == 0) {
        float Ttop = finv(kt);
        float dis_pos = (SGT + (512.0f - CGT) * Ttop) * (1.0f / 512.0f);
        float Sx = SEXP + ((float)(NROWS / 2) - CLT);
        float a = dis_pos * INV_TAU, b = Tmed * INV_TAU;
        float m = fmaxf(a, b);
        float lse = m + logf(expf(a - m) + Sx * expf(b - m));
        atomicAdd(contra, (double)(lse - a));
    }
}

// ---------------- finalize scalars ----------------
__global__ void finalize_kernel(const int* __restrict__ counts,
                                const double* __restrict__ qlat,
                                const double* __restrict__ contra,
                                const double* __restrict__ recon,
                                float* __restrict__ out_sc)
{
    __shared__ float rr[256];
    int t = threadIdx.x;
    float p = (float)counts[t] / (float)NROWS;
    rr[t] = p * logf(p + 1e-10f);
    __syncthreads();
    for (int s = 128; s; s >>= 1) { if (t < s) rr[t] += rr[t + s]; __syncthreads(); }
    if (t == 0) {
        float q = (float)(*qlat / ((double)NROWS * ED));
        out_sc[0] = q;
        out_sc[1] = 0.25f * q;
        out_sc[2] = (float)(*contra / (double)KCB);
        out_sc[3] = expf(-rr[0]);
        out_sc[4] = (float)(*recon / ((double)NROWS * ACT_D));
    }
}

// ---------------- launch ----------------
extern "C" void kernel_launch(void* const* d_in, const int* in_sizes, int n_in,
                              void* d_out, int out_size)
{
    const float* actions    = (const float*)d_in[0];
    const float* conditions = (const float*)d_in[1];
    const float* enc_w1 = (const float*)d_in[2];  const float* enc_b1 = (const float*)d_in[3];
    const float* enc_w2 = (const float*)d_in[4];  const float* enc_b2 = (const float*)d_in[5];
    const float* enc_w3 = (const float*)d_in[6];  const float* enc_b3 = (const float*)d_in[7];
    const float* dec_w1 = (const float*)d_in[8];  const float* dec_b1 = (const float*)d_in[9];
    const float* dec_w2 = (const float*)d_in[10]; const float* dec_b2 = (const float*)d_in[11];
    const float* dec_w3 = (const float*)d_in[12]; const float* dec_b3 = (const float*)d_in[13];
    const float* embedding = (const float*)d_in[14];

    float* out = (float*)d_out;
    float* out_rec = out;
    float* out_q   = out + (size_t)NROWS * ACT_D;
    float* out_idx = out_q + (size_t)NROWS * ED;
    float* out_sc  = out_idx + NROWS;

    __half *A1, *Ah1, *B1h, *B2h;
    __nv_bfloat16 *A3, *Ad1, *B3, *B4;
    float *h2, *z, *dist, *d2;
    double *qlat, *contra, *recon; int *counts, *ncand, *cand;
    cudaGetSymbolAddress((void**)&A1,  g_A1);
    cudaGetSymbolAddress((void**)&Ah1, g_Ah1);
    cudaGetSymbolAddress((void**)&B1h, g_B1h);
    cudaGetSymbolAddress((void**)&B2h, g_B2h);
    cudaGetSymbolAddress((void**)&A3,  g_A3);
    cudaGetSymbolAddress((void**)&Ad1, g_Ad1);
    cudaGetSymbolAddress((void**)&B3,  g_B3);
    cudaGetSymbolAddress((void**)&B4,  g_B4);
    cudaGetSymbolAddress((void**)&h2,  g_h2);
    cudaGetSymbolAddress((void**)&z,   g_z);
    cudaGetSymbolAddress((void**)&dist,g_dist);
    cudaGetSymbolAddress((void**)&d2,  g_d2);
    cudaGetSymbolAddress((void**)&qlat,  g_qlat);
    cudaGetSymbolAddress((void**)&contra,g_contra);
    cudaGetSymbolAddress((void**)&recon, g_recon);
    cudaGetSymbolAddress((void**)&counts,g_counts);
    cudaGetSymbolAddress((void**)&ncand, g_ncand);
    cudaGetSymbolAddress((void**)&cand,  g_cand);

    cudaFuncSetAttribute((const void*)tgemm<KE1, 2, 1, 1>, cudaFuncAttributeMaxDynamicSharedMemorySize, TG_SMEM);
    cudaFuncSetAttribute((const void*)tgemm<KE2, 0, 1, 1>, cudaFuncAttributeMaxDynamicSharedMemorySize, TG_SMEM);
    cudaFuncSetAttribute((const void*)tgemm<KP1, 1, 3, 0>, cudaFuncAttributeMaxDynamicSharedMemorySize, TG_SMEM);
    cudaFuncSetAttribute((const void*)tgemm<KP4, 0, 3, 0>, cudaFuncAttributeMaxDynamicSharedMemorySize, TG_SMEM);
    cudaFuncSetAttribute((const void*)refine_kernel, cudaFuncAttributeMaxDynamicSharedMemorySize, RF_SMEM);

    init_kernel<<<1, 256>>>(counts, qlat, contra, recon, ncand);

    conv_w_f16<<<((size_t)H1D * KE1 + 255) / 256, 256>>>(enc_w1, 268, H1D, B1h, KE1);
    conv_w_f16<<<((size_t)H2D * KE2 + 255) / 256, 256>>>(enc_w2, 512, H2D, B2h, KE2);
    conv_w_kernel<<<((size_t)H2D * KA1 + 255) / 256, 256>>>(dec_w1, 272, H2D, B3, KP1, KA1);
    conv_w_kernel<<<((size_t)H1D * KA4 + 255) / 256, 256>>>(dec_w2, 256, H1D, B4, KP4, KA4);

    conv_cat_f16<<<((size_t)NROWS * (KE1 / 2) + 255) / 256, 256>>>(
        actions, ACT_D, conditions, COND_D, A1, KE1);

    // enc1: 268 -> 512 (fp16 single-pass, fp16 out)
    tgemm<KE1, 2, 1, 1><<<dim3(2, NROWS / 128), 512, TG_SMEM>>>(
        (const uint16_t*)A1, (const uint16_t*)B1h, enc_b1, nullptr, (uint16_t*)Ah1, H1D, KE2);
    // enc2: 512 -> 256 (fp16 single-pass, fp32 out)
    tgemm<KE2, 0, 1, 1><<<dim3(1, NROWS / 128), 512, TG_SMEM>>>(
        (const uint16_t*)Ah1, (const uint16_t*)B2h, enc_b2, h2, nullptr, H2D, 0);
    // enc3: 256 -> 16 (fp32 SIMT, no ELU)
    ngemm_kernel<ED, H2D, false><<<NROWS / 128, 128>>>(h2, enc_w3, enc_b3, z, nullptr, nullptr);

    quantize_kernel<<<NROWS / 16, 256>>>(z, embedding, out_q, out_idx, dist, counts, qlat,
                                         ncand, cand);
    refine_kernel<<<2048, 256, RF_SMEM>>>(actions, conditions,
                                 enc_w1, enc_b1, enc_w2, enc_b2, enc_w3, enc_b3,
                                 embedding, z, out_q, out_idx, counts, qlat, ncand, cand);
    select_kernel<<<KCB, 256>>>(dist, contra);

    conv_cat_kernel<<<((size_t)NROWS * (KP1 / 2) + 255) / 256, 256>>>(
        out_q, ED, conditions, COND_D, A3, KP1, KA1);

    // dec1: 272 -> 256 (bf16 3-term, [hi|lo] out)
    tgemm<KP1, 1, 3, 0><<<dim3(1, NROWS / 128), 512, TG_SMEM>>>(
        (const uint16_t*)A3, (const uint16_t*)B3, dec_b1, nullptr, (uint16_t*)Ad1, H2D, KP4);
    // dec2: 256 -> 512 (bf16 3-term, fp32 out)
    tgemm<KP4, 0, 3, 0><<<dim3(2, NROWS / 128), 512, TG_SMEM>>>(
        (const uint16_t*)Ad1, (const uint16_t*)B4, dec_b2, d2, nullptr, H1D, 0);
    // dec3: 512 -> 12 + reconstruction loss
    ngemm_kernel<ACT_D, H1D, true><<<NROWS / 128, 128>>>(d2, dec_w3, dec_b3, out_rec, actions, recon);

    finalize_kernel<<<1, 256>>>(counts, qlat, contra, recon, out_sc);
}

// round 10
// speedup vs baseline: 1.1157x; 1.0184x over previous
#include <cuda_runtime.h>
#include <cuda_bf16.h>
#include <cuda_fp16.h>
#include <math.h>
#include <stdint.h>

#define NROWS 131072
#define ACT_D 12
#define COND_D 256
#define KCB 256
#define ED 16
#define H1D 512
#define H2D 256

// encoder (fp16 single-pass) K layouts
#define KE1 288      // enc1 input K=268 padded
#define KE2 512      // enc2 input
// decoder (bf16 [hi|lo] 3-term) layouts
#define KP1 288
#define KA1 576      // dec1 input (K=272 padded)
#define KP4 256
#define KA4 512      // dec2 input (K=256)

#define GAP_TAU 8e-3f
#define RB 16        // refine batch rows per block

// ---------------- scratch (static device globals; no allocs) ----------------
__device__ __half         g_A1 [(size_t)NROWS * KE1];
__device__ __half         g_Ah1[(size_t)NROWS * KE2];
__device__ __half         g_B1h[(size_t)H1D * KE1];
__device__ __half         g_B2h[(size_t)H2D * KE2];
__device__ __nv_bfloat16 g_A3 [(size_t)NROWS * KA1];
__device__ __nv_bfloat16 g_Ad1[(size_t)NROWS * KA4];
__device__ __nv_bfloat16 g_B3 [(size_t)H2D * KA1];
__device__ __nv_bfloat16 g_B4 [(size_t)H1D * KA4];
__device__ float g_h2  [(size_t)NROWS * H2D];
__device__ float g_z   [(size_t)NROWS * ED];
__device__ float g_dist[(size_t)KCB * NROWS];   // transposed: [k][n]
__device__ float g_d2  [(size_t)NROWS * H1D];
__device__ double g_qlat, g_contra, g_recon;
__device__ int    g_counts[KCB];
__device__ int    g_ncand;
__device__ int    g_cand[NROWS];

// ---------------- helpers ----------------
__device__ __forceinline__ uint32_t smem_u32(const void* p) {
    uint32_t a;
    asm("{ .reg .u64 t; cvta.to.shared.u64 t, %1; cvt.u32.u64 %0, t; }"
        : "=r"(a) : "l"(p));
    return a;
}
__device__ __forceinline__ void cp_async16(uint32_t s, const void* g) {
    asm volatile("cp.async.cg.shared.global [%0], [%1], 16;" :: "r"(s), "l"(g) : "memory");
}
__device__ __forceinline__ void cp_commit() {
    asm volatile("cp.async.commit_group;" ::: "memory");
}
template <int N>
__device__ __forceinline__ void cp_wait() {
    asm volatile("cp.async.wait_group %0;" :: "n"(N) : "memory");
}
__device__ __forceinline__ void ldmx4(uint32_t& r0, uint32_t& r1, uint32_t& r2, uint32_t& r3,
                                      uint32_t addr) {
    asm volatile("ldmatrix.sync.aligned.m8n8.x4.shared.b16 {%0,%1,%2,%3}, [%4];"
                 : "=r"(r0), "=r"(r1), "=r"(r2), "=r"(r3) : "r"(addr));
}
template <int F16>
__device__ __forceinline__ void mma_any(float* c, const uint32_t* a, const uint32_t* b) {
    if (F16)
        asm volatile("mma.sync.aligned.m16n8k16.row.col.f32.f16.f16.f32 "
                     "{%0,%1,%2,%3}, {%4,%5,%6,%7}, {%8,%9}, {%0,%1,%2,%3};"
                     : "+f"(c[0]), "+f"(c[1]), "+f"(c[2]), "+f"(c[3])
                     : "r"(a[0]), "r"(a[1]), "r"(a[2]), "r"(a[3]), "r"(b[0]), "r"(b[1]));
    else
        asm volatile("mma.sync.aligned.m16n8k16.row.col.f32.bf16.bf16.f32 "
                     "{%0,%1,%2,%3}, {%4,%5,%6,%7}, {%8,%9}, {%0,%1,%2,%3};"
                     : "+f"(c[0]), "+f"(c[1]), "+f"(c[2]), "+f"(c[3])
                     : "r"(a[0]), "r"(a[1]), "r"(a[2]), "r"(a[3]), "r"(b[0]), "r"(b[1]));
}
__device__ __forceinline__ unsigned fkey(float x) {
    unsigned u = __float_as_uint(x);
    return (u & 0x80000000u) ? ~u : (u | 0x80000000u);
}
__device__ __forceinline__ float finv(unsigned k) {
    return (k & 0x80000000u) ? __uint_as_float(k & 0x7fffffffu)
                             : __uint_as_float(~k);
}

// ---------------- init ----------------
__global__ void init_kernel(int* counts, double* a, double* b, double* c, int* ncand) {
    int t = threadIdx.x;
    counts[t] = 0;
    if (t == 0) { *a = 0.0; *b = 0.0; *c = 0.0; *ncand = 0; }
}

// ---------------- conversions ----------------
__global__ void conv_cat_f16(const float* __restrict__ a, int ad,
                             const float* __restrict__ b, int bd,
                             __half* __restrict__ o, int KP)
{
    int pairs = KP >> 1;
    size_t t = (size_t)blockIdx.x * 256 + threadIdx.x;
    size_t row = t / pairs;
    if (row >= NROWS) return;
    int p = (int)(t % pairs);
    int j = p * 2;
    float v0, v1;
    if (j + 1 < ad)           { v0 = a[row * ad + j];        v1 = a[row * ad + j + 1]; }
    else if (j + 1 < ad + bd) { v0 = b[row * bd + (j - ad)]; v1 = b[row * bd + (j - ad) + 1]; }
    else                      { v0 = 0.f; v1 = 0.f; }
    ((__half2*)(o + row * (size_t)KP))[p] = __floats2half2_rn(v0, v1);
}
__global__ void conv_w_f16(const float* __restrict__ W, int K, int Nn,
                           __half* __restrict__ o, int KP)
{
    size_t t = (size_t)blockIdx.x * 256 + threadIdx.x;
    if (t >= (size_t)Nn * KP) return;
    int n = (int)(t / KP);
    int k = (int)(t % KP);
    float v = (k < K) ? W[(size_t)k * Nn + n] : 0.f;
    o[(size_t)n * KP + k] = __float2half(v);
}
__global__ void conv_cat_kernel(const float* __restrict__ a, int ad,
                                const float* __restrict__ b, int bd,
                                __nv_bfloat16* __restrict__ o, int KP, int KA)
{
    int pairs = KP >> 1;
    size_t t = (size_t)blockIdx.x * 256 + threadIdx.x;
    size_t row = t / pairs;
    if (row >= NROWS) return;
    int p = (int)(t % pairs);
    int j = p * 2;
    float v0, v1;
    if (j + 1 < ad)           { v0 = a[row * ad + j];        v1 = a[row * ad + j + 1]; }
    else if (j + 1 < ad + bd) { v0 = b[row * bd + (j - ad)]; v1 = b[row * bd + (j - ad) + 1]; }
    else if (j < ad + bd)     { v0 = b[row * bd + (j - ad)]; v1 = 0.f; }
    else                      { v0 = 0.f; v1 = 0.f; }
    __nv_bfloat162 hh, ll;
    hh.x = __float2bfloat16(v0); hh.y = __float2bfloat16(v1);
    ll.x = __float2bfloat16(v0 - __bfloat162float(hh.x));
    ll.y = __float2bfloat16(v1 - __bfloat162float(hh.y));
    __nv_bfloat16* base = o + row * (size_t)KA;
    ((__nv_bfloat162*)(base))[p]      = hh;
    ((__nv_bfloat162*)(base + KP))[p] = ll;
}
__global__ void conv_w_kernel(const float* __restrict__ W, int K, int Nn,
                              __nv_bfloat16* __restrict__ o, int KP, int KA)
{
    size_t t = (size_t)blockIdx.x * 256 + threadIdx.x;
    if (t >= (size_t)Nn * KA) return;
    int n  = (int)(t / KA);
    int kt = (int)(t % KA);
    int s  = kt < KP ? 0 : 1;
    int k  = kt - s * KP;
    float v = (k < K) ? W[(size_t)k * Nn + n] : 0.f;
    __nv_bfloat16 h = __float2bfloat16(v);
    __nv_bfloat16 r = s ? __float2bfloat16(v - __bfloat162float(h)) : h;
    o[(size_t)n * KA + kt] = r;
}

// ---------------- tensor-core GEMM: 128x256 CTA tile, 16 warps, NS-stage pipe ----
#define SROW 80
template <int KP, int OUTM, int NT, int F16, int NS>
__global__ __launch_bounds__(512, 1) void tgemm(
    const uint16_t* __restrict__ Ap,
    const uint16_t* __restrict__ Bp,
    const float* __restrict__ bias,
    float* __restrict__ Cf,
    uint16_t* __restrict__ Cb,
    int Nfull, int KPn)
{
    extern __shared__ __align__(16) uint8_t smem[];
    const uint32_t sm = smem_u32(smem);
    constexpr int KA = (NT == 3) ? 2 * KP : KP;
    constexpr uint32_t OFF_AHI = 0;
    constexpr uint32_t OFF_ALO = 10240;                       // NT3 only
    constexpr uint32_t OFF_BHI = (NT == 3) ? 20480 : 10240;
    constexpr uint32_t OFF_BLO = 40960;                       // NT3 only
    constexpr uint32_t STAGE_B = (NT == 3) ? 61440 : 30720;

    const int tid = threadIdx.x;
    const int wid = tid >> 5, lane = tid & 31;
    const int wr = wid >> 3, wc = wid & 7;          // warps 2 x 8
    const size_t row0 = (size_t)blockIdx.y * 128;
    const int    col0 = blockIdx.x * 256;

    const int NCH = KP / 32;

    float acc[4][4][4];
#pragma unroll
    for (int i = 0; i < 4; i++)
#pragma unroll
        for (int j = 0; j < 4; j++)
#pragma unroll
            for (int e = 0; e < 4; e++) acc[i][j][e] = 0.f;

    auto load_chunk = [&](int c, int buf) {
        const int kc = c * 32;
        const uint32_t base = sm + buf * STAGE_B;
        {
            int row = tid >> 2, seg = tid & 3;
            const uint16_t* ga = Ap + (row0 + row) * (size_t)KA + kc + seg * 8;
            uint32_t so = row * SROW + seg * 16;
            cp_async16(base + OFF_AHI + so, ga);
            if (NT == 3) cp_async16(base + OFF_ALO + so, ga + KP);
        }
#pragma unroll
        for (int l = 0; l < 2; l++) {
            int L = tid + l * 512;
            int row = L >> 2, seg = L & 3;
            const uint16_t* gb = Bp + (size_t)(col0 + row) * KA + kc + seg * 8;
            uint32_t so = row * SROW + seg * 16;
            cp_async16(base + OFF_BHI + so, gb);
            if (NT == 3) cp_async16(base + OFF_BLO + so, gb + KP);
        }
        cp_commit();
    };

    // prologue: fill NS-1 stages (NCH >= NS-1 for all instantiations)
#pragma unroll
    for (int s = 0; s < NS - 1; s++) load_chunk(s, s);

    for (int c = 0; c < NCH; c++) {
        int nc = c + NS - 1;
        if (nc < NCH) load_chunk(nc, nc % NS);
        else          cp_commit();                 // dummy group: uniform accounting
        cp_wait<NS - 1>();
        __syncthreads();

        const uint32_t st = sm + (c % NS) * STAGE_B;
        const int g = lane >> 3, lr = lane & 7;

#pragma unroll
        for (int ks = 0; ks < 2; ks++) {
            const uint32_t acolo = (ks * 16 + (g >> 1) * 8) * 2;
            const uint32_t bcolo = (ks * 16 + (g & 1) * 8) * 2;
            uint32_t afh[4][4];
#pragma unroll
            for (int mt = 0; mt < 4; mt++) {
                int r = wr * 64 + mt * 16 + (g & 1) * 8 + lr;
                ldmx4(afh[mt][0], afh[mt][1], afh[mt][2], afh[mt][3],
                      st + OFF_AHI + r * SROW + acolo);
            }
            uint32_t bfh[4][2];
#pragma unroll
            for (int bt = 0; bt < 2; bt++) {
                int r = wc * 32 + bt * 16 + (g >> 1) * 8 + lr;
                uint32_t r0, r1, r2, r3;
                ldmx4(r0, r1, r2, r3, st + OFF_BHI + r * SROW + bcolo);
                bfh[bt * 2][0] = r0;     bfh[bt * 2][1] = r1;
                bfh[bt * 2 + 1][0] = r2; bfh[bt * 2 + 1][1] = r3;
            }
#pragma unroll
            for (int mt = 0; mt < 4; mt++)
#pragma unroll
                for (int nt = 0; nt < 4; nt++)
                    mma_any<F16>(acc[mt][nt], afh[mt], bfh[nt]);
            if (NT == 3) {
#pragma unroll
                for (int mt = 0; mt < 4; mt++) {
                    int r = wr * 64 + mt * 16 + (g & 1) * 8 + lr;
                    uint32_t al[4];
                    ldmx4(al[0], al[1], al[2], al[3], st + OFF_ALO + r * SROW + acolo);
#pragma unroll
                    for (int nt = 0; nt < 4; nt++)
                        mma_any<F16>(acc[mt][nt], al, bfh[nt]);
                }
#pragma unroll
                for (int bt = 0; bt < 2; bt++) {
                    int r = wc * 32 + bt * 16 + (g >> 1) * 8 + lr;
                    uint32_t r0, r1, r2, r3;
                    ldmx4(r0, r1, r2, r3, st + OFF_BLO + r * SROW + bcolo);
                    uint32_t bl0[2] = {r0, r1}, bl1[2] = {r2, r3};
#pragma unroll
                    for (int mt = 0; mt < 4; mt++) {
                        mma_any<F16>(acc[mt][bt * 2],     afh[mt], bl0);
                        mma_any<F16>(acc[mt][bt * 2 + 1], afh[mt], bl1);
                    }
                }
            }
        }
        __syncthreads();
    }

#pragma unroll
    for (int mt = 0; mt < 4; mt++) {
        size_t ra = row0 + wr * 64 + mt * 16 + (lane >> 2);
        size_t rb = ra + 8;
#pragma unroll
        for (int nt = 0; nt < 4; nt++) {
            int colg = col0 + wc * 32 + nt * 8 + (lane & 3) * 2;
            float b0 = bias[colg], b1 = bias[colg + 1];
            float v00 = acc[mt][nt][0] + b0, v01 = acc[mt][nt][1] + b1;
            float v10 = acc[mt][nt][2] + b0, v11 = acc[mt][nt][3] + b1;
            v00 = (v00 > 0.f) ? v00 : expm1f(v00);
            v01 = (v01 > 0.f) ? v01 : expm1f(v01);
            v10 = (v10 > 0.f) ? v10 : expm1f(v10);
            v11 = (v11 > 0.f) ? v11 : expm1f(v11);
            if (OUTM == 0) {
                *(float2*)(Cf + ra * (size_t)Nfull + colg) = make_float2(v00, v01);
                *(float2*)(Cf + rb * (size_t)Nfull + colg) = make_float2(v10, v11);
            } else if (OUTM == 1) {
                const size_t KTn = 2 * (size_t)KPn;
                __nv_bfloat162 hh, ll;
                uint16_t* pa = Cb + ra * KTn;
                hh.x = __float2bfloat16(v00); hh.y = __float2bfloat16(v01);
                ll.x = __float2bfloat16(v00 - __bfloat162float(hh.x));
                ll.y = __float2bfloat16(v01 - __bfloat162float(hh.y));
                *(__nv_bfloat162*)(pa + colg)       = hh;
                *(__nv_bfloat162*)(pa + KPn + colg) = ll;
                uint16_t* pb = Cb + rb * KTn;
                hh.x = __float2bfloat16(v10); hh.y = __float2bfloat16(v11);
                ll.x = __float2bfloat16(v10 - __bfloat162float(hh.x));
                ll.y = __float2bfloat16(v11 - __bfloat162float(hh.y));
                *(__nv_bfloat162*)(pb + colg)       = hh;
                *(__nv_bfloat162*)(pb + KPn + colg) = ll;
            } else {
                uint16_t* pa = Cb + ra * (size_t)KPn;
                uint16_t* pb = Cb + rb * (size_t)KPn;
                *(__half2*)(pa + colg) = __floats2half2_rn(v00, v01);
                *(__half2*)(pb + colg) = __floats2half2_rn(v10, v11);
            }
        }
    }
}
#define TG_SMEM3 (3 * 61440)
#define TG_SMEM1 (5 * 30720)

// ---------------- narrow GEMM (N=16 or 12), fp32 SIMT ----------------
template <int NO, int KK, bool RLOSS>
__global__ __launch_bounds__(128) void ngemm_kernel(
    const float* __restrict__ A, const float* __restrict__ B,
    const float* __restrict__ bias, float* __restrict__ C,
    const float* __restrict__ ref, double* __restrict__ rloss)
{
    __shared__ float Bs[KK][NO];
    __shared__ float As[128][33];
    int tid = threadIdx.x;
    size_t row0 = (size_t)blockIdx.x * 128;
    for (int e = tid; e < KK * NO; e += 128) Bs[e / NO][e % NO] = B[e];
    float acc[NO];
#pragma unroll
    for (int j = 0; j < NO; j++) acc[j] = 0.f;

    for (int k0 = 0; k0 < KK; k0 += 32) {
        __syncthreads();
#pragma unroll
        for (int l = 0; l < 32; l++) {
            int e = tid + l * 128;
            int r = e >> 5, c = e & 31;
            As[r][c] = A[(row0 + r) * KK + k0 + c];
        }
        __syncthreads();
#pragma unroll
        for (int kk = 0; kk < 32; kk++) {
            float a = As[tid][kk];
#pragma unroll
            for (int j = 0; j < NO; j++) acc[j] = fmaf(a, Bs[k0 + kk][j], acc[j]);
        }
    }
    float rl = 0.f;
    size_t r = row0 + tid;
#pragma unroll
    for (int j = 0; j < NO; j++) {
        float v = acc[j] + bias[j];
        C[r * NO + j] = v;
        if (RLOSS) { float d = v - ref[r * NO + j]; rl += d * d; }
    }
    if (RLOSS) {
#pragma unroll
        for (int o = 16; o > 0; o >>= 1) rl += __shfl_down_sync(0xffffffffu, rl, o);
        __shared__ float ws[4];
        if ((tid & 31) == 0) ws[tid >> 5] = rl;
        __syncthreads();
        if (tid == 0) atomicAdd(rloss, (double)(ws[0] + ws[1] + ws[2] + ws[3]));
    }
}

// ---------------- quantize (+ near-tie candidate collection) ----------------
__global__ __launch_bounds__(256) void quantize_kernel(
    const float* __restrict__ z, const float* __restrict__ emb,
    float* __restrict__ out_q, float* __restrict__ out_idx,
    float* __restrict__ dist,
    int* __restrict__ counts, double* __restrict__ qlat,
    int* __restrict__ ncand, int* __restrict__ cand)
{
    __shared__ float embn[KCB][ED];
    __shared__ float zt[16][ED + 1];
    __shared__ float rinv[16];
    __shared__ float n2[16];
    __shared__ float sd[KCB][17];
    __shared__ int   shist[KCB];
    __shared__ float sq;
    int tid = threadIdx.x;
    size_t row0 = (size_t)blockIdx.x * 16;
    shist[tid] = 0;
    if (tid == 0) sq = 0.f;
    {
        float e[ED], s = 0.f;
#pragma unroll
        for (int j = 0; j < ED; j++) { e[j] = emb[tid * ED + j]; s += e[j] * e[j]; }
        float inv = 1.f / fmaxf(sqrtf(s), 1e-12f);
#pragma unroll
        for (int j = 0; j < ED; j++) embn[tid][j] = e[j] * inv;
    }
    { int r = tid >> 4, j = tid & 15; zt[r][j] = z[(row0 + r) * ED + j]; }
    __syncthreads();
    if (tid < 16) {
        float s = 0.f;
#pragma unroll
        for (int j = 0; j < ED; j++) s += zt[tid][j] * zt[tid][j];
        n2[tid] = s;
        rinv[tid] = 1.f / fmaxf(sqrtf(s), 1e-12f);
    }
    __syncthreads();
    for (int r = 0; r < 16; r++) {
        float s = 0.f;
#pragma unroll
        for (int j = 0; j < ED; j++) s += zt[r][j] * embn[tid][j];
        sd[tid][r] = s * rinv[r];
    }
    __syncthreads();
    int w = tid >> 5, lane = tid & 31;
    for (int c = 0; c < 32; c++) {
        int k = w * 32 + c;
        if (lane < 16) dist[(size_t)k * NROWS + row0 + lane] = sd[k][lane];
    }
    for (int rr = 0; rr < 2; rr++) {
        int r = w * 2 + rr;
        float best = -2.f; int bi = 0;
        for (int kk = lane; kk < KCB; kk += 32) {
            float v = sd[kk][r];
            if (v > best) { best = v; bi = kk; }
        }
#pragma unroll
        for (int o = 16; o > 0; o >>= 1) {
            float ov = __shfl_down_sync(0xffffffffu, best, o);
            int   oi = __shfl_down_sync(0xffffffffu, bi, o);
            if (ov > best || (ov == best && oi < bi)) { best = ov; bi = oi; }
        }
        bi   = __shfl_sync(0xffffffffu, bi, 0);
        best = __shfl_sync(0xffffffffu, best, 0);
        float sec = -2.f;
        for (int kk = lane; kk < KCB; kk += 32)
            if (kk != bi) sec = fmaxf(sec, sd[kk][r]);
#pragma unroll
        for (int o = 16; o > 0; o >>= 1)
            sec = fmaxf(sec, __shfl_down_sync(0xffffffffu, sec, o));
        float dd = 0.f;
        if (lane < ED) {
            float qv = emb[bi * ED + lane];
            float d = qv - zt[r][lane];
            out_q[(row0 + r) * ED + lane] = qv;
            dd = d * d;
        }
#pragma unroll
        for (int o = 16; o > 0; o >>= 1) dd += __shfl_down_sync(0xffffffffu, dd, o);
        if (lane == 0) {
            atomicAdd(&sq, dd);
            atomicAdd(&shist[bi], 1);
            out_idx[row0 + r] = (float)bi;
            if (best - sec < GAP_TAU || n2[r] < 4e-3f) {
                int s = atomicAdd(ncand, 1);
                cand[s] = (int)(row0 + r);
            }
        }
    }
    __syncthreads();
    if (shist[tid]) atomicAdd(&counts[tid], shist[tid]);
    if (tid == 0) atomicAdd(qlat, (double)sq);
}

// ---------------- batched exact fp32 re-check of near-tie rows ----------------
#define RF_SMEM ((RB * 272 + RB * 512 + RB * 256 + RB * 16 + RB + RB * 256) * 4 + RB * 12)
__global__ __launch_bounds__(256) void refine_kernel(
    const float* __restrict__ actions, const float* __restrict__ conditions,
    const float* __restrict__ ew1, const float* __restrict__ eb1,
    const float* __restrict__ ew2, const float* __restrict__ eb2,
    const float* __restrict__ ew3, const float* __restrict__ eb3,
    const float* __restrict__ emb,
    const float* __restrict__ zbf,
    float* __restrict__ out_q, float* __restrict__ out_idx,
    int* __restrict__ counts, double* __restrict__ qlat,
    const int* __restrict__ ncand, const int* __restrict__ cand)
{
    extern __shared__ float sh[];
    float* xs   = sh;                        // RB*272
    float* h1s  = xs + RB * 272;             // RB*512
    float* h2s  = h1s + RB * 512;            // RB*256
    float* zs   = h2s + RB * 256;            // RB*16
    float* zinv = zs + RB * 16;              // RB
    float* ds   = zinv + RB;                 // RB*256
    int*   ri   = (int*)(ds + RB * 256);     // RB
    int*   vl   = ri + RB;                   // RB
    int*   ni   = vl + RB;                   // RB

    int tid = threadIdx.x;
    int n = *ncand;
    for (int bi = blockIdx.x; bi * RB < n; bi += gridDim.x) {
        if (tid < RB) {
            int idx = bi * RB + tid;
            vl[tid] = (idx < n);
            ri[tid] = cand[(idx < n) ? idx : (n - 1)];
        }
        __syncthreads();
        for (int e = tid; e < RB * 268; e += 256) {
            int r = e / 268, j = e % 268;
            size_t row = (size_t)ri[r];
            xs[r * 272 + j] = (j < ACT_D) ? actions[row * ACT_D + j]
                                          : conditions[row * COND_D + (j - ACT_D)];
        }
        __syncthreads();
#pragma unroll
        for (int cc = 0; cc < 2; cc++) {
            int c = tid + cc * 256;
            float a0[RB];
            float b = eb1[c];
#pragma unroll
            for (int r = 0; r < RB; r++) a0[r] = b;
            for (int k = 0; k < 268; k++) {
                float w = ew1[(size_t)k * H1D + c];
#pragma unroll
                for (int r = 0; r < RB; r++) a0[r] = fmaf(xs[r * 272 + k], w, a0[r]);
            }
#pragma unroll
            for (int r = 0; r < RB; r++)
                h1s[r * 512 + c] = (a0[r] > 0.f) ? a0[r] : expm1f(a0[r]);
        }
        __syncthreads();
        {
            int c = tid;
            float a0[RB];
            float b = eb2[c];
#pragma unroll
            for (int r = 0; r < RB; r++) a0[r] = b;
            for (int k = 0; k < 512; k++) {
                float w = ew2[(size_t)k * H2D + c];
#pragma unroll
                for (int r = 0; r < RB; r++) a0[r] = fmaf(h1s[r * 512 + k], w, a0[r]);
            }
#pragma unroll
            for (int r = 0; r < RB; r++)
                h2s[r * 256 + c] = (a0[r] > 0.f) ? a0[r] : expm1f(a0[r]);
        }
        __syncthreads();
        {
            int r = tid >> 4, c = tid & 15;
            float s = eb3[c];
            for (int k = 0; k < 256; k++)
                s = fmaf(h2s[r * 256 + k], ew3[(size_t)k * ED + c], s);
            zs[r * 16 + c] = s;
        }
        __syncthreads();
        if (tid < RB) {
            float s = 0.f;
#pragma unroll
            for (int j = 0; j < ED; j++) s += zs[tid * 16 + j] * zs[tid * 16 + j];
            zinv[tid] = 1.f / fmaxf(sqrtf(s), 1e-12f);
        }
        __syncthreads();
        {
            int c = tid;
            float e[ED], s = 0.f;
#pragma unroll
            for (int j = 0; j < ED; j++) { e[j] = emb[c * ED + j]; s += e[j] * e[j]; }
            float inv = 1.f / fmaxf(sqrtf(s), 1e-12f);
#pragma unroll
            for (int r = 0; r < RB; r++) {
                float dot = 0.f;
#pragma unroll
                for (int j = 0; j < ED; j++)
                    dot += (zs[r * 16 + j] * zinv[r]) * (e[j] * inv);
                ds[r * 256 + c] = dot;
            }
        }
        __syncthreads();
        {
            int w = tid >> 5, lane = tid & 31;
#pragma unroll
            for (int rr = 0; rr < 2; rr++) {
                int r = w * 2 + rr;
                float best = -2.f; int bidx = 0;
                for (int kk = lane; kk < KCB; kk += 32) {
                    float v = ds[r * 256 + kk];
                    if (v > best) { best = v; bidx = kk; }
                }
#pragma unroll
                for (int o = 16; o > 0; o >>= 1) {
                    float ov = __shfl_down_sync(0xffffffffu, best, o);
                    int   oi = __shfl_down_sync(0xffffffffu, bidx, o);
                    if (ov > best || (ov == best && oi < bidx)) { best = ov; bidx = oi; }
                }
                if (lane == 0) ni[r] = bidx;
            }
        }
        __syncthreads();
        if (tid < RB && vl[tid]) {
            size_t row = (size_t)ri[tid];
            int oldidx = (int)out_idx[row];
            int newidx = ni[tid];
            if (newidx != oldidx) {
                out_idx[row] = (float)newidx;
                atomicSub(counts + oldidx, 1);
                atomicAdd(counts + newidx, 1);
                float dq = 0.f;
#pragma unroll
                for (int j = 0; j < ED; j++) {
                    float zb = zbf[row * ED + j];
                    float dn = emb[newidx * ED + j] - zb;
                    float dl = emb[oldidx * ED + j] - zb;
                    dq += dn * dn - dl * dl;
                }
                atomicAdd(qlat, (double)dq);
#pragma unroll
                for (int j = 0; j < ED; j++)
                    out_q[row * ED + j] = emb[newidx * ED + j];
            }
        }
        __syncthreads();
    }
}

// ---------------- per-column order statistics + contra loss ----------------
__global__ __launch_bounds__(256) void select_kernel(
    const float* __restrict__ dist, double* __restrict__ contra)
{
    __shared__ unsigned ha[2048], hb[2048];
    __shared__ unsigned s_bin[2], s_rem[2];
    __shared__ float rf[256];
    int tid = threadIdx.x;
    const float* col = dist + (size_t)blockIdx.x * NROWS;
    const unsigned RA = NROWS / 2 - 1;
    const unsigned RBK = NROWS - 512;

    for (int i = tid; i < 2048; i += 256) ha[i] = 0;
    __syncthreads();
    for (int i = tid; i < NROWS; i += 256) atomicAdd(&ha[fkey(col[i]) >> 21], 1u);
    __syncthreads();
    if (tid == 0) {
        unsigned c = 0;
        for (unsigned b = 0; b < 2048; b++) {
            unsigned h = ha[b];
            if (c <= RA && c + h > RA) { s_bin[0] = b; s_rem[0] = RA - c; }
            if (c <= RBK && c + h > RBK) { s_bin[1] = b; s_rem[1] = RBK - c; }
            c += h;
        }
    }
    __syncthreads();
    unsigned p0a = s_bin[0], p0b = s_bin[1];
    unsigned rema = s_rem[0], remb = s_rem[1];
    __syncthreads();

    for (int i = tid; i < 2048; i += 256) { ha[i] = 0; hb[i] = 0; }
    __syncthreads();
    for (int i = tid; i < NROWS; i += 256) {
        unsigned u = fkey(col[i]);
        unsigned t = u >> 21, m = (u >> 10) & 2047u;
        if (t == p0a) atomicAdd(&ha[m], 1u);
        if (t == p0b) atomicAdd(&hb[m], 1u);
    }
    __syncthreads();
    if (tid == 0) { unsigned c = 0; for (unsigned b = 0; b < 2048; b++) { unsigned h = ha[b];
        if (c + h > rema) { s_bin[0] = b; s_rem[0] = rema - c; break; } c += h; } }
    if (tid == 1) { unsigned c = 0; for (unsigned b = 0; b < 2048; b++) { unsigned h = hb[b];
        if (c + h > remb) { s_bin[1] = b; s_rem[1] = remb - c; break; } c += h; } }
    __syncthreads();
    unsigned p1a = (p0a << 11) | s_bin[0], p1b = (p0b << 11) | s_bin[1];
    rema = s_rem[0]; remb = s_rem[1];
    __syncthreads();

    for (int i = tid; i < 1024; i += 256) { ha[i] = 0; hb[i] = 0; }
    __syncthreads();
    for (int i = tid; i < NROWS; i += 256) {
        unsigned u = fkey(col[i]);
        if ((u >> 10) == p1a) atomicAdd(&ha[u & 1023u], 1u);
        if ((u >> 10) == p1b) atomicAdd(&hb[u & 1023u], 1u);
    }
    __syncthreads();
    if (tid == 0) { unsigned c = 0; for (unsigned b = 0; b < 1024; b++) { unsigned h = ha[b];
        if (c + h > rema) { s_bin[0] = b; break; } c += h; } }
    if (tid == 1) { unsigned c = 0; for (unsigned b = 0; b < 1024; b++) { unsigned h = hb[b];
        if (c + h > remb) { s_bin[1] = b; break; } c += h; } }
    __syncthreads();
    unsigned km = (p1a << 10) | s_bin[0];
    unsigned kt = (p1b << 10) | s_bin[1];

    float Tmed = finv(km);
    const float INV_TAU = 1.0f / 0.07f;
    int cgt = 0, clt = 0;
    float sgt = 0.f, sexp = 0.f;
    for (int i = tid; i < NROWS; i += 256) {
        float x = col[i];
        unsigned u = fkey(x);
        if (u > kt) { cgt++; sgt += x; }
        if (u < km) { clt++; sexp += expf((x - Tmed) * INV_TAU); }
    }
    float CGT, SGT, CLT, SEXP;
    rf[tid] = (float)cgt; __syncthreads();
    for (int s = 128; s; s >>= 1) { if (tid < s) rf[tid] += rf[tid + s]; __syncthreads(); }
    CGT = rf[0]; __syncthreads();
    rf[tid] = sgt; __syncthreads();
    for (int s = 128; s; s >>= 1) { if (tid < s) rf[tid] += rf[tid + s]; __syncthreads(); }
    SGT = rf[0]; __syncthreads();
    rf[tid] = (float)clt; __syncthreads();
    for (int s = 128; s; s >>= 1) { if (tid < s) rf[tid] += rf[tid + s]; __syncthreads(); }
    CLT = rf[0]; __syncthreads();
    rf[tid] = sexp; __syncthreads();
    for (int s = 128; s; s >>= 1) { if (tid < s) rf[tid] += rf[tid + s]; __syncthreads(); }
    SEXP = rf[0];

    if (tid == 0) {
        float Ttop = finv(kt);
        float dis_pos = (SGT + (512.0f - CGT) * Ttop) * (1.0f / 512.0f);
        float Sx = SEXP + ((float)(NROWS / 2) - CLT);
        float a = dis_pos * INV_TAU, b = Tmed * INV_TAU;
        float m = fmaxf(a, b);
        float lse = m + logf(expf(a - m) + Sx * expf(b - m));
        atomicAdd(contra, (double)(lse - a));
    }
}

// ---------------- finalize scalars ----------------
__global__ void finalize_kernel(const int* __restrict__ counts,
                                const double* __restrict__ qlat,
                                const double* __restrict__ contra,
                                const double* __restrict__ recon,
                                float* __restrict__ out_sc)
{
    __shared__ float rr[256];
    int t = threadIdx.x;
    float p = (float)counts[t] / (float)NROWS;
    rr[t] = p * logf(p + 1e-10f);
    __syncthreads();
    for (int s = 128; s; s >>= 1) { if (t < s) rr[t] += rr[t + s]; __syncthreads(); }
    if (t == 0) {
        float q = (float)(*qlat / ((double)NROWS * ED));
        out_sc[0] = q;
        out_sc[1] = 0.25f * q;
        out_sc[2] = (float)(*contra / (double)KCB);
        out_sc[3] = expf(-rr[0]);
        out_sc[4] = (float)(*recon / ((double)NROWS * ACT_D));
    }
}

// ---------------- launch ----------------
extern "C" void kernel_launch(void* const* d_in, const int* in_sizes, int n_in,
                              void* d_out, int out_size)
{
    const float* actions    = (const float*)d_in[0];
    const float* conditions = (const float*)d_in[1];
    const float* enc_w1 = (const float*)d_in[2];  const float* enc_b1 = (const float*)d_in[3];
    const float* enc_w2 = (const float*)d_in[4];  const float* enc_b2 = (const float*)d_in[5];
    const float* enc_w3 = (const float*)d_in[6];  const float* enc_b3 = (const float*)d_in[7];
    const float* dec_w1 = (const float*)d_in[8];  const float* dec_b1 = (const float*)d_in[9];
    const float* dec_w2 = (const float*)d_in[10]; const float* dec_b2 = (const float*)d_in[11];
    const float* dec_w3 = (const float*)d_in[12]; const float* dec_b3 = (const float*)d_in[13];
    const float* embedding = (const float*)d_in[14];

    float* out = (float*)d_out;
    float* out_rec = out;
    float* out_q   = out + (size_t)NROWS * ACT_D;
    float* out_idx = out_q + (size_t)NROWS * ED;
    float* out_sc  = out_idx + NROWS;

    __half *A1, *Ah1, *B1h, *B2h;
    __nv_bfloat16 *A3, *Ad1, *B3, *B4;
    float *h2, *z, *dist, *d2;
    double *qlat, *contra, *recon; int *counts, *ncand, *cand;
    cudaGetSymbolAddress((void**)&A1,  g_A1);
    cudaGetSymbolAddress((void**)&Ah1, g_Ah1);
    cudaGetSymbolAddress((void**)&B1h, g_B1h);
    cudaGetSymbolAddress((void**)&B2h, g_B2h);
    cudaGetSymbolAddress((void**)&A3,  g_A3);
    cudaGetSymbolAddress((void**)&Ad1, g_Ad1);
    cudaGetSymbolAddress((void**)&B3,  g_B3);
    cudaGetSymbolAddress((void**)&B4,  g_B4);
    cudaGetSymbolAddress((void**)&h2,  g_h2);
    cudaGetSymbolAddress((void**)&z,   g_z);
    cudaGetSymbolAddress((void**)&dist,g_dist);
    cudaGetSymbolAddress((void**)&d2,  g_d2);
    cudaGetSymbolAddress((void**)&qlat,  g_qlat);
    cudaGetSymbolAddress((void**)&contra,g_contra);
    cudaGetSymbolAddress((void**)&recon, g_recon);
    cudaGetSymbolAddress((void**)&counts,g_counts);
    cudaGetSymbolAddress((void**)&ncand, g_ncand);
    cudaGetSymbolAddress((void**)&cand,  g_cand);

    cudaFuncSetAttribute((const void*)tgemm<KE1, 2, 1, 1, 5>, cudaFuncAttributeMaxDynamicSharedMemorySize, TG_SMEM1);
    cudaFuncSetAttribute((const void*)tgemm<KE2, 0, 1, 1, 5>, cudaFuncAttributeMaxDynamicSharedMemorySize, TG_SMEM1);
    cudaFuncSetAttribute((const void*)tgemm<KP1, 1, 3, 0, 3>, cudaFuncAttributeMaxDynamicSharedMemorySize, TG_SMEM3);
    cudaFuncSetAttribute((const void*)tgemm<KP4, 0, 3, 0, 3>, cudaFuncAttributeMaxDynamicSharedMemorySize, TG_SMEM3);
    cudaFuncSetAttribute((const void*)refine_kernel, cudaFuncAttributeMaxDynamicSharedMemorySize, RF_SMEM);

    init_kernel<<<1, 256>>>(counts, qlat, contra, recon, ncand);

    conv_w_f16<<<((size_t)H1D * KE1 + 255) / 256, 256>>>(enc_w1, 268, H1D, B1h, KE1);
    conv_w_f16<<<((size_t)H2D * KE2 + 255) / 256, 256>>>(enc_w2, 512, H2D, B2h, KE2);
    conv_w_kernel<<<((size_t)H2D * KA1 + 255) / 256, 256>>>(dec_w1, 272, H2D, B3, KP1, KA1);
    conv_w_kernel<<<((size_t)H1D * KA4 + 255) / 256, 256>>>(dec_w2, 256, H1D, B4, KP4, KA4);

    conv_cat_f16<<<((size_t)NROWS * (KE1 / 2) + 255) / 256, 256>>>(
        actions, ACT_D, conditions, COND_D, A1, KE1);

    // enc1: 268 -> 512 (fp16 single-pass, fp16 out, 5-stage pipe)
    tgemm<KE1, 2, 1, 1, 5><<<dim3(2, NROWS / 128), 512, TG_SMEM1>>>(
        (const uint16_t*)A1, (const uint16_t*)B1h, enc_b1, nullptr, (uint16_t*)Ah1, H1D, KE2);
    // enc2: 512 -> 256 (fp16 single-pass, fp32 out, 5-stage pipe)
    tgemm<KE2, 0, 1, 1, 5><<<dim3(1, NROWS / 128), 512, TG_SMEM1>>>(
        (const uint16_t*)Ah1, (const uint16_t*)B2h, enc_b2, h2, nullptr, H2D, 0);
    // enc3: 256 -> 16 (fp32 SIMT, no ELU)
    ngemm_kernel<ED, H2D, false><<<NROWS / 128, 128>>>(h2, enc_w3, enc_b3, z, nullptr, nullptr);

    quantize_kernel<<<NROWS / 16, 256>>>(z, embedding, out_q, out_idx, dist, counts, qlat,
                                         ncand, cand);
    refine_kernel<<<2048, 256, RF_SMEM>>>(actions, conditions,
                                 enc_w1, enc_b1, enc_w2, enc_b2, enc_w3, enc_b3,
                                 embedding, z, out_q, out_idx, counts, qlat, ncand, cand);
    select_kernel<<<KCB, 256>>>(dist, contra);

    conv_cat_kernel<<<((size_t)NROWS * (KP1 / 2) + 255) / 256, 256>>>(
        out_q, ED, conditions, COND_D, A3, KP1, KA1);

    // dec1: 272 -> 256 (bf16 3-term, [hi|lo] out, 3-stage pipe)
    tgemm<KP1, 1, 3, 0, 3><<<dim3(1, NROWS / 128), 512, TG_SMEM3>>>(
        (const uint16_t*)A3, (const uint16_t*)B3, dec_b1, nullptr, (uint16_t*)Ad1, H2D, KP4);
    // dec2: 256 -> 512 (bf16 3-term, fp32 out, 3-stage pipe)
    tgemm<KP4, 0, 3, 0, 3><<<dim3(2, NROWS / 128), 512, TG_SMEM3>>>(
        (const uint16_t*)Ad1, (const uint16_t*)B4, dec_b2, d2, nullptr, H1D, 0);
    // dec3: 512 -> 12 + reconstruction loss
    ngemm_kernel<ACT_D, H1D, true><<<NROWS / 128, 128>>>(d2, dec_w3, dec_b3, out_rec, actions, recon);

    finalize_kernel<<<1, 256>>>(counts, qlat, contra, recon, out_sc);
}

// round 11
// speedup vs baseline: 1.1338x; 1.0162x over previous
#include <cuda_runtime.h>
#include <cuda_bf16.h>
#include <math.h>
#include <stdint.h>

#define NROWS 131072
#define ACT_D 12
#define COND_D 256
#define KCB 256
#define ED 16
#define H1D 512
#define H2D 256

// 2-segment [hi|lo] layouts; KP = segment length (multiple of 32)
#define KP1 288
#define KA1 576      // enc1 (K=268) / dec1 (K=272) inputs
#define KP2 512
#define KA2 1024     // enc2 input (K=512)
#define KP4 256
#define KA4 512      // dec2 input (K=256)

#define GAP_TAU 2e-3f
#define RB 16        // refine batch rows per block

// ---------------- scratch (static device globals; no allocs) ----------------
__device__ __nv_bfloat16 g_A1 [(size_t)NROWS * KA1];
__device__ __nv_bfloat16 g_Ah1[(size_t)NROWS * KA2];
__device__ __nv_bfloat16 g_A3 [(size_t)NROWS * KA1];
__device__ __nv_bfloat16 g_Ad1[(size_t)NROWS * KA4];
__device__ __nv_bfloat16 g_B1 [(size_t)H1D * KA1];
__device__ __nv_bfloat16 g_B2 [(size_t)H2D * KA2];
__device__ __nv_bfloat16 g_B3 [(size_t)H2D * KA1];
__device__ __nv_bfloat16 g_B4 [(size_t)H1D * KA4];
__device__ float g_h2  [(size_t)NROWS * H2D];
__device__ float g_z   [(size_t)NROWS * ED];
__device__ float g_dist[(size_t)KCB * NROWS];   // transposed: [k][n]
__device__ float g_d2  [(size_t)NROWS * H1D];
__device__ double g_qlat, g_contra, g_recon;
__device__ int    g_counts[KCB];
__device__ int    g_ncand;
__device__ int    g_cand[NROWS];

// ---------------- helpers ----------------
__device__ __forceinline__ uint32_t smem_u32(const void* p) {
    uint32_t a;
    asm("{ .reg .u64 t; cvta.to.shared.u64 t, %1; cvt.u32.u64 %0, t; }"
        : "=r"(a) : "l"(p));
    return a;
}
__device__ __forceinline__ void cp_async16(uint32_t s, const void* g) {
    asm volatile("cp.async.cg.shared.global [%0], [%1], 16;" :: "r"(s), "l"(g) : "memory");
}
__device__ __forceinline__ void cp_commit() {
    asm volatile("cp.async.commit_group;" ::: "memory");
}
template <int N>
__device__ __forceinline__ void cp_wait() {
    asm volatile("cp.async.wait_group %0;" :: "n"(N) : "memory");
}
__device__ __forceinline__ void ldmx4(uint32_t& r0, uint32_t& r1, uint32_t& r2, uint32_t& r3,
                                      uint32_t addr) {
    asm volatile("ldmatrix.sync.aligned.m8n8.x4.shared.b16 {%0,%1,%2,%3}, [%4];"
                 : "=r"(r0), "=r"(r1), "=r"(r2), "=r"(r3) : "r"(addr));
}
__device__ __forceinline__ void mma_bf16(float* c, const uint32_t* a, const uint32_t* b) {
    asm volatile("mma.sync.aligned.m16n8k16.row.col.f32.bf16.bf16.f32 "
                 "{%0,%1,%2,%3}, {%4,%5,%6,%7}, {%8,%9}, {%0,%1,%2,%3};"
                 : "+f"(c[0]), "+f"(c[1]), "+f"(c[2]), "+f"(c[3])
                 : "r"(a[0]), "r"(a[1]), "r"(a[2]), "r"(a[3]), "r"(b[0]), "r"(b[1]));
}
__device__ __forceinline__ unsigned fkey(float x) {
    unsigned u = __float_as_uint(x);
    return (u & 0x80000000u) ? ~u : (u | 0x80000000u);
}
__device__ __forceinline__ float finv(unsigned k) {
    return (k & 0x80000000u) ? __uint_as_float(k & 0x7fffffffu)
                             : __uint_as_float(~k);
}

// ---------------- init ----------------
__global__ void init_kernel(int* counts, double* a, double* b, double* c, int* ncand) {
    int t = threadIdx.x;
    counts[t] = 0;
    if (t == 0) { *a = 0.0; *b = 0.0; *c = 0.0; *ncand = 0; }
}

// ---------------- split conversions (2-segment [hi|lo]) ----------------
__global__ void conv_cat_kernel(const float* __restrict__ a, int ad,
                                const float* __restrict__ b, int bd,
                                __nv_bfloat16* __restrict__ o, int KP, int KA)
{
    int pairs = KP >> 1;
    size_t t = (size_t)blockIdx.x * 256 + threadIdx.x;
    size_t row = t / pairs;
    if (row >= NROWS) return;
    int p = (int)(t % pairs);
    int j = p * 2;
    float v0, v1;
    if (j + 1 < ad)           { v0 = a[row * ad + j];        v1 = a[row * ad + j + 1]; }
    else if (j + 1 < ad + bd) { v0 = b[row * bd + (j - ad)]; v1 = b[row * bd + (j - ad) + 1]; }
    else if (j < ad + bd)     { v0 = b[row * bd + (j - ad)]; v1 = 0.f; }
    else                      { v0 = 0.f; v1 = 0.f; }
    __nv_bfloat162 hh, ll;
    hh.x = __float2bfloat16(v0); hh.y = __float2bfloat16(v1);
    ll.x = __float2bfloat16(v0 - __bfloat162float(hh.x));
    ll.y = __float2bfloat16(v1 - __bfloat162float(hh.y));
    __nv_bfloat16* base = o + row * (size_t)KA;
    ((__nv_bfloat162*)(base))[p]      = hh;
    ((__nv_bfloat162*)(base + KP))[p] = ll;
}
__global__ void conv_w_kernel(const float* __restrict__ W, int K, int Nn,
                              __nv_bfloat16* __restrict__ o, int KP, int KA)
{
    size_t t = (size_t)blockIdx.x * 256 + threadIdx.x;
    if (t >= (size_t)Nn * KA) return;
    int n  = (int)(t / KA);
    int kt = (int)(t % KA);
    int s  = kt < KP ? 0 : 1;
    int k  = kt - s * KP;
    float v = (k < K) ? W[(size_t)k * Nn + n] : 0.f;
    __nv_bfloat16 h = __float2bfloat16(v);
    __nv_bfloat16 r = s ? __float2bfloat16(v - __bfloat162float(h)) : h;
    o[(size_t)n * KA + kt] = r;
}

// ---------------- tensor-core GEMM: 128x256 CTA tile, 16 warps, 3-stage pipe ----
// bf16 [hi|lo] operands, 3-term compensated (Ahi*Bhi + Alo*Bhi + Ahi*Blo).
// OUTM 0: fp32 out (bias+ELU); 1: bf16 [hi|lo] out (segment KPn)
#define SROW 80
#define S_AHI 0
#define S_ALO 10240
#define S_BHI 20480
#define S_BLO 40960
#define STAGE 61440
#define NSTG 3
#define TG_SMEM (NSTG * STAGE)

template <int KP, int OUTM>
__global__ __launch_bounds__(512, 1) void tgemm(
    const __nv_bfloat16* __restrict__ Ap,
    const __nv_bfloat16* __restrict__ Bp,
    const float* __restrict__ bias,
    float* __restrict__ Cf,
    __nv_bfloat16* __restrict__ Cb,
    int Nfull, int KPn)
{
    extern __shared__ __align__(16) uint8_t smem[];
    const uint32_t sm = smem_u32(smem);
    const int KA = 2 * KP;

    const int tid = threadIdx.x;
    const int wid = tid >> 5, lane = tid & 31;
    const int wr = wid >> 3, wc = wid & 7;          // warps 2 x 8
    const size_t row0 = (size_t)blockIdx.y * 128;
    const int    col0 = blockIdx.x * 256;

    const int NCH = KP / 32;

    float acc[4][4][4];
#pragma unroll
    for (int i = 0; i < 4; i++)
#pragma unroll
        for (int j = 0; j < 4; j++)
#pragma unroll
            for (int e = 0; e < 4; e++) acc[i][j][e] = 0.f;

    auto load_chunk = [&](int c, int buf) {
        const int kc = c * 32;
        const uint32_t base = sm + buf * STAGE;
        {
            int row = tid >> 2, seg = tid & 3;
            const __nv_bfloat16* ga = Ap + (row0 + row) * (size_t)KA + kc + seg * 8;
            uint32_t so = row * SROW + seg * 16;
            cp_async16(base + S_AHI + so, ga);
            cp_async16(base + S_ALO + so, ga + KP);
        }
#pragma unroll
        for (int l = 0; l < 2; l++) {
            int L = tid + l * 512;
            int row = L >> 2, seg = L & 3;
            const __nv_bfloat16* gb = Bp + (size_t)(col0 + row) * KA + kc + seg * 8;
            uint32_t so = row * SROW + seg * 16;
            cp_async16(base + S_BHI + so, gb);
            cp_async16(base + S_BLO + so, gb + KP);
        }
        cp_commit();
    };

    // prologue: fill NSTG-1 stages
#pragma unroll
    for (int s = 0; s < NSTG - 1; s++) load_chunk(s, s);

    for (int c = 0; c < NCH; c++) {
        int nc = c + NSTG - 1;
        if (nc < NCH) load_chunk(nc, nc % NSTG);
        else          cp_commit();                 // dummy group: uniform accounting
        cp_wait<NSTG - 1>();
        __syncthreads();

        const uint32_t st = sm + (c % NSTG) * STAGE;
        const int g = lane >> 3, lr = lane & 7;

#pragma unroll
        for (int ks = 0; ks < 2; ks++) {
            const uint32_t acolo = (ks * 16 + (g >> 1) * 8) * 2;
            const uint32_t bcolo = (ks * 16 + (g & 1) * 8) * 2;
            uint32_t afh[4][4];
#pragma unroll
            for (int mt = 0; mt < 4; mt++) {
                int r = wr * 64 + mt * 16 + (g & 1) * 8 + lr;
                ldmx4(afh[mt][0], afh[mt][1], afh[mt][2], afh[mt][3],
                      st + S_AHI + r * SROW + acolo);
            }
            uint32_t bfh[4][2];
#pragma unroll
            for (int bt = 0; bt < 2; bt++) {
                int r = wc * 32 + bt * 16 + (g >> 1) * 8 + lr;
                uint32_t r0, r1, r2, r3;
                ldmx4(r0, r1, r2, r3, st + S_BHI + r * SROW + bcolo);
                bfh[bt * 2][0] = r0;     bfh[bt * 2][1] = r1;
                bfh[bt * 2 + 1][0] = r2; bfh[bt * 2 + 1][1] = r3;
            }
#pragma unroll
            for (int mt = 0; mt < 4; mt++)
#pragma unroll
                for (int nt = 0; nt < 4; nt++)
                    mma_bf16(acc[mt][nt], afh[mt], bfh[nt]);
            // A-lo x B-hi
#pragma unroll
            for (int mt = 0; mt < 4; mt++) {
                int r = wr * 64 + mt * 16 + (g & 1) * 8 + lr;
                uint32_t al[4];
                ldmx4(al[0], al[1], al[2], al[3], st + S_ALO + r * SROW + acolo);
#pragma unroll
                for (int nt = 0; nt < 4; nt++)
                    mma_bf16(acc[mt][nt], al, bfh[nt]);
            }
            // A-hi x B-lo
#pragma unroll
            for (int bt = 0; bt < 2; bt++) {
                int r = wc * 32 + bt * 16 + (g >> 1) * 8 + lr;
                uint32_t r0, r1, r2, r3;
                ldmx4(r0, r1, r2, r3, st + S_BLO + r * SROW + bcolo);
                uint32_t bl0[2] = {r0, r1}, bl1[2] = {r2, r3};
#pragma unroll
                for (int mt = 0; mt < 4; mt++) {
                    mma_bf16(acc[mt][bt * 2],     afh[mt], bl0);
                    mma_bf16(acc[mt][bt * 2 + 1], afh[mt], bl1);
                }
            }
        }
        __syncthreads();
    }

    // epilogue: bias + ELU (+ [hi|lo] re-emit)
#pragma unroll
    for (int mt = 0; mt < 4; mt++) {
        size_t ra = row0 + wr * 64 + mt * 16 + (lane >> 2);
        size_t rb = ra + 8;
#pragma unroll
        for (int nt = 0; nt < 4; nt++) {
            int colg = col0 + wc * 32 + nt * 8 + (lane & 3) * 2;
            float b0 = bias[colg], b1 = bias[colg + 1];
            float v00 = acc[mt][nt][0] + b0, v01 = acc[mt][nt][1] + b1;
            float v10 = acc[mt][nt][2] + b0, v11 = acc[mt][nt][3] + b1;
            v00 = (v00 > 0.f) ? v00 : expm1f(v00);
            v01 = (v01 > 0.f) ? v01 : expm1f(v01);
            v10 = (v10 > 0.f) ? v10 : expm1f(v10);
            v11 = (v11 > 0.f) ? v11 : expm1f(v11);
            if (OUTM == 0) {
                *(float2*)(Cf + ra * (size_t)Nfull + colg) = make_float2(v00, v01);
                *(float2*)(Cf + rb * (size_t)Nfull + colg) = make_float2(v10, v11);
            } else {
                const size_t KTn = 2 * (size_t)KPn;
                __nv_bfloat162 hh, ll;
                __nv_bfloat16* pa = Cb + ra * KTn;
                hh.x = __float2bfloat16(v00); hh.y = __float2bfloat16(v01);
                ll.x = __float2bfloat16(v00 - __bfloat162float(hh.x));
                ll.y = __float2bfloat16(v01 - __bfloat162float(hh.y));
                *(__nv_bfloat162*)(pa + colg)       = hh;
                *(__nv_bfloat162*)(pa + KPn + colg) = ll;
                __nv_bfloat16* pb = Cb + rb * KTn;
                hh.x = __float2bfloat16(v10); hh.y = __float2bfloat16(v11);
                ll.x = __float2bfloat16(v10 - __bfloat162float(hh.x));
                ll.y = __float2bfloat16(v11 - __bfloat162float(hh.y));
                *(__nv_bfloat162*)(pb + colg)       = hh;
                *(__nv_bfloat162*)(pb + KPn + colg) = ll;
            }
        }
    }
}

// ---------------- narrow GEMM (N=16 or 12), fp32 SIMT ----------------
template <int NO, int KK, bool RLOSS>
__global__ __launch_bounds__(128) void ngemm_kernel(
    const float* __restrict__ A, const float* __restrict__ B,
    const float* __restrict__ bias, float* __restrict__ C,
    const float* __restrict__ ref, double* __restrict__ rloss)
{
    __shared__ float Bs[KK][NO];
    __shared__ float As[128][33];
    int tid = threadIdx.x;
    size_t row0 = (size_t)blockIdx.x * 128;
    for (int e = tid; e < KK * NO; e += 128) Bs[e / NO][e % NO] = B[e];
    float acc[NO];
#pragma unroll
    for (int j = 0; j < NO; j++) acc[j] = 0.f;

    for (int k0 = 0; k0 < KK; k0 += 32) {
        __syncthreads();
#pragma unroll
        for (int l = 0; l < 32; l++) {
            int e = tid + l * 128;
            int r = e >> 5, c = e & 31;
            As[r][c] = A[(row0 + r) * KK + k0 + c];
        }
        __syncthreads();
#pragma unroll
        for (int kk = 0; kk < 32; kk++) {
            float a = As[tid][kk];
#pragma unroll
            for (int j = 0; j < NO; j++) acc[j] = fmaf(a, Bs[k0 + kk][j], acc[j]);
        }
    }
    float rl = 0.f;
    size_t r = row0 + tid;
#pragma unroll
    for (int j = 0; j < NO; j++) {
        float v = acc[j] + bias[j];
        C[r * NO + j] = v;
        if (RLOSS) { float d = v - ref[r * NO + j]; rl += d * d; }
    }
    if (RLOSS) {
#pragma unroll
        for (int o = 16; o > 0; o >>= 1) rl += __shfl_down_sync(0xffffffffu, rl, o);
        __shared__ float ws[4];
        if ((tid & 31) == 0) ws[tid >> 5] = rl;
        __syncthreads();
        if (tid == 0) atomicAdd(rloss, (double)(ws[0] + ws[1] + ws[2] + ws[3]));
    }
}

// ---------------- quantize (+ near-tie candidate collection) ----------------
__global__ __launch_bounds__(256) void quantize_kernel(
    const float* __restrict__ z, const float* __restrict__ emb,
    float* __restrict__ out_q, float* __restrict__ out_idx,
    float* __restrict__ dist,
    int* __restrict__ counts, double* __restrict__ qlat,
    int* __restrict__ ncand, int* __restrict__ cand)
{
    __shared__ float embn[KCB][ED];
    __shared__ float zt[16][ED + 1];
    __shared__ float rinv[16];
    __shared__ float n2[16];
    __shared__ float sd[KCB][17];
    __shared__ int   shist[KCB];
    __shared__ float sq;
    int tid = threadIdx.x;
    size_t row0 = (size_t)blockIdx.x * 16;
    shist[tid] = 0;
    if (tid == 0) sq = 0.f;
    {
        float e[ED], s = 0.f;
#pragma unroll
        for (int j = 0; j < ED; j++) { e[j] = emb[tid * ED + j]; s += e[j] * e[j]; }
        float inv = 1.f / fmaxf(sqrtf(s), 1e-12f);
#pragma unroll
        for (int j = 0; j < ED; j++) embn[tid][j] = e[j] * inv;
    }
    { int r = tid >> 4, j = tid & 15; zt[r][j] = z[(row0 + r) * ED + j]; }
    __syncthreads();
    if (tid < 16) {
        float s = 0.f;
#pragma unroll
        for (int j = 0; j < ED; j++) s += zt[tid][j] * zt[tid][j];
        n2[tid] = s;
        rinv[tid] = 1.f / fmaxf(sqrtf(s), 1e-12f);
    }
    __syncthreads();
    for (int r = 0; r < 16; r++) {
        float s = 0.f;
#pragma unroll
        for (int j = 0; j < ED; j++) s += zt[r][j] * embn[tid][j];
        sd[tid][r] = s * rinv[r];
    }
    __syncthreads();
    int w = tid >> 5, lane = tid & 31;
    for (int c = 0; c < 32; c++) {
        int k = w * 32 + c;
        if (lane < 16) dist[(size_t)k * NROWS + row0 + lane] = sd[k][lane];
    }
    for (int rr = 0; rr < 2; rr++) {
        int r = w * 2 + rr;
        float best = -2.f; int bi = 0;
        for (int kk = lane; kk < KCB; kk += 32) {
            float v = sd[kk][r];
            if (v > best) { best = v; bi = kk; }
        }
#pragma unroll
        for (int o = 16; o > 0; o >>= 1) {
            float ov = __shfl_down_sync(0xffffffffu, best, o);
            int   oi = __shfl_down_sync(0xffffffffu, bi, o);
            if (ov > best || (ov == best && oi < bi)) { best = ov; bi = oi; }
        }
        bi   = __shfl_sync(0xffffffffu, bi, 0);
        best = __shfl_sync(0xffffffffu, best, 0);
        float sec = -2.f;
        for (int kk = lane; kk < KCB; kk += 32)
            if (kk != bi) sec = fmaxf(sec, sd[kk][r]);
#pragma unroll
        for (int o = 16; o > 0; o >>= 1)
            sec = fmaxf(sec, __shfl_down_sync(0xffffffffu, sec, o));
        float dd = 0.f;
        if (lane < ED) {
            float qv = emb[bi * ED + lane];
            float d = qv - zt[r][lane];
            out_q[(row0 + r) * ED + lane] = qv;
            dd = d * d;
        }
#pragma unroll
        for (int o = 16; o > 0; o >>= 1) dd += __shfl_down_sync(0xffffffffu, dd, o);
        if (lane == 0) {
            atomicAdd(&sq, dd);
            atomicAdd(&shist[bi], 1);
            out_idx[row0 + r] = (float)bi;
            if (best - sec < GAP_TAU || n2[r] < 1e-4f) {
                int s = atomicAdd(ncand, 1);
                cand[s] = (int)(row0 + r);
            }
        }
    }
    __syncthreads();
    if (shist[tid]) atomicAdd(&counts[tid], shist[tid]);
    if (tid == 0) atomicAdd(qlat, (double)sq);
}

// ---------------- batched exact fp32 re-check of near-tie rows ----------------
#define RF_SMEM ((RB * 272 + RB * 512 + RB * 256 + RB * 16 + RB + RB * 256) * 4 + RB * 12)
__global__ __launch_bounds__(256) void refine_kernel(
    const float* __restrict__ actions, const float* __restrict__ conditions,
    const float* __restrict__ ew1, const float* __restrict__ eb1,
    const float* __restrict__ ew2, const float* __restrict__ eb2,
    const float* __restrict__ ew3, const float* __restrict__ eb3,
    const float* __restrict__ emb,
    const float* __restrict__ zbf,
    float* __restrict__ out_q, float* __restrict__ out_idx,
    int* __restrict__ counts, double* __restrict__ qlat,
    const int* __restrict__ ncand, const int* __restrict__ cand)
{
    extern __shared__ float sh[];
    float* xs   = sh;                        // RB*272
    float* h1s  = xs + RB * 272;             // RB*512
    float* h2s  = h1s + RB * 512;            // RB*256
    float* zs   = h2s + RB * 256;            // RB*16
    float* zinv = zs + RB * 16;              // RB
    float* ds   = zinv + RB;                 // RB*256
    int*   ri   = (int*)(ds + RB * 256);     // RB
    int*   vl   = ri + RB;                   // RB
    int*   ni   = vl + RB;                   // RB

    int tid = threadIdx.x;
    int n = *ncand;
    for (int bi = blockIdx.x; bi * RB < n; bi += gridDim.x) {
        if (tid < RB) {
            int idx = bi * RB + tid;
            vl[tid] = (idx < n);
            ri[tid] = cand[(idx < n) ? idx : (n - 1)];
        }
        __syncthreads();
        for (int e = tid; e < RB * 268; e += 256) {
            int r = e / 268, j = e % 268;
            size_t row = (size_t)ri[r];
            xs[r * 272 + j] = (j < ACT_D) ? actions[row * ACT_D + j]
                                          : conditions[row * COND_D + (j - ACT_D)];
        }
        __syncthreads();
#pragma unroll
        for (int cc = 0; cc < 2; cc++) {
            int c = tid + cc * 256;
            float a0[RB];
            float b = eb1[c];
#pragma unroll
            for (int r = 0; r < RB; r++) a0[r] = b;
            for (int k = 0; k < 268; k++) {
                float w = ew1[(size_t)k * H1D + c];
#pragma unroll
                for (int r = 0; r < RB; r++) a0[r] = fmaf(xs[r * 272 + k], w, a0[r]);
            }
#pragma unroll
            for (int r = 0; r < RB; r++)
                h1s[r * 512 + c] = (a0[r] > 0.f) ? a0[r] : expm1f(a0[r]);
        }
        __syncthreads();
        {
            int c = tid;
            float a0[RB];
            float b = eb2[c];
#pragma unroll
            for (int r = 0; r < RB; r++) a0[r] = b;
            for (int k = 0; k < 512; k++) {
                float w = ew2[(size_t)k * H2D + c];
#pragma unroll
                for (int r = 0; r < RB; r++) a0[r] = fmaf(h1s[r * 512 + k], w, a0[r]);
            }
#pragma unroll
            for (int r = 0; r < RB; r++)
                h2s[r * 256 + c] = (a0[r] > 0.f) ? a0[r] : expm1f(a0[r]);
        }
        __syncthreads();
        {
            int r = tid >> 4, c = tid & 15;
            float s = eb3[c];
            for (int k = 0; k < 256; k++)
                s = fmaf(h2s[r * 256 + k], ew3[(size_t)k * ED + c], s);
            zs[r * 16 + c] = s;
        }
        __syncthreads();
        if (tid < RB) {
            float s = 0.f;
#pragma unroll
            for (int j = 0; j < ED; j++) s += zs[tid * 16 + j] * zs[tid * 16 + j];
            zinv[tid] = 1.f / fmaxf(sqrtf(s), 1e-12f);
        }
        __syncthreads();
        {
            int c = tid;
            float e[ED], s = 0.f;
#pragma unroll
            for (int j = 0; j < ED; j++) { e[j] = emb[c * ED + j]; s += e[j] * e[j]; }
            float inv = 1.f / fmaxf(sqrtf(s), 1e-12f);
#pragma unroll
            for (int r = 0; r < RB; r++) {
                float dot = 0.f;
#pragma unroll
                for (int j = 0; j < ED; j++)
                    dot += (zs[r * 16 + j] * zinv[r]) * (e[j] * inv);
                ds[r * 256 + c] = dot;
            }
        }
        __syncthreads();
        {
            int w = tid >> 5, lane = tid & 31;
#pragma unroll
            for (int rr = 0; rr < 2; rr++) {
                int r = w * 2 + rr;
                float best = -2.f; int bidx = 0;
                for (int kk = lane; kk < KCB; kk += 32) {
                    float v = ds[r * 256 + kk];
                    if (v > best) { best = v; bidx = kk; }
                }
#pragma unroll
                for (int o = 16; o > 0; o >>= 1) {
                    float ov = __shfl_down_sync(0xffffffffu, best, o);
                    int   oi = __shfl_down_sync(0xffffffffu, bidx, o);
                    if (ov > best || (ov == best && oi < bidx)) { best = ov; bidx = oi; }
                }
                if (lane == 0) ni[r] = bidx;
            }
        }
        __syncthreads();
        if (tid < RB && vl[tid]) {
            size_t row = (size_t)ri[tid];
            int oldidx = (int)out_idx[row];
            int newidx = ni[tid];
            if (newidx != oldidx) {
                out_idx[row] = (float)newidx;
                atomicSub(counts + oldidx, 1);
                atomicAdd(counts + newidx, 1);
                float dq = 0.f;
#pragma unroll
                for (int j = 0; j < ED; j++) {
                    float zb = zbf[row * ED + j];
                    float dn = emb[newidx * ED + j] - zb;
                    float dl = emb[oldidx * ED + j] - zb;
                    dq += dn * dn - dl * dl;
                }
                atomicAdd(qlat, (double)dq);
#pragma unroll
                for (int j = 0; j < ED; j++)
                    out_q[row * ED + j] = emb[newidx * ED + j];
            }
        }
        __syncthreads();
    }
}

// ---------------- per-column order statistics + contra loss ----------------
__global__ __launch_bounds__(256) void select_kernel(
    const float* __restrict__ dist, double* __restrict__ contra)
{
    __shared__ unsigned ha[2048], hb[2048];
    __shared__ unsigned s_bin[2], s_rem[2];
    __shared__ float rf[256];
    int tid = threadIdx.x;
    const float* col = dist + (size_t)blockIdx.x * NROWS;
    const unsigned RA = NROWS / 2 - 1;
    const unsigned RBK = NROWS - 512;

    for (int i = tid; i < 2048; i += 256) ha[i] = 0;
    __syncthreads();
    for (int i = tid; i < NROWS; i += 256) atomicAdd(&ha[fkey(col[i]) >> 21], 1u);
    __syncthreads();
    if (tid == 0) {
        unsigned c = 0;
        for (unsigned b = 0; b < 2048; b++) {
            unsigned h = ha[b];
            if (c <= RA && c + h > RA) { s_bin[0] = b; s_rem[0] = RA - c; }
            if (c <= RBK && c + h > RBK) { s_bin[1] = b; s_rem[1] = RBK - c; }
            c += h;
        }
    }
    __syncthreads();
    unsigned p0a = s_bin[0], p0b = s_bin[1];
    unsigned rema = s_rem[0], remb = s_rem[1];
    __syncthreads();

    for (int i = tid; i < 2048; i += 256) { ha[i] = 0; hb[i] = 0; }
    __syncthreads();
    for (int i = tid; i < NROWS; i += 256) {
        unsigned u = fkey(col[i]);
        unsigned t = u >> 21, m = (u >> 10) & 2047u;
        if (t == p0a) atomicAdd(&ha[m], 1u);
        if (t == p0b) atomicAdd(&hb[m], 1u);
    }
    __syncthreads();
    if (tid == 0) { unsigned c = 0; for (unsigned b = 0; b < 2048; b++) { unsigned h = ha[b];
        if (c + h > rema) { s_bin[0] = b; s_rem[0] = rema - c; break; } c += h; } }
    if (tid == 1) { unsigned c = 0; for (unsigned b = 0; b < 2048; b++) { unsigned h = hb[b];
        if (c + h > remb) { s_bin[1] = b; s_rem[1] = remb - c; break; } c += h; } }
    __syncthreads();
    unsigned p1a = (p0a << 11) | s_bin[0], p1b = (p0b << 11) | s_bin[1];
    rema = s_rem[0]; remb = s_rem[1];
    __syncthreads();

    for (int i = tid; i < 1024; i += 256) { ha[i] = 0; hb[i] = 0; }
    __syncthreads();
    for (int i = tid; i < NROWS; i += 256) {
        unsigned u = fkey(col[i]);
        if ((u >> 10) == p1a) atomicAdd(&ha[u & 1023u], 1u);
        if ((u >> 10) == p1b) atomicAdd(&hb[u & 1023u], 1u);
    }
    __syncthreads();
    if (tid == 0) { unsigned c = 0; for (unsigned b = 0; b < 1024; b++) { unsigned h = ha[b];
        if (c + h > rema) { s_bin[0] = b; break; } c += h; } }
    if (tid == 1) { unsigned c = 0; for (unsigned b = 0; b < 1024; b++) { unsigned h = hb[b];
        if (c + h > remb) { s_bin[1] = b; break; } c += h; } }
    __syncthreads();
    unsigned km = (p1a << 10) | s_bin[0];
    unsigned kt = (p1b << 10) | s_bin[1];

    float Tmed = finv(km);
    const float INV_TAU = 1.0f / 0.07f;
    int cgt = 0, clt = 0;
    float sgt = 0.f, sexp = 0.f;
    for (int i = tid; i < NROWS; i += 256) {
        float x = col[i];
        unsigned u = fkey(x);
        if (u > kt) { cgt++; sgt += x; }
        if (u < km) { clt++; sexp += expf((x - Tmed) * INV_TAU); }
    }
    float CGT, SGT, CLT, SEXP;
    rf[tid] = (float)cgt; __syncthreads();
    for (int s = 128; s; s >>= 1) { if (tid < s) rf[tid] += rf[tid + s]; __syncthreads(); }
    CGT = rf[0]; __syncthreads();
    rf[tid] = sgt; __syncthreads();
    for (int s = 128; s; s >>= 1) { if (tid < s) rf[tid] += rf[tid + s]; __syncthreads(); }
    SGT = rf[0]; __syncthreads();
    rf[tid] = (float)clt; __syncthreads();
    for (int s = 128; s; s >>= 1) { if (tid < s) rf[tid] += rf[tid + s]; __syncthreads(); }
    CLT = rf[0]; __syncthreads();
    rf[tid] = sexp; __syncthreads();
    for (int s = 128; s; s >>= 1) { if (tid < s) rf[tid] += rf[tid + s]; __syncthreads(); }
    SEXP = rf[0];

    if (tid == 0) {
        float Ttop = finv(kt);
        float dis_pos = (SGT + (512.0f - CGT) * Ttop) * (1.0f / 512.0f);
        float Sx = SEXP + ((float)(NROWS / 2) - CLT);
        float a = dis_pos * INV_TAU, b = Tmed * INV_TAU;
        float m = fmaxf(a, b);
        float lse = m + logf(expf(a - m) + Sx * expf(b - m));
        atomicAdd(contra, (double)(lse - a));
    }
}

// ---------------- finalize scalars ----------------
__global__ void finalize_kernel(const int* __restrict__ counts,
                                const double* __restrict__ qlat,
                                const double* __restrict__ contra,
                                const double* __restrict__ recon,
                                float* __restrict__ out_sc)
{
    __shared__ float rr[256];
    int t = threadIdx.x;
    float p = (float)counts[t] / (float)NROWS;
    rr[t] = p * logf(p + 1e-10f);
    __syncthreads();
    for (int s = 128; s; s >>= 1) { if (t < s) rr[t] += rr[t + s]; __syncthreads(); }
    if (t == 0) {
        float q = (float)(*qlat / ((double)NROWS * ED));
        out_sc[0] = q;
        out_sc[1] = 0.25f * q;
        out_sc[2] = (float)(*contra / (double)KCB);
        out_sc[3] = expf(-rr[0]);
        out_sc[4] = (float)(*recon / ((double)NROWS * ACT_D));
    }
}

// ---------------- launch ----------------
extern "C" void kernel_launch(void* const* d_in, const int* in_sizes, int n_in,
                              void* d_out, int out_size)
{
    const float* actions    = (const float*)d_in[0];
    const float* conditions = (const float*)d_in[1];
    const float* enc_w1 = (const float*)d_in[2];  const float* enc_b1 = (const float*)d_in[3];
    const float* enc_w2 = (const float*)d_in[4];  const float* enc_b2 = (const float*)d_in[5];
    const float* enc_w3 = (const float*)d_in[6];  const float* enc_b3 = (const float*)d_in[7];
    const float* dec_w1 = (const float*)d_in[8];  const float* dec_b1 = (const float*)d_in[9];
    const float* dec_w2 = (const float*)d_in[10]; const float* dec_b2 = (const float*)d_in[11];
    const float* dec_w3 = (const float*)d_in[12]; const float* dec_b3 = (const float*)d_in[13];
    const float* embedding = (const float*)d_in[14];

    float* out = (float*)d_out;
    float* out_rec = out;
    float* out_q   = out + (size_t)NROWS * ACT_D;
    float* out_idx = out_q + (size_t)NROWS * ED;
    float* out_sc  = out_idx + NROWS;

    __nv_bfloat16 *A1, *Ah1, *A3, *Ad1, *B1, *B2, *B3, *B4;
    float *h2, *z, *dist, *d2;
    double *qlat, *contra, *recon; int *counts, *ncand, *cand;
    cudaGetSymbolAddress((void**)&A1,  g_A1);
    cudaGetSymbolAddress((void**)&Ah1, g_Ah1);
    cudaGetSymbolAddress((void**)&A3,  g_A3);
    cudaGetSymbolAddress((void**)&Ad1, g_Ad1);
    cudaGetSymbolAddress((void**)&B1,  g_B1);
    cudaGetSymbolAddress((void**)&B2,  g_B2);
    cudaGetSymbolAddress((void**)&B3,  g_B3);
    cudaGetSymbolAddress((void**)&B4,  g_B4);
    cudaGetSymbolAddress((void**)&h2,  g_h2);
    cudaGetSymbolAddress((void**)&z,   g_z);
    cudaGetSymbolAddress((void**)&dist,g_dist);
    cudaGetSymbolAddress((void**)&d2,  g_d2);
    cudaGetSymbolAddress((void**)&qlat,  g_qlat);
    cudaGetSymbolAddress((void**)&contra,g_contra);
    cudaGetSymbolAddress((void**)&recon, g_recon);
    cudaGetSymbolAddress((void**)&counts,g_counts);
    cudaGetSymbolAddress((void**)&ncand, g_ncand);
    cudaGetSymbolAddress((void**)&cand,  g_cand);

    cudaFuncSetAttribute((const void*)tgemm<KP1, 1>, cudaFuncAttributeMaxDynamicSharedMemorySize, TG_SMEM);
    cudaFuncSetAttribute((const void*)tgemm<KP2, 0>, cudaFuncAttributeMaxDynamicSharedMemorySize, TG_SMEM);
    cudaFuncSetAttribute((const void*)tgemm<KP4, 0>, cudaFuncAttributeMaxDynamicSharedMemorySize, TG_SMEM);
    cudaFuncSetAttribute((const void*)refine_kernel, cudaFuncAttributeMaxDynamicSharedMemorySize, RF_SMEM);

    // Launch order puts tgemm at positions 4/6 so the ncu window (-s 5 -c 1)
    // captures a GEMM instead of a 5us conversion kernel.
    init_kernel<<<1, 256>>>(counts, qlat, contra, recon, ncand);                        // 1
    conv_w_kernel<<<((size_t)H1D * KA1 + 255) / 256, 256>>>(enc_w1, 268, H1D, B1, KP1, KA1); // 2
    conv_cat_kernel<<<((size_t)NROWS * (KP1 / 2) + 255) / 256, 256>>>(
        actions, ACT_D, conditions, COND_D, A1, KP1, KA1);                              // 3
    // enc1: 268 -> 512 ([hi|lo] out)
    tgemm<KP1, 1><<<dim3(2, NROWS / 128), 512, TG_SMEM>>>(
        A1, B1, enc_b1, nullptr, Ah1, H1D, KP2);                                        // 4
    conv_w_kernel<<<((size_t)H2D * KA2 + 255) / 256, 256>>>(enc_w2, 512, H2D, B2, KP2, KA2); // 5
    // enc2: 512 -> 256 (fp32 out)
    tgemm<KP2, 0><<<dim3(1, NROWS / 128), 512, TG_SMEM>>>(
        Ah1, B2, enc_b2, h2, nullptr, H2D, 0);                                          // 6
    // enc3: 256 -> 16 (fp32 SIMT, no ELU)
    ngemm_kernel<ED, H2D, false><<<NROWS / 128, 128>>>(h2, enc_w3, enc_b3, z, nullptr, nullptr);

    quantize_kernel<<<NROWS / 16, 256>>>(z, embedding, out_q, out_idx, dist, counts, qlat,
                                         ncand, cand);
    refine_kernel<<<2048, 256, RF_SMEM>>>(actions, conditions,
                                 enc_w1, enc_b1, enc_w2, enc_b2, enc_w3, enc_b3,
                                 embedding, z, out_q, out_idx, counts, qlat, ncand, cand);

    conv_w_kernel<<<((size_t)H2D * KA1 + 255) / 256, 256>>>(dec_w1, 272, H2D, B3, KP1, KA1);
    conv_w_kernel<<<((size_t)H1D * KA4 + 255) / 256, 256>>>(dec_w2, 256, H1D, B4, KP4, KA4);
    select_kernel<<<KCB, 256>>>(dist, contra);

    conv_cat_kernel<<<((size_t)NROWS * (KP1 / 2) + 255) / 256, 256>>>(
        out_q, ED, conditions, COND_D, A3, KP1, KA1);

    // dec1: 272 -> 256 ([hi|lo] out)
    tgemm<KP1, 1><<<dim3(1, NROWS / 128), 512, TG_SMEM>>>(
        A3, B3, dec_b1, nullptr, Ad1, H2D, KP4);
    // dec2: 256 -> 512 (fp32 out)
    tgemm<KP4, 0><<<dim3(2, NROWS / 128), 512, TG_SMEM>>>(
        Ad1, B4, dec_b2, d2, nullptr, H1D, 0);
    // dec3: 512 -> 12 + reconstruction loss
    ngemm_kernel<ACT_D, H1D, true><<<NROWS / 128, 128>>>(d2, dec_w3, dec_b3, out_rec, actions, recon);

    finalize_kernel<<<1, 256>>>(counts, qlat, contra, recon, out_sc);
}

// round 12
// speedup vs baseline: 1.1516x; 1.0157x over previous
#include <cuda_runtime.h>
#include <cuda_bf16.h>
#include <math.h>
#include <stdint.h>

#define NROWS 131072
#define ACT_D 12
#define COND_D 256
#define KCB 256
#define ED 16
#define H1D 512
#define H2D 256

// Unified K-layout: small block at [0,16), conditions at [16,272).
#define KP1 288
#define KA1 576      // enc1 / dec1 inputs
#define KP2 512
#define KA2 1024     // enc2 input (K=512)
#define KP4 256
#define KA4 512      // dec2 input (K=256)

#define GAP_TAU 2e-3f
#define RB 16        // refine batch rows per block

// ---------------- scratch (static device globals; no allocs) ----------------
__device__ __nv_bfloat16 g_A1 [(size_t)NROWS * KA1];
__device__ __nv_bfloat16 g_Ah1[(size_t)NROWS * KA2];
__device__ __nv_bfloat16 g_Aq [(size_t)NROWS * 32];   // quantized [hi(16)|lo(16)]
__device__ __nv_bfloat16 g_Ad1[(size_t)NROWS * KA4];
__device__ __nv_bfloat16 g_B1 [(size_t)H1D * KA1];
__device__ __nv_bfloat16 g_B2 [(size_t)H2D * KA2];
__device__ __nv_bfloat16 g_B3 [(size_t)H2D * KA1];
__device__ __nv_bfloat16 g_B4 [(size_t)H1D * KA4];
__device__ float g_h2  [(size_t)NROWS * H2D];
__device__ float g_z   [(size_t)NROWS * ED];
__device__ float g_dist[(size_t)KCB * NROWS];   // transposed: [k][n]
__device__ float g_d2  [(size_t)NROWS * H1D];
__device__ double g_qlat, g_contra, g_recon;
__device__ int    g_counts[KCB];
__device__ int    g_ncand;
__device__ int    g_cand[NROWS];

// ---------------- helpers ----------------
__device__ __forceinline__ uint32_t smem_u32(const void* p) {
    uint32_t a;
    asm("{ .reg .u64 t; cvta.to.shared.u64 t, %1; cvt.u32.u64 %0, t; }"
        : "=r"(a) : "l"(p));
    return a;
}
__device__ __forceinline__ void cp_async16(uint32_t s, const void* g) {
    asm volatile("cp.async.cg.shared.global [%0], [%1], 16;" :: "r"(s), "l"(g) : "memory");
}
__device__ __forceinline__ void cp_commit() {
    asm volatile("cp.async.commit_group;" ::: "memory");
}
template <int N>
__device__ __forceinline__ void cp_wait() {
    asm volatile("cp.async.wait_group %0;" :: "n"(N) : "memory");
}
__device__ __forceinline__ void ldmx4(uint32_t& r0, uint32_t& r1, uint32_t& r2, uint32_t& r3,
                                      uint32_t addr) {
    asm volatile("ldmatrix.sync.aligned.m8n8.x4.shared.b16 {%0,%1,%2,%3}, [%4];"
                 : "=r"(r0), "=r"(r1), "=r"(r2), "=r"(r3) : "r"(addr));
}
__device__ __forceinline__ void mma_bf16(float* c, const uint32_t* a, const uint32_t* b) {
    asm volatile("mma.sync.aligned.m16n8k16.row.col.f32.bf16.bf16.f32 "
                 "{%0,%1,%2,%3}, {%4,%5,%6,%7}, {%8,%9}, {%0,%1,%2,%3};"
                 : "+f"(c[0]), "+f"(c[1]), "+f"(c[2]), "+f"(c[3])
                 : "r"(a[0]), "r"(a[1]), "r"(a[2]), "r"(a[3]), "r"(b[0]), "r"(b[1]));
}
__device__ __forceinline__ unsigned fkey(float x) {
    unsigned u = __float_as_uint(x);
    return (u & 0x80000000u) ? ~u : (u | 0x80000000u);
}
__device__ __forceinline__ float finv(unsigned k) {
    return (k & 0x80000000u) ? __uint_as_float(k & 0x7fffffffu)
                             : __uint_as_float(~k);
}

// ---------------- init ----------------
__global__ void init_kernel(int* counts, double* a, double* b, double* c, int* ncand) {
    int t = threadIdx.x;
    counts[t] = 0;
    if (t == 0) { *a = 0.0; *b = 0.0; *c = 0.0; *ncand = 0; }
}

// ---------------- split conversions (unified layout, 2-segment [hi|lo]) ----------
// activations: cols [0,16) = a (ad real, rest 0), [16,16+bd) = b, rest 0.
__global__ void conv_cat_kernel(const float* __restrict__ a, int ad,
                                const float* __restrict__ b, int bd,
                                __nv_bfloat16* __restrict__ o, int KP, int KA)
{
    int pairs = KP >> 1;
    size_t t = (size_t)blockIdx.x * 256 + threadIdx.x;
    size_t row = t / pairs;
    if (row >= NROWS) return;
    int p = (int)(t % pairs);
    int j = p * 2;
    float v0 = 0.f, v1 = 0.f;
    if (j < 16) {
        if (j < ad)     v0 = a[row * ad + j];
        if (j + 1 < ad) v1 = a[row * ad + j + 1];
    } else {
        int c = j - 16;
        if (c < bd)     v0 = b[row * bd + c];
        if (c + 1 < bd) v1 = b[row * bd + c + 1];
    }
    __nv_bfloat162 hh, ll;
    hh.x = __float2bfloat16(v0); hh.y = __float2bfloat16(v1);
    ll.x = __float2bfloat16(v0 - __bfloat162float(hh.x));
    ll.y = __float2bfloat16(v1 - __bfloat162float(hh.y));
    __nv_bfloat16* base = o + row * (size_t)KA;
    ((__nv_bfloat162*)(base))[p]      = hh;
    ((__nv_bfloat162*)(base + KP))[p] = ll;
}
// weights with the same K-permutation: col c<16 -> W row c (if c<ad), c>=16 -> W row c-(16-ad).
__global__ void conv_w_kernel(const float* __restrict__ W, int ad, int K, int Nn,
                              __nv_bfloat16* __restrict__ o, int KP, int KA)
{
    size_t t = (size_t)blockIdx.x * 256 + threadIdx.x;
    if (t >= (size_t)Nn * KA) return;
    int n  = (int)(t / KA);
    int kt = (int)(t % KA);
    int s  = kt < KP ? 0 : 1;
    int c  = kt - s * KP;
    int k  = (c < 16) ? ((c < ad) ? c : -1) : (c - (16 - ad));
    float v = (k >= 0 && k < K) ? W[(size_t)k * Nn + n] : 0.f;
    __nv_bfloat16 h = __float2bfloat16(v);
    __nv_bfloat16 r = s ? __float2bfloat16(v - __bfloat162float(h)) : h;
    o[(size_t)n * KA + kt] = r;
}

// ---------------- tensor-core GEMM: 128x256 CTA tile, 16 warps, 3-stage pipe ----
// Single barrier per chunk. QSRC: A cols [0,16) come from qsplit (hi at +0, lo at +16).
#define SROW 80
#define S_AHI 0
#define S_ALO 10240
#define S_BHI 20480
#define S_BLO 40960
#define STAGE 61440
#define NSTG 3
#define TG_SMEM (NSTG * STAGE)

template <int KP, int OUTM, bool QSRC>
__global__ __launch_bounds__(512, 1) void tgemm(
    const __nv_bfloat16* __restrict__ Ap,
    const __nv_bfloat16* __restrict__ Bp,
    const __nv_bfloat16* __restrict__ Qs,
    const float* __restrict__ bias,
    float* __restrict__ Cf,
    __nv_bfloat16* __restrict__ Cb,
    int Nfull, int KPn)
{
    extern __shared__ __align__(16) uint8_t smem[];
    const uint32_t sm = smem_u32(smem);
    const int KA = 2 * KP;

    const int tid = threadIdx.x;
    const int wid = tid >> 5, lane = tid & 31;
    const int wr = wid >> 3, wc = wid & 7;          // warps 2 x 8
    const size_t row0 = (size_t)blockIdx.y * 128;
    const int    col0 = blockIdx.x * 256;

    const int NCH = KP / 32;

    float acc[4][4][4];
#pragma unroll
    for (int i = 0; i < 4; i++)
#pragma unroll
        for (int j = 0; j < 4; j++)
#pragma unroll
            for (int e = 0; e < 4; e++) acc[i][j][e] = 0.f;

    auto load_chunk = [&](int c, int buf) {
        const int kc = c * 32;
        const uint32_t base = sm + buf * STAGE;
        {
            int row = tid >> 2, seg = tid & 3;
            size_t rg = row0 + row;
            int c0 = kc + seg * 8;
            uint32_t so = row * SROW + seg * 16;
            const __nv_bfloat16* hs;
            const __nv_bfloat16* ls;
            if (QSRC && c0 < 16) {
                hs = Qs + rg * 32 + c0;
                ls = Qs + rg * 32 + 16 + c0;
            } else {
                hs = Ap + rg * (size_t)KA + c0;
                ls = hs + KP;
            }
            cp_async16(base + S_AHI + so, hs);
            cp_async16(base + S_ALO + so, ls);
        }
#pragma unroll
        for (int l = 0; l < 2; l++) {
            int L = tid + l * 512;
            int row = L >> 2, seg = L & 3;
            const __nv_bfloat16* gb = Bp + (size_t)(col0 + row) * KA + kc + seg * 8;
            uint32_t so = row * SROW + seg * 16;
            cp_async16(base + S_BHI + so, gb);
            cp_async16(base + S_BLO + so, gb + KP);
        }
        cp_commit();
    };

    // prologue: fill NSTG-1 stages
#pragma unroll
    for (int s = 0; s < NSTG - 1; s++) load_chunk(s, s);

    for (int c = 0; c < NCH; c++) {
        cp_wait<NSTG - 2>();     // chunk c's group complete (thread-local)
        __syncthreads();         // all threads' copies visible; prior stage reads done
        int nc = c + NSTG - 1;
        if (nc < NCH) load_chunk(nc, nc % NSTG);   // overwrites stage (c-1)%NSTG — safe
        else          cp_commit();                  // dummy: uniform group accounting

        const uint32_t st = sm + (c % NSTG) * STAGE;
        const int g = lane >> 3, lr = lane & 7;

#pragma unroll
        for (int ks = 0; ks < 2; ks++) {
            const uint32_t acolo = (ks * 16 + (g >> 1) * 8) * 2;
            const uint32_t bcolo = (ks * 16 + (g & 1) * 8) * 2;
            uint32_t afh[4][4];
#pragma unroll
            for (int mt = 0; mt < 4; mt++) {
                int r = wr * 64 + mt * 16 + (g & 1) * 8 + lr;
                ldmx4(afh[mt][0], afh[mt][1], afh[mt][2], afh[mt][3],
                      st + S_AHI + r * SROW + acolo);
            }
            uint32_t bfh[4][2];
#pragma unroll
            for (int bt = 0; bt < 2; bt++) {
                int r = wc * 32 + bt * 16 + (g >> 1) * 8 + lr;
                uint32_t r0, r1, r2, r3;
                ldmx4(r0, r1, r2, r3, st + S_BHI + r * SROW + bcolo);
                bfh[bt * 2][0] = r0;     bfh[bt * 2][1] = r1;
                bfh[bt * 2 + 1][0] = r2; bfh[bt * 2 + 1][1] = r3;
            }
#pragma unroll
            for (int mt = 0; mt < 4; mt++)
#pragma unroll
                for (int nt = 0; nt < 4; nt++)
                    mma_bf16(acc[mt][nt], afh[mt], bfh[nt]);
            // A-lo x B-hi
#pragma unroll
            for (int mt = 0; mt < 4; mt++) {
                int r = wr * 64 + mt * 16 + (g & 1) * 8 + lr;
                uint32_t al[4];
                ldmx4(al[0], al[1], al[2], al[3], st + S_ALO + r * SROW + acolo);
#pragma unroll
                for (int nt = 0; nt < 4; nt++)
                    mma_bf16(acc[mt][nt], al, bfh[nt]);
            }
            // A-hi x B-lo
#pragma unroll
            for (int bt = 0; bt < 2; bt++) {
                int r = wc * 32 + bt * 16 + (g >> 1) * 8 + lr;
                uint32_t r0, r1, r2, r3;
                ldmx4(r0, r1, r2, r3, st + S_BLO + r * SROW + bcolo);
                uint32_t bl0[2] = {r0, r1}, bl1[2] = {r2, r3};
#pragma unroll
                for (int mt = 0; mt < 4; mt++) {
                    mma_bf16(acc[mt][bt * 2],     afh[mt], bl0);
                    mma_bf16(acc[mt][bt * 2 + 1], afh[mt], bl1);
                }
            }
        }
    }

    // epilogue: bias + ELU (+ [hi|lo] re-emit)
#pragma unroll
    for (int mt = 0; mt < 4; mt++) {
        size_t ra = row0 + wr * 64 + mt * 16 + (lane >> 2);
        size_t rb = ra + 8;
#pragma unroll
        for (int nt = 0; nt < 4; nt++) {
            int colg = col0 + wc * 32 + nt * 8 + (lane & 3) * 2;
            float b0 = bias[colg], b1 = bias[colg + 1];
            float v00 = acc[mt][nt][0] + b0, v01 = acc[mt][nt][1] + b1;
            float v10 = acc[mt][nt][2] + b0, v11 = acc[mt][nt][3] + b1;
            v00 = (v00 > 0.f) ? v00 : expm1f(v00);
            v01 = (v01 > 0.f) ? v01 : expm1f(v01);
            v10 = (v10 > 0.f) ? v10 : expm1f(v10);
            v11 = (v11 > 0.f) ? v11 : expm1f(v11);
            if (OUTM == 0) {
                *(float2*)(Cf + ra * (size_t)Nfull + colg) = make_float2(v00, v01);
                *(float2*)(Cf + rb * (size_t)Nfull + colg) = make_float2(v10, v11);
            } else {
                const size_t KTn = 2 * (size_t)KPn;
                __nv_bfloat162 hh, ll;
                __nv_bfloat16* pa = Cb + ra * KTn;
                hh.x = __float2bfloat16(v00); hh.y = __float2bfloat16(v01);
                ll.x = __float2bfloat16(v00 - __bfloat162float(hh.x));
                ll.y = __float2bfloat16(v01 - __bfloat162float(hh.y));
                *(__nv_bfloat162*)(pa + colg)       = hh;
                *(__nv_bfloat162*)(pa + KPn + colg) = ll;
                __nv_bfloat16* pb = Cb + rb * KTn;
                hh.x = __float2bfloat16(v10); hh.y = __float2bfloat16(v11);
                ll.x = __float2bfloat16(v10 - __bfloat162float(hh.x));
                ll.y = __float2bfloat16(v11 - __bfloat162float(hh.y));
                *(__nv_bfloat162*)(pb + colg)       = hh;
                *(__nv_bfloat162*)(pb + KPn + colg) = ll;
            }
        }
    }
}

// ---------------- narrow GEMM (N=16 or 12), fp32 SIMT ----------------
template <int NO, int KK, bool RLOSS>
__global__ __launch_bounds__(128) void ngemm_kernel(
    const float* __restrict__ A, const float* __restrict__ B,
    const float* __restrict__ bias, float* __restrict__ C,
    const float* __restrict__ ref, double* __restrict__ rloss)
{
    __shared__ float Bs[KK][NO];
    __shared__ float As[128][33];
    int tid = threadIdx.x;
    size_t row0 = (size_t)blockIdx.x * 128;
    for (int e = tid; e < KK * NO; e += 128) Bs[e / NO][e % NO] = B[e];
    float acc[NO];
#pragma unroll
    for (int j = 0; j < NO; j++) acc[j] = 0.f;

    for (int k0 = 0; k0 < KK; k0 += 32) {
        __syncthreads();
#pragma unroll
        for (int l = 0; l < 32; l++) {
            int e = tid + l * 128;
            int r = e >> 5, c = e & 31;
            As[r][c] = A[(row0 + r) * KK + k0 + c];
        }
        __syncthreads();
#pragma unroll
        for (int kk = 0; kk < 32; kk++) {
            float a = As[tid][kk];
#pragma unroll
            for (int j = 0; j < NO; j++) acc[j] = fmaf(a, Bs[k0 + kk][j], acc[j]);
        }
    }
    float rl = 0.f;
    size_t r = row0 + tid;
#pragma unroll
    for (int j = 0; j < NO; j++) {
        float v = acc[j] + bias[j];
        C[r * NO + j] = v;
        if (RLOSS) { float d = v - ref[r * NO + j]; rl += d * d; }
    }
    if (RLOSS) {
#pragma unroll
        for (int o = 16; o > 0; o >>= 1) rl += __shfl_down_sync(0xffffffffu, rl, o);
        __shared__ float ws[4];
        if ((tid & 31) == 0) ws[tid >> 5] = rl;
        __syncthreads();
        if (tid == 0) atomicAdd(rloss, (double)(ws[0] + ws[1] + ws[2] + ws[3]));
    }
}

// ---------------- quantize (+ near-tie candidates + qsplit emit) ----------------
__global__ __launch_bounds__(256) void quantize_kernel(
    const float* __restrict__ z, const float* __restrict__ emb,
    float* __restrict__ out_q, float* __restrict__ out_idx,
    float* __restrict__ dist, __nv_bfloat16* __restrict__ qs,
    int* __restrict__ counts, double* __restrict__ qlat,
    int* __restrict__ ncand, int* __restrict__ cand)
{
    __shared__ float embn[KCB][ED];
    __shared__ float zt[16][ED + 1];
    __shared__ float rinv[16];
    __shared__ float n2[16];
    __shared__ float sd[KCB][17];
    __shared__ int   shist[KCB];
    __shared__ float sq;
    int tid = threadIdx.x;
    size_t row0 = (size_t)blockIdx.x * 16;
    shist[tid] = 0;
    if (tid == 0) sq = 0.f;
    {
        float e[ED], s = 0.f;
#pragma unroll
        for (int j = 0; j < ED; j++) { e[j] = emb[tid * ED + j]; s += e[j] * e[j]; }
        float inv = 1.f / fmaxf(sqrtf(s), 1e-12f);
#pragma unroll
        for (int j = 0; j < ED; j++) embn[tid][j] = e[j] * inv;
    }
    { int r = tid >> 4, j = tid & 15; zt[r][j] = z[(row0 + r) * ED + j]; }
    __syncthreads();
    if (tid < 16) {
        float s = 0.f;
#pragma unroll
        for (int j = 0; j < ED; j++) s += zt[tid][j] * zt[tid][j];
        n2[tid] = s;
        rinv[tid] = 1.f / fmaxf(sqrtf(s), 1e-12f);
    }
    __syncthreads();
    for (int r = 0; r < 16; r++) {
        float s = 0.f;
#pragma unroll
        for (int j = 0; j < ED; j++) s += zt[r][j] * embn[tid][j];
        sd[tid][r] = s * rinv[r];
    }
    __syncthreads();
    int w = tid >> 5, lane = tid & 31;
    for (int c = 0; c < 32; c++) {
        int k = w * 32 + c;
        if (lane < 16) dist[(size_t)k * NROWS + row0 + lane] = sd[k][lane];
    }
    for (int rr = 0; rr < 2; rr++) {
        int r = w * 2 + rr;
        float best = -2.f; int bi = 0;
        for (int kk = lane; kk < KCB; kk += 32) {
            float v = sd[kk][r];
            if (v > best) { best = v; bi = kk; }
        }
#pragma unroll
        for (int o = 16; o > 0; o >>= 1) {
            float ov = __shfl_down_sync(0xffffffffu, best, o);
            int   oi = __shfl_down_sync(0xffffffffu, bi, o);
            if (ov > best || (ov == best && oi < bi)) { best = ov; bi = oi; }
        }
        bi   = __shfl_sync(0xffffffffu, bi, 0);
        best = __shfl_sync(0xffffffffu, best, 0);
        float sec = -2.f;
        for (int kk = lane; kk < KCB; kk += 32)
            if (kk != bi) sec = fmaxf(sec, sd[kk][r]);
#pragma unroll
        for (int o = 16; o > 0; o >>= 1)
            sec = fmaxf(sec, __shfl_down_sync(0xffffffffu, sec, o));
        float dd = 0.f;
        if (lane < ED) {
            float qv = emb[bi * ED + lane];
            float d = qv - zt[r][lane];
            out_q[(row0 + r) * ED + lane] = qv;
            __nv_bfloat16 h = __float2bfloat16(qv);
            qs[(row0 + r) * 32 + lane]      = h;
            qs[(row0 + r) * 32 + 16 + lane] = __float2bfloat16(qv - __bfloat162float(h));
            dd = d * d;
        }
#pragma unroll
        for (int o = 16; o > 0; o >>= 1) dd += __shfl_down_sync(0xffffffffu, dd, o);
        if (lane == 0) {
            atomicAdd(&sq, dd);
            atomicAdd(&shist[bi], 1);
            out_idx[row0 + r] = (float)bi;
            if (best - sec < GAP_TAU || n2[r] < 1e-4f) {
                int s = atomicAdd(ncand, 1);
                cand[s] = (int)(row0 + r);
            }
        }
    }
    __syncthreads();
    if (shist[tid]) atomicAdd(&counts[tid], shist[tid]);
    if (tid == 0) atomicAdd(qlat, (double)sq);
}

// ---------------- batched exact fp32 re-check of near-tie rows ----------------
#define RF_SMEM ((RB * 272 + RB * 512 + RB * 256 + RB * 16 + RB + RB * 256) * 4 + RB * 12)
__global__ __launch_bounds__(256) void refine_kernel(
    const float* __restrict__ actions, const float* __restrict__ conditions,
    const float* __restrict__ ew1, const float* __restrict__ eb1,
    const float* __restrict__ ew2, const float* __restrict__ eb2,
    const float* __restrict__ ew3, const float* __restrict__ eb3,
    const float* __restrict__ emb,
    const float* __restrict__ zbf,
    float* __restrict__ out_q, float* __restrict__ out_idx,
    __nv_bfloat16* __restrict__ qs,
    int* __restrict__ counts, double* __restrict__ qlat,
    const int* __restrict__ ncand, const int* __restrict__ cand)
{
    extern __shared__ float sh[];
    float* xs   = sh;                        // RB*272
    float* h1s  = xs + RB * 272;             // RB*512
    float* h2s  = h1s + RB * 512;            // RB*256
    float* zs   = h2s + RB * 256;            // RB*16
    float* zinv = zs + RB * 16;              // RB
    float* ds   = zinv + RB;                 // RB*256
    int*   ri   = (int*)(ds + RB * 256);     // RB
    int*   vl   = ri + RB;                   // RB
    int*   ni   = vl + RB;                   // RB

    int tid = threadIdx.x;
    int n = *ncand;
    for (int bi = blockIdx.x; bi * RB < n; bi += gridDim.x) {
        if (tid < RB) {
            int idx = bi * RB + tid;
            vl[tid] = (idx < n);
            ri[tid] = cand[(idx < n) ? idx : (n - 1)];
        }
        __syncthreads();
        for (int e = tid; e < RB * 268; e += 256) {
            int r = e / 268, j = e % 268;
            size_t row = (size_t)ri[r];
            xs[r * 272 + j] = (j < ACT_D) ? actions[row * ACT_D + j]
                                          : conditions[row * COND_D + (j - ACT_D)];
        }
        __syncthreads();
#pragma unroll
        for (int cc = 0; cc < 2; cc++) {
            int c = tid + cc * 256;
            float a0[RB];
            float b = eb1[c];
#pragma unroll
            for (int r = 0; r < RB; r++) a0[r] = b;
            for (int k = 0; k < 268; k++) {
                float w = ew1[(size_t)k * H1D + c];
#pragma unroll
                for (int r = 0; r < RB; r++) a0[r] = fmaf(xs[r * 272 + k], w, a0[r]);
            }
#pragma unroll
            for (int r = 0; r < RB; r++)
                h1s[r * 512 + c] = (a0[r] > 0.f) ? a0[r] : expm1f(a0[r]);
        }
        __syncthreads();
        {
            int c = tid;
            float a0[RB];
            float b = eb2[c];
#pragma unroll
            for (int r = 0; r < RB; r++) a0[r] = b;
            for (int k = 0; k < 512; k++) {
                float w = ew2[(size_t)k * H2D + c];
#pragma unroll
                for (int r = 0; r < RB; r++) a0[r] = fmaf(h1s[r * 512 + k], w, a0[r]);
            }
#pragma unroll
            for (int r = 0; r < RB; r++)
                h2s[r * 256 + c] = (a0[r] > 0.f) ? a0[r] : expm1f(a0[r]);
        }
        __syncthreads();
        {
            int r = tid >> 4, c = tid & 15;
            float s = eb3[c];
            for (int k = 0; k < 256; k++)
                s = fmaf(h2s[r * 256 + k], ew3[(size_t)k * ED + c], s);
            zs[r * 16 + c] = s;
        }
        __syncthreads();
        if (tid < RB) {
            float s = 0.f;
#pragma unroll
            for (int j = 0; j < ED; j++) s += zs[tid * 16 + j] * zs[tid * 16 + j];
            zinv[tid] = 1.f / fmaxf(sqrtf(s), 1e-12f);
        }
        __syncthreads();
        {
            int c = tid;
            float e[ED], s = 0.f;
#pragma unroll
            for (int j = 0; j < ED; j++) { e[j] = emb[c * ED + j]; s += e[j] * e[j]; }
            float inv = 1.f / fmaxf(sqrtf(s), 1e-12f);
#pragma unroll
            for (int r = 0; r < RB; r++) {
                float dot = 0.f;
#pragma unroll
                for (int j = 0; j < ED; j++)
                    dot += (zs[r * 16 + j] * zinv[r]) * (e[j] * inv);
                ds[r * 256 + c] = dot;
            }
        }
        __syncthreads();
        {
            int w = tid >> 5, lane = tid & 31;
#pragma unroll
            for (int rr = 0; rr < 2; rr++) {
                int r = w * 2 + rr;
                float best = -2.f; int bidx = 0;
                for (int kk = lane; kk < KCB; kk += 32) {
                    float v = ds[r * 256 + kk];
                    if (v > best) { best = v; bidx = kk; }
                }
#pragma unroll
                for (int o = 16; o > 0; o >>= 1) {
                    float ov = __shfl_down_sync(0xffffffffu, best, o);
                    int   oi = __shfl_down_sync(0xffffffffu, bidx, o);
                    if (ov > best || (ov == best && oi < bidx)) { best = ov; bidx = oi; }
                }
                if (lane == 0) ni[r] = bidx;
            }
        }
        __syncthreads();
        if (tid < RB && vl[tid]) {
            size_t row = (size_t)ri[tid];
            int oldidx = (int)out_idx[row];
            int newidx = ni[tid];
            if (newidx != oldidx) {
                out_idx[row] = (float)newidx;
                atomicSub(counts + oldidx, 1);
                atomicAdd(counts + newidx, 1);
                float dq = 0.f;
#pragma unroll
                for (int j = 0; j < ED; j++) {
                    float zb = zbf[row * ED + j];
                    float qv = emb[newidx * ED + j];
                    float dn = qv - zb;
                    float dl = emb[oldidx * ED + j] - zb;
                    dq += dn * dn - dl * dl;
                    out_q[row * ED + j] = qv;
                    __nv_bfloat16 h = __float2bfloat16(qv);
                    qs[row * 32 + j]      = h;
                    qs[row * 32 + 16 + j] = __float2bfloat16(qv - __bfloat162float(h));
                }
                atomicAdd(qlat, (double)dq);
            }
        }
        __syncthreads();
    }
}

// ---------------- per-column order statistics + contra loss ----------------
__global__ __launch_bounds__(256) void select_kernel(
    const float* __restrict__ dist, double* __restrict__ contra)
{
    __shared__ unsigned ha[2048], hb[2048];
    __shared__ unsigned s_bin[2], s_rem[2];
    __shared__ float rf[256];
    int tid = threadIdx.x;
    const float* col = dist + (size_t)blockIdx.x * NROWS;
    const unsigned RA = NROWS / 2 - 1;
    const unsigned RBK = NROWS - 512;

    for (int i = tid; i < 2048; i += 256) ha[i] = 0;
    __syncthreads();
    for (int i = tid; i < NROWS; i += 256) atomicAdd(&ha[fkey(col[i]) >> 21], 1u);
    __syncthreads();
    if (tid == 0) {
        unsigned c = 0;
        for (unsigned b = 0; b < 2048; b++) {
            unsigned h = ha[b];
            if (c <= RA && c + h > RA) { s_bin[0] = b; s_rem[0] = RA - c; }
            if (c <= RBK && c + h > RBK) { s_bin[1] = b; s_rem[1] = RBK - c; }
            c += h;
        }
    }
    __syncthreads();
    unsigned p0a = s_bin[0], p0b = s_bin[1];
    unsigned rema = s_rem[0], remb = s_rem[1];
    __syncthreads();

    for (int i = tid; i < 2048; i += 256) { ha[i] = 0; hb[i] = 0; }
    __syncthreads();
    for (int i = tid; i < NROWS; i += 256) {
        unsigned u = fkey(col[i]);
        unsigned t = u >> 21, m = (u >> 10) & 2047u;
        if (t == p0a) atomicAdd(&ha[m], 1u);
        if (t == p0b) atomicAdd(&hb[m], 1u);
    }
    __syncthreads();
    if (tid == 0) { unsigned c = 0; for (unsigned b = 0; b < 2048; b++) { unsigned h = ha[b];
        if (c + h > rema) { s_bin[0] = b; s_rem[0] = rema - c; break; } c += h; } }
    if (tid == 1) { unsigned c = 0; for (unsigned b = 0; b < 2048; b++) { unsigned h = hb[b];
        if (c + h > remb) { s_bin[1] = b; s_rem[1] = remb - c; break; } c += h; } }
    __syncthreads();
    unsigned p1a = (p0a << 11) | s_bin[0], p1b = (p0b << 11) | s_bin[1];
    rema = s_rem[0]; remb = s_rem[1];
    __syncthreads();

    for (int i = tid; i < 1024; i += 256) { ha[i] = 0; hb[i] = 0; }
    __syncthreads();
    for (int i = tid; i < NROWS; i += 256) {
        unsigned u = fkey(col[i]);
        if ((u >> 10) == p1a) atomicAdd(&ha[u & 1023u], 1u);
        if ((u >> 10) == p1b) atomicAdd(&hb[u & 1023u], 1u);
    }
    __syncthreads();
    if (tid == 0) { unsigned c = 0; for (unsigned b = 0; b < 1024; b++) { unsigned h = ha[b];
        if (c + h > rema) { s_bin[0] = b; break; } c += h; } }
    if (tid == 1) { unsigned c = 0; for (unsigned b = 0; b < 1024; b++) { unsigned h = hb[b];
        if (c + h > remb) { s_bin[1] = b; break; } c += h; } }
    __syncthreads();
    unsigned km = (p1a << 10) | s_bin[0];
    unsigned kt = (p1b << 10) | s_bin[1];

    float Tmed = finv(km);
    const float INV_TAU = 1.0f / 0.07f;
    int cgt = 0, clt = 0;
    float sgt = 0.f, sexp = 0.f;
    for (int i = tid; i < NROWS; i += 256) {
        float x = col[i];
        unsigned u = fkey(x);
        if (u > kt) { cgt++; sgt += x; }
        if (u < km) { clt++; sexp += expf((x - Tmed) * INV_TAU); }
    }
    float CGT, SGT, CLT, SEXP;
    rf[tid] = (float)cgt; __syncthreads();
    for (int s = 128; s; s >>= 1) { if (tid < s) rf[tid] += rf[tid + s]; __syncthreads(); }
    CGT = rf[0]; __syncthreads();
    rf[tid] = sgt; __syncthreads();
    for (int s = 128; s; s >>= 1) { if (tid < s) rf[tid] += rf[tid + s]; __syncthreads(); }
    SGT = rf[0]; __syncthreads();
    rf[tid] = (float)clt; __syncthreads();
    for (int s = 128; s; s >>= 1) { if (tid < s) rf[tid] += rf[tid + s]; __syncthreads(); }
    CLT = rf[0]; __syncthreads();
    rf[tid] = sexp; __syncthreads();
    for (int s = 128; s; s >>= 1) { if (tid < s) rf[tid] += rf[tid + s]; __syncthreads(); }
    SEXP = rf[0];

    if (tid == 0) {
        float Ttop = finv(kt);
        float dis_pos = (SGT + (512.0f - CGT) * Ttop) * (1.0f / 512.0f);
        float Sx = SEXP + ((float)(NROWS / 2) - CLT);
        float a = dis_pos * INV_TAU, b = Tmed * INV_TAU;
        float m = fmaxf(a, b);
        float lse = m + logf(expf(a - m) + Sx * expf(b - m));
        atomicAdd(contra, (double)(lse - a));
    }
}

// ---------------- finalize scalars ----------------
__global__ void finalize_kernel(const int* __restrict__ counts,
                                const double* __restrict__ qlat,
                                const double* __restrict__ contra,
                                const double* __restrict__ recon,
                                float* __restrict__ out_sc)
{
    __shared__ float rr[256];
    int t = threadIdx.x;
    float p = (float)counts[t] / (float)NROWS;
    rr[t] = p * logf(p + 1e-10f);
    __syncthreads();
    for (int s = 128; s; s >>= 1) { if (t < s) rr[t] += rr[t + s]; __syncthreads(); }
    if (t == 0) {
        float q = (float)(*qlat / ((double)NROWS * ED));
        out_sc[0] = q;
        out_sc[1] = 0.25f * q;
        out_sc[2] = (float)(*contra / (double)KCB);
        out_sc[3] = expf(-rr[0]);
        out_sc[4] = (float)(*recon / ((double)NROWS * ACT_D));
    }
}

// ---------------- launch ----------------
extern "C" void kernel_launch(void* const* d_in, const int* in_sizes, int n_in,
                              void* d_out, int out_size)
{
    const float* actions    = (const float*)d_in[0];
    const float* conditions = (const float*)d_in[1];
    const float* enc_w1 = (const float*)d_in[2];  const float* enc_b1 = (const float*)d_in[3];
    const float* enc_w2 = (const float*)d_in[4];  const float* enc_b2 = (const float*)d_in[5];
    const float* enc_w3 = (const float*)d_in[6];  const float* enc_b3 = (const float*)d_in[7];
    const float* dec_w1 = (const float*)d_in[8];  const float* dec_b1 = (const float*)d_in[9];
    const float* dec_w2 = (const float*)d_in[10]; const float* dec_b2 = (const float*)d_in[11];
    const float* dec_w3 = (const float*)d_in[12]; const float* dec_b3 = (const float*)d_in[13];
    const float* embedding = (const float*)d_in[14];

    float* out = (float*)d_out;
    float* out_rec = out;
    float* out_q   = out + (size_t)NROWS * ACT_D;
    float* out_idx = out_q + (size_t)NROWS * ED;
    float* out_sc  = out_idx + NROWS;

    __nv_bfloat16 *A1, *Ah1, *Aq, *Ad1, *B1, *B2, *B3, *B4;
    float *h2, *z, *dist, *d2;
    double *qlat, *contra, *recon; int *counts, *ncand, *cand;
    cudaGetSymbolAddress((void**)&A1,  g_A1);
    cudaGetSymbolAddress((void**)&Ah1, g_Ah1);
    cudaGetSymbolAddress((void**)&Aq,  g_Aq);
    cudaGetSymbolAddress((void**)&Ad1, g_Ad1);
    cudaGetSymbolAddress((void**)&B1,  g_B1);
    cudaGetSymbolAddress((void**)&B2,  g_B2);
    cudaGetSymbolAddress((void**)&B3,  g_B3);
    cudaGetSymbolAddress((void**)&B4,  g_B4);
    cudaGetSymbolAddress((void**)&h2,  g_h2);
    cudaGetSymbolAddress((void**)&z,   g_z);
    cudaGetSymbolAddress((void**)&dist,g_dist);
    cudaGetSymbolAddress((void**)&d2,  g_d2);
    cudaGetSymbolAddress((void**)&qlat,  g_qlat);
    cudaGetSymbolAddress((void**)&contra,g_contra);
    cudaGetSymbolAddress((void**)&recon, g_recon);
    cudaGetSymbolAddress((void**)&counts,g_counts);
    cudaGetSymbolAddress((void**)&ncand, g_ncand);
    cudaGetSymbolAddress((void**)&cand,  g_cand);

    cudaFuncSetAttribute((const void*)tgemm<KP1, 1, false>, cudaFuncAttributeMaxDynamicSharedMemorySize, TG_SMEM);
    cudaFuncSetAttribute((const void*)tgemm<KP2, 0, false>, cudaFuncAttributeMaxDynamicSharedMemorySize, TG_SMEM);
    cudaFuncSetAttribute((const void*)tgemm<KP1, 1, true>,  cudaFuncAttributeMaxDynamicSharedMemorySize, TG_SMEM);
    cudaFuncSetAttribute((const void*)tgemm<KP4, 0, false>, cudaFuncAttributeMaxDynamicSharedMemorySize, TG_SMEM);
    cudaFuncSetAttribute((const void*)refine_kernel, cudaFuncAttributeMaxDynamicSharedMemorySize, RF_SMEM);

    init_kernel<<<1, 256>>>(counts, qlat, contra, recon, ncand);                        // 1
    conv_w_kernel<<<((size_t)H1D * KA1 + 255) / 256, 256>>>(enc_w1, 12, 268, H1D, B1, KP1, KA1); // 2
    conv_cat_kernel<<<((size_t)NROWS * (KP1 / 2) + 255) / 256, 256>>>(
        actions, ACT_D, conditions, COND_D, A1, KP1, KA1);                              // 3
    // enc1: 268 -> 512 ([hi|lo] out)
    tgemm<KP1, 1, false><<<dim3(2, NROWS / 128), 512, TG_SMEM>>>(
        A1, B1, nullptr, enc_b1, nullptr, Ah1, H1D, KP2);                               // 4
    conv_w_kernel<<<((size_t)H2D * KA2 + 255) / 256, 256>>>(enc_w2, 16, 512, H2D, B2, KP2, KA2); // 5
    // enc2: 512 -> 256 (fp32 out)  [note: enc2 weights use identity map via ad=16 only
    //  if K+? -- enc2 input has no concat; ad=16 gives row=c for c<16 and c-0 for c>=16]
    tgemm<KP2, 0, false><<<dim3(1, NROWS / 128), 512, TG_SMEM>>>(
        Ah1, B2, nullptr, enc_b2, h2, nullptr, H2D, 0);                                 // 6
    // enc3: 256 -> 16 (fp32 SIMT, no ELU)
    ngemm_kernel<ED, H2D, false><<<NROWS / 128, 128>>>(h2, enc_w3, enc_b3, z, nullptr, nullptr);

    quantize_kernel<<<NROWS / 16, 256>>>(z, embedding, out_q, out_idx, dist, Aq,
                                         counts, qlat, ncand, cand);
    refine_kernel<<<2048, 256, RF_SMEM>>>(actions, conditions,
                                 enc_w1, enc_b1, enc_w2, enc_b2, enc_w3, enc_b3,
                                 embedding, z, out_q, out_idx, Aq, counts, qlat, ncand, cand);

    conv_w_kernel<<<((size_t)H2D * KA1 + 255) / 256, 256>>>(dec_w1, 16, 272, H2D, B3, KP1, KA1);
    conv_w_kernel<<<((size_t)H1D * KA4 + 255) / 256, 256>>>(dec_w2, 16, 256, H1D, B4, KP4, KA4);
    select_kernel<<<KCB, 256>>>(dist, contra);

    // dec1: 272 -> 256 ([hi|lo] out) — A cols [0,16) from qsplit, rest reuses A1
    tgemm<KP1, 1, true><<<dim3(1, NROWS / 128), 512, TG_SMEM>>>(
        A1, B3, Aq, dec_b1, nullptr, Ad1, H2D, KP4);
    // dec2: 256 -> 512 (fp32 out)
    tgemm<KP4, 0, false><<<dim3(2, NROWS / 128), 512, TG_SMEM>>>(
        Ad1, B4, nullptr, dec_b2, d2, nullptr, H1D, 0);
    // dec3: 512 -> 12 + reconstruction loss
    ngemm_kernel<ACT_D, H1D, true><<<NROWS / 128, 128>>>(d2, dec_w3, dec_b3, out_rec, actions, recon);

    finalize_kernel<<<1, 256>>>(counts, qlat, contra, recon, out_sc);
}

// round 13
// speedup vs baseline: 1.1885x; 1.0321x over previous
#include <cuda_runtime.h>
#include <cuda_bf16.h>
#include <math.h>
#include <stdint.h>

#define NROWS 131072
#define ACT_D 12
#define COND_D 256
#define KCB 256
#define ED 16
#define H1D 512
#define H2D 256

// Unified K-layout: small block at [0,16), conditions at [16,272).
#define KP1 288
#define KA1 576      // enc1 / dec1 inputs
#define KP2 512
#define KA2 1024     // enc2 input (K=512)
#define KP4 256
#define KA4 512      // dec2 input (K=256)

#define GAP_TAU 2e-3f
#define RB 16        // refine batch rows per block

// ---------------- scratch (static device globals; no allocs) ----------------
__device__ __nv_bfloat16 g_A1 [(size_t)NROWS * KA1];
__device__ __nv_bfloat16 g_Ah1[(size_t)NROWS * KA2];
__device__ __nv_bfloat16 g_Aq [(size_t)NROWS * 32];   // quantized [hi(16)|lo(16)]
__device__ __nv_bfloat16 g_Ad1[(size_t)NROWS * KA4];
__device__ __nv_bfloat16 g_B1 [(size_t)H1D * KA1];
__device__ __nv_bfloat16 g_B2 [(size_t)H2D * KA2];
__device__ __nv_bfloat16 g_B3 [(size_t)H2D * KA1];
__device__ __nv_bfloat16 g_B4 [(size_t)H1D * KA4];
__device__ float g_z   [(size_t)NROWS * ED];
__device__ float g_dist[(size_t)KCB * NROWS];   // transposed: [k][n]
__device__ double g_qlat, g_contra, g_recon;
__device__ int    g_counts[KCB];
__device__ int    g_ncand;
__device__ int    g_cand[NROWS];

// ---------------- helpers ----------------
__device__ __forceinline__ uint32_t smem_u32(const void* p) {
    uint32_t a;
    asm("{ .reg .u64 t; cvta.to.shared.u64 t, %1; cvt.u32.u64 %0, t; }"
        : "=r"(a) : "l"(p));
    return a;
}
__device__ __forceinline__ void cp_async16(uint32_t s, const void* g) {
    asm volatile("cp.async.cg.shared.global [%0], [%1], 16;" :: "r"(s), "l"(g) : "memory");
}
__device__ __forceinline__ void cp_commit() {
    asm volatile("cp.async.commit_group;" ::: "memory");
}
template <int N>
__device__ __forceinline__ void cp_wait() {
    asm volatile("cp.async.wait_group %0;" :: "n"(N) : "memory");
}
__device__ __forceinline__ void ldmx4(uint32_t& r0, uint32_t& r1, uint32_t& r2, uint32_t& r3,
                                      uint32_t addr) {
    asm volatile("ldmatrix.sync.aligned.m8n8.x4.shared.b16 {%0,%1,%2,%3}, [%4];"
                 : "=r"(r0), "=r"(r1), "=r"(r2), "=r"(r3) : "r"(addr));
}
__device__ __forceinline__ void mma_bf16(float* c, const uint32_t* a, const uint32_t* b) {
    asm volatile("mma.sync.aligned.m16n8k16.row.col.f32.bf16.bf16.f32 "
                 "{%0,%1,%2,%3}, {%4,%5,%6,%7}, {%8,%9}, {%0,%1,%2,%3};"
                 : "+f"(c[0]), "+f"(c[1]), "+f"(c[2]), "+f"(c[3])
                 : "r"(a[0]), "r"(a[1]), "r"(a[2]), "r"(a[3]), "r"(b[0]), "r"(b[1]));
}
__device__ __forceinline__ unsigned fkey(float x) {
    unsigned u = __float_as_uint(x);
    return (u & 0x80000000u) ? ~u : (u | 0x80000000u);
}
__device__ __forceinline__ float finv(unsigned k) {
    return (k & 0x80000000u) ? __uint_as_float(k & 0x7fffffffu)
                             : __uint_as_float(~k);
}

// ---------------- init ----------------
__global__ void init_kernel(int* counts, double* a, double* b, double* c, int* ncand) {
    int t = threadIdx.x;
    counts[t] = 0;
    if (t == 0) { *a = 0.0; *b = 0.0; *c = 0.0; *ncand = 0; }
}
// out_rec pre-seeded with dec_b3 (dec2 epilogue atomically accumulates partials)
__global__ void rec_init_kernel(const float* __restrict__ b3, float* __restrict__ rec) {
    size_t i = (size_t)blockIdx.x * 256 + threadIdx.x;
    if (i < (size_t)NROWS * ACT_D) rec[i] = b3[i % ACT_D];
}
// reconstruction loss from completed out_rec
__global__ void recon_kernel(const float* __restrict__ rec, const float* __restrict__ act,
                             double* __restrict__ out) {
    __shared__ float rf[256];
    int tid = threadIdx.x;
    float s = 0.f;
    for (size_t i = (size_t)blockIdx.x * 256 + tid; i < (size_t)NROWS * ACT_D;
         i += (size_t)gridDim.x * 256) {
        float d = rec[i] - act[i];
        s += d * d;
    }
    rf[tid] = s; __syncthreads();
    for (int st = 128; st; st >>= 1) { if (tid < st) rf[tid] += rf[tid + st]; __syncthreads(); }
    if (tid == 0) atomicAdd(out, (double)rf[0]);
}

// ---------------- split conversions (unified layout, 2-segment [hi|lo]) ----------
__global__ void conv_cat_kernel(const float* __restrict__ a, int ad,
                                const float* __restrict__ b, int bd,
                                __nv_bfloat16* __restrict__ o, int KP, int KA)
{
    int pairs = KP >> 1;
    size_t t = (size_t)blockIdx.x * 256 + threadIdx.x;
    size_t row = t / pairs;
    if (row >= NROWS) return;
    int p = (int)(t % pairs);
    int j = p * 2;
    float v0 = 0.f, v1 = 0.f;
    if (j < 16) {
        if (j < ad)     v0 = a[row * ad + j];
        if (j + 1 < ad) v1 = a[row * ad + j + 1];
    } else {
        int c = j - 16;
        if (c < bd)     v0 = b[row * bd + c];
        if (c + 1 < bd) v1 = b[row * bd + c + 1];
    }
    __nv_bfloat162 hh, ll;
    hh.x = __float2bfloat16(v0); hh.y = __float2bfloat16(v1);
    ll.x = __float2bfloat16(v0 - __bfloat162float(hh.x));
    ll.y = __float2bfloat16(v1 - __bfloat162float(hh.y));
    __nv_bfloat16* base = o + row * (size_t)KA;
    ((__nv_bfloat162*)(base))[p]      = hh;
    ((__nv_bfloat162*)(base + KP))[p] = ll;
}
__global__ void conv_w_kernel(const float* __restrict__ W, int ad, int K, int Nn,
                              __nv_bfloat16* __restrict__ o, int KP, int KA)
{
    size_t t = (size_t)blockIdx.x * 256 + threadIdx.x;
    if (t >= (size_t)Nn * KA) return;
    int n  = (int)(t / KA);
    int kt = (int)(t % KA);
    int s  = kt < KP ? 0 : 1;
    int c  = kt - s * KP;
    int k  = (c < 16) ? ((c < ad) ? c : -1) : (c - (16 - ad));
    float v = (k >= 0 && k < K) ? W[(size_t)k * Nn + n] : 0.f;
    __nv_bfloat16 h = __float2bfloat16(v);
    __nv_bfloat16 r = s ? __float2bfloat16(v - __bfloat162float(h)) : h;
    o[(size_t)n * KA + kt] = r;
}

// ---------------- tensor-core GEMM: 128x256 CTA tile, 16 warps, 3-stage pipe ----
// OUTM 1: bf16 [hi|lo] out (segment KPn)
// OUTM 2: fused z-epilogue (full-K tile): z = elu(tile) @ W3[256x16] + B3o  -> Zf
// OUTM 3: fused partial-rec epilogue: atomicAdd(Rf, elu(tile) @ W3slice[.,12])
#define SROW 80
#define S_AHI 0
#define S_ALO 10240
#define S_BHI 20480
#define S_BLO 40960
#define STAGE 61440
#define NSTG 3
#define TG_SMEM (NSTG * STAGE)
#define ERS 258   // fp32 epilogue smem row stride

template <int KP, int OUTM, bool QSRC>
__global__ __launch_bounds__(512, 1) void tgemm(
    const __nv_bfloat16* __restrict__ Ap,
    const __nv_bfloat16* __restrict__ Bp,
    const __nv_bfloat16* __restrict__ Qs,
    const float* __restrict__ bias,
    const float* __restrict__ W3,
    const float* __restrict__ B3o,
    float* __restrict__ Zf,
    __nv_bfloat16* __restrict__ Cb,
    float* __restrict__ Rf,
    int KPn)
{
    extern __shared__ __align__(16) uint8_t smem[];
    const uint32_t sm = smem_u32(smem);
    const int KA = 2 * KP;

    const int tid = threadIdx.x;
    const int wid = tid >> 5, lane = tid & 31;
    const int wr = wid >> 3, wc = wid & 7;          // warps 2 x 8
    const size_t row0 = (size_t)blockIdx.y * 128;
    const int    col0 = blockIdx.x * 256;

    const int NCH = KP / 32;

    float acc[4][4][4];
#pragma unroll
    for (int i = 0; i < 4; i++)
#pragma unroll
        for (int j = 0; j < 4; j++)
#pragma unroll
            for (int e = 0; e < 4; e++) acc[i][j][e] = 0.f;

    auto load_chunk = [&](int c, int buf) {
        const int kc = c * 32;
        const uint32_t base = sm + buf * STAGE;
        {
            int row = tid >> 2, seg = tid & 3;
            size_t rg = row0 + row;
            int c0 = kc + seg * 8;
            uint32_t so = row * SROW + seg * 16;
            const __nv_bfloat16* hs;
            const __nv_bfloat16* ls;
            if (QSRC && c0 < 16) {
                hs = Qs + rg * 32 + c0;
                ls = Qs + rg * 32 + 16 + c0;
            } else {
                hs = Ap + rg * (size_t)KA + c0;
                ls = hs + KP;
            }
            cp_async16(base + S_AHI + so, hs);
            cp_async16(base + S_ALO + so, ls);
        }
#pragma unroll
        for (int l = 0; l < 2; l++) {
            int L = tid + l * 512;
            int row = L >> 2, seg = L & 3;
            const __nv_bfloat16* gb = Bp + (size_t)(col0 + row) * KA + kc + seg * 8;
            uint32_t so = row * SROW + seg * 16;
            cp_async16(base + S_BHI + so, gb);
            cp_async16(base + S_BLO + so, gb + KP);
        }
        cp_commit();
    };

#pragma unroll
    for (int s = 0; s < NSTG - 1; s++) load_chunk(s, s);

    for (int c = 0; c < NCH; c++) {
        cp_wait<NSTG - 2>();
        __syncthreads();
        int nc = c + NSTG - 1;
        if (nc < NCH) load_chunk(nc, nc % NSTG);
        else          cp_commit();

        const uint32_t st = sm + (c % NSTG) * STAGE;
        const int g = lane >> 3, lr = lane & 7;

#pragma unroll
        for (int ks = 0; ks < 2; ks++) {
            const uint32_t acolo = (ks * 16 + (g >> 1) * 8) * 2;
            const uint32_t bcolo = (ks * 16 + (g & 1) * 8) * 2;
            uint32_t afh[4][4];
#pragma unroll
            for (int mt = 0; mt < 4; mt++) {
                int r = wr * 64 + mt * 16 + (g & 1) * 8 + lr;
                ldmx4(afh[mt][0], afh[mt][1], afh[mt][2], afh[mt][3],
                      st + S_AHI + r * SROW + acolo);
            }
            uint32_t bfh[4][2];
#pragma unroll
            for (int bt = 0; bt < 2; bt++) {
                int r = wc * 32 + bt * 16 + (g >> 1) * 8 + lr;
                uint32_t r0, r1, r2, r3;
                ldmx4(r0, r1, r2, r3, st + S_BHI + r * SROW + bcolo);
                bfh[bt * 2][0] = r0;     bfh[bt * 2][1] = r1;
                bfh[bt * 2 + 1][0] = r2; bfh[bt * 2 + 1][1] = r3;
            }
#pragma unroll
            for (int mt = 0; mt < 4; mt++)
#pragma unroll
                for (int nt = 0; nt < 4; nt++)
                    mma_bf16(acc[mt][nt], afh[mt], bfh[nt]);
#pragma unroll
            for (int mt = 0; mt < 4; mt++) {
                int r = wr * 64 + mt * 16 + (g & 1) * 8 + lr;
                uint32_t al[4];
                ldmx4(al[0], al[1], al[2], al[3], st + S_ALO + r * SROW + acolo);
#pragma unroll
                for (int nt = 0; nt < 4; nt++)
                    mma_bf16(acc[mt][nt], al, bfh[nt]);
            }
#pragma unroll
            for (int bt = 0; bt < 2; bt++) {
                int r = wc * 32 + bt * 16 + (g >> 1) * 8 + lr;
                uint32_t r0, r1, r2, r3;
                ldmx4(r0, r1, r2, r3, st + S_BLO + r * SROW + bcolo);
                uint32_t bl0[2] = {r0, r1}, bl1[2] = {r2, r3};
#pragma unroll
                for (int mt = 0; mt < 4; mt++) {
                    mma_bf16(acc[mt][bt * 2],     afh[mt], bl0);
                    mma_bf16(acc[mt][bt * 2 + 1], afh[mt], bl1);
                }
            }
        }
    }

    if (OUTM == 1) {
        // [hi|lo] re-emit
#pragma unroll
        for (int mt = 0; mt < 4; mt++) {
            size_t ra = row0 + wr * 64 + mt * 16 + (lane >> 2);
            size_t rb = ra + 8;
#pragma unroll
            for (int nt = 0; nt < 4; nt++) {
                int colg = col0 + wc * 32 + nt * 8 + (lane & 3) * 2;
                float b0 = bias[colg], b1 = bias[colg + 1];
                float v00 = acc[mt][nt][0] + b0, v01 = acc[mt][nt][1] + b1;
                float v10 = acc[mt][nt][2] + b0, v11 = acc[mt][nt][3] + b1;
                v00 = (v00 > 0.f) ? v00 : expm1f(v00);
                v01 = (v01 > 0.f) ? v01 : expm1f(v01);
                v10 = (v10 > 0.f) ? v10 : expm1f(v10);
                v11 = (v11 > 0.f) ? v11 : expm1f(v11);
                const size_t KTn = 2 * (size_t)KPn;
                __nv_bfloat162 hh, ll;
                __nv_bfloat16* pa = Cb + ra * KTn;
                hh.x = __float2bfloat16(v00); hh.y = __float2bfloat16(v01);
                ll.x = __float2bfloat16(v00 - __bfloat162float(hh.x));
                ll.y = __float2bfloat16(v01 - __bfloat162float(hh.y));
                *(__nv_bfloat162*)(pa + colg)       = hh;
                *(__nv_bfloat162*)(pa + KPn + colg) = ll;
                __nv_bfloat16* pb = Cb + rb * KTn;
                hh.x = __float2bfloat16(v10); hh.y = __float2bfloat16(v11);
                ll.x = __float2bfloat16(v10 - __bfloat162float(hh.x));
                ll.y = __float2bfloat16(v11 - __bfloat162float(hh.y));
                *(__nv_bfloat162*)(pb + colg)       = hh;
                *(__nv_bfloat162*)(pb + KPn + colg) = ll;
            }
        }
    } else {
        // fused epilogue: stage elu(tile) to smem fp32 then small GEMM
        __syncthreads();                    // all mainloop smem reads done
        float* fsm = (float*)smem;
#pragma unroll
        for (int mt = 0; mt < 4; mt++) {
            int ra = wr * 64 + mt * 16 + (lane >> 2);
            int rb = ra + 8;
#pragma unroll
            for (int nt = 0; nt < 4; nt++) {
                int colL = wc * 32 + nt * 8 + (lane & 3) * 2;
                float b0 = bias[col0 + colL], b1 = bias[col0 + colL + 1];
                float v00 = acc[mt][nt][0] + b0, v01 = acc[mt][nt][1] + b1;
                float v10 = acc[mt][nt][2] + b0, v11 = acc[mt][nt][3] + b1;
                v00 = (v00 > 0.f) ? v00 : expm1f(v00);
                v01 = (v01 > 0.f) ? v01 : expm1f(v01);
                v10 = (v10 > 0.f) ? v10 : expm1f(v10);
                v11 = (v11 > 0.f) ? v11 : expm1f(v11);
                *(float2*)(fsm + ra * ERS + colL) = make_float2(v00, v01);
                *(float2*)(fsm + rb * ERS + colL) = make_float2(v10, v11);
            }
        }
        __syncthreads();
        if (OUTM == 2) {
            // z: 128 rows x 16 cols, K = 256 (this CTA covers the full K)
            int r = tid >> 2, jb = (tid & 3) * 4;
            float s0 = B3o[jb], s1 = B3o[jb + 1], s2 = B3o[jb + 2], s3 = B3o[jb + 3];
            const float* fr = fsm + r * ERS;
            for (int k = 0; k < 256; k++) {
                float a = fr[k];
                const float4 w = *(const float4*)(W3 + k * 16 + jb);
                s0 = fmaf(a, w.x, s0); s1 = fmaf(a, w.y, s1);
                s2 = fmaf(a, w.z, s2); s3 = fmaf(a, w.w, s3);
            }
            *(float4*)(Zf + (row0 + r) * 16 + jb) = make_float4(s0, s1, s2, s3);
        } else {
            // partial rec: 128 rows x 12 cols, K-slice [col0, col0+256)
            int r = tid >> 2, jb = (tid & 3) * 3;
            float s0 = 0.f, s1 = 0.f, s2 = 0.f;
            const float* fr = fsm + r * ERS;
            for (int k = 0; k < 256; k++) {
                float a = fr[k];
                const float* w = W3 + (size_t)(col0 + k) * 12 + jb;
                s0 = fmaf(a, w[0], s0); s1 = fmaf(a, w[1], s1); s2 = fmaf(a, w[2], s2);
            }
            float* ro = Rf + (row0 + r) * 12 + jb;
            atomicAdd(ro + 0, s0); atomicAdd(ro + 1, s1); atomicAdd(ro + 2, s2);
        }
    }
}

// ---------------- quantize (+ near-tie candidates + qsplit emit) ----------------
__global__ __launch_bounds__(256) void quantize_kernel(
    const float* __restrict__ z, const float* __restrict__ emb,
    float* __restrict__ out_q, float* __restrict__ out_idx,
    float* __restrict__ dist, __nv_bfloat16* __restrict__ qs,
    int* __restrict__ counts, double* __restrict__ qlat,
    int* __restrict__ ncand, int* __restrict__ cand)
{
    __shared__ float embn[KCB][ED];
    __shared__ float zt[16][ED + 1];
    __shared__ float rinv[16];
    __shared__ float n2[16];
    __shared__ float sd[KCB][17];
    __shared__ int   shist[KCB];
    __shared__ float sq;
    int tid = threadIdx.x;
    size_t row0 = (size_t)blockIdx.x * 16;
    shist[tid] = 0;
    if (tid == 0) sq = 0.f;
    {
        float e[ED], s = 0.f;
#pragma unroll
        for (int j = 0; j < ED; j++) { e[j] = emb[tid * ED + j]; s += e[j] * e[j]; }
        float inv = 1.f / fmaxf(sqrtf(s), 1e-12f);
#pragma unroll
        for (int j = 0; j < ED; j++) embn[tid][j] = e[j] * inv;
    }
    { int r = tid >> 4, j = tid & 15; zt[r][j] = z[(row0 + r) * ED + j]; }
    __syncthreads();
    if (tid < 16) {
        float s = 0.f;
#pragma unroll
        for (int j = 0; j < ED; j++) s += zt[tid][j] * zt[tid][j];
        n2[tid] = s;
        rinv[tid] = 1.f / fmaxf(sqrtf(s), 1e-12f);
    }
    __syncthreads();
    for (int r = 0; r < 16; r++) {
        float s = 0.f;
#pragma unroll
        for (int j = 0; j < ED; j++) s += zt[r][j] * embn[tid][j];
        sd[tid][r] = s * rinv[r];
    }
    __syncthreads();
    int w = tid >> 5, lane = tid & 31;
    for (int c = 0; c < 32; c++) {
        int k = w * 32 + c;
        if (lane < 16) dist[(size_t)k * NROWS + row0 + lane] = sd[k][lane];
    }
    for (int rr = 0; rr < 2; rr++) {
        int r = w * 2 + rr;
        float best = -2.f; int bi = 0;
        for (int kk = lane; kk < KCB; kk += 32) {
            float v = sd[kk][r];
            if (v > best) { best = v; bi = kk; }
        }
#pragma unroll
        for (int o = 16; o > 0; o >>= 1) {
            float ov = __shfl_down_sync(0xffffffffu, best, o);
            int   oi = __shfl_down_sync(0xffffffffu, bi, o);
            if (ov > best || (ov == best && oi < bi)) { best = ov; bi = oi; }
        }
        bi   = __shfl_sync(0xffffffffu, bi, 0);
        best = __shfl_sync(0xffffffffu, best, 0);
        float sec = -2.f;
        for (int kk = lane; kk < KCB; kk += 32)
            if (kk != bi) sec = fmaxf(sec, sd[kk][r]);
#pragma unroll
        for (int o = 16; o > 0; o >>= 1)
            sec = fmaxf(sec, __shfl_down_sync(0xffffffffu, sec, o));
        float dd = 0.f;
        if (lane < ED) {
            float qv = emb[bi * ED + lane];
            float d = qv - zt[r][lane];
            out_q[(row0 + r) * ED + lane] = qv;
            __nv_bfloat16 h = __float2bfloat16(qv);
            qs[(row0 + r) * 32 + lane]      = h;
            qs[(row0 + r) * 32 + 16 + lane] = __float2bfloat16(qv - __bfloat162float(h));
            dd = d * d;
        }
#pragma unroll
        for (int o = 16; o > 0; o >>= 1) dd += __shfl_down_sync(0xffffffffu, dd, o);
        if (lane == 0) {
            atomicAdd(&sq, dd);
            atomicAdd(&shist[bi], 1);
            out_idx[row0 + r] = (float)bi;
            if (best - sec < GAP_TAU || n2[r] < 1e-4f) {
                int s = atomicAdd(ncand, 1);
                cand[s] = (int)(row0 + r);
            }
        }
    }
    __syncthreads();
    if (shist[tid]) atomicAdd(&counts[tid], shist[tid]);
    if (tid == 0) atomicAdd(qlat, (double)sq);
}

// ---------------- batched exact fp32 re-check of near-tie rows ----------------
#define RF_SMEM ((RB * 272 + RB * 512 + RB * 256 + RB * 16 + RB + RB * 256) * 4 + RB * 12)
__global__ __launch_bounds__(256) void refine_kernel(
    const float* __restrict__ actions, const float* __restrict__ conditions,
    const float* __restrict__ ew1, const float* __restrict__ eb1,
    const float* __restrict__ ew2, const float* __restrict__ eb2,
    const float* __restrict__ ew3, const float* __restrict__ eb3,
    const float* __restrict__ emb,
    const float* __restrict__ zbf,
    float* __restrict__ out_q, float* __restrict__ out_idx,
    __nv_bfloat16* __restrict__ qs,
    int* __restrict__ counts, double* __restrict__ qlat,
    const int* __restrict__ ncand, const int* __restrict__ cand)
{
    extern __shared__ float sh[];
    float* xs   = sh;
    float* h1s  = xs + RB * 272;
    float* h2s  = h1s + RB * 512;
    float* zs   = h2s + RB * 256;
    float* zinv = zs + RB * 16;
    float* ds   = zinv + RB;
    int*   ri   = (int*)(ds + RB * 256);
    int*   vl   = ri + RB;
    int*   ni   = vl + RB;

    int tid = threadIdx.x;
    int n = *ncand;
    for (int bi = blockIdx.x; bi * RB < n; bi += gridDim.x) {
        if (tid < RB) {
            int idx = bi * RB + tid;
            vl[tid] = (idx < n);
            ri[tid] = cand[(idx < n) ? idx : (n - 1)];
        }
        __syncthreads();
        for (int e = tid; e < RB * 268; e += 256) {
            int r = e / 268, j = e % 268;
            size_t row = (size_t)ri[r];
            xs[r * 272 + j] = (j < ACT_D) ? actions[row * ACT_D + j]
                                          : conditions[row * COND_D + (j - ACT_D)];
        }
        __syncthreads();
#pragma unroll
        for (int cc = 0; cc < 2; cc++) {
            int c = tid + cc * 256;
            float a0[RB];
            float b = eb1[c];
#pragma unroll
            for (int r = 0; r < RB; r++) a0[r] = b;
            for (int k = 0; k < 268; k++) {
                float w = ew1[(size_t)k * H1D + c];
#pragma unroll
                for (int r = 0; r < RB; r++) a0[r] = fmaf(xs[r * 272 + k], w, a0[r]);
            }
#pragma unroll
            for (int r = 0; r < RB; r++)
                h1s[r * 512 + c] = (a0[r] > 0.f) ? a0[r] : expm1f(a0[r]);
        }
        __syncthreads();
        {
            int c = tid;
            float a0[RB];
            float b = eb2[c];
#pragma unroll
            for (int r = 0; r < RB; r++) a0[r] = b;
            for (int k = 0; k < 512; k++) {
                float w = ew2[(size_t)k * H2D + c];
#pragma unroll
                for (int r = 0; r < RB; r++) a0[r] = fmaf(h1s[r * 512 + k], w, a0[r]);
            }
#pragma unroll
            for (int r = 0; r < RB; r++)
                h2s[r * 256 + c] = (a0[r] > 0.f) ? a0[r] : expm1f(a0[r]);
        }
        __syncthreads();
        {
            int r = tid >> 4, c = tid & 15;
            float s = eb3[c];
            for (int k = 0; k < 256; k++)
                s = fmaf(h2s[r * 256 + k], ew3[(size_t)k * ED + c], s);
            zs[r * 16 + c] = s;
        }
        __syncthreads();
        if (tid < RB) {
            float s = 0.f;
#pragma unroll
            for (int j = 0; j < ED; j++) s += zs[tid * 16 + j] * zs[tid * 16 + j];
            zinv[tid] = 1.f / fmaxf(sqrtf(s), 1e-12f);
        }
        __syncthreads();
        {
            int c = tid;
            float e[ED], s = 0.f;
#pragma unroll
            for (int j = 0; j < ED; j++) { e[j] = emb[c * ED + j]; s += e[j] * e[j]; }
            float inv = 1.f / fmaxf(sqrtf(s), 1e-12f);
#pragma unroll
            for (int r = 0; r < RB; r++) {
                float dot = 0.f;
#pragma unroll
                for (int j = 0; j < ED; j++)
                    dot += (zs[r * 16 + j] * zinv[r]) * (e[j] * inv);
                ds[r * 256 + c] = dot;
            }
        }
        __syncthreads();
        {
            int w = tid >> 5, lane = tid & 31;
#pragma unroll
            for (int rr = 0; rr < 2; rr++) {
                int r = w * 2 + rr;
                float best = -2.f; int bidx = 0;
                for (int kk = lane; kk < KCB; kk += 32) {
                    float v = ds[r * 256 + kk];
                    if (v > best) { best = v; bidx = kk; }
                }
#pragma unroll
                for (int o = 16; o > 0; o >>= 1) {
                    float ov = __shfl_down_sync(0xffffffffu, best, o);
                    int   oi = __shfl_down_sync(0xffffffffu, bidx, o);
                    if (ov > best || (ov == best && oi < bidx)) { best = ov; bidx = oi; }
                }
                if (lane == 0) ni[r] = bidx;
            }
        }
        __syncthreads();
        if (tid < RB && vl[tid]) {
            size_t row = (size_t)ri[tid];
            int oldidx = (int)out_idx[row];
            int newidx = ni[tid];
            if (newidx != oldidx) {
                out_idx[row] = (float)newidx;
                atomicSub(counts + oldidx, 1);
                atomicAdd(counts + newidx, 1);
                float dq = 0.f;
#pragma unroll
                for (int j = 0; j < ED; j++) {
                    float zb = zbf[row * ED + j];
                    float qv = emb[newidx * ED + j];
                    float dn = qv - zb;
                    float dl = emb[oldidx * ED + j] - zb;
                    dq += dn * dn - dl * dl;
                    out_q[row * ED + j] = qv;
                    __nv_bfloat16 h = __float2bfloat16(qv);
                    qs[row * 32 + j]      = h;
                    qs[row * 32 + 16 + j] = __float2bfloat16(qv - __bfloat162float(h));
                }
                atomicAdd(qlat, (double)dq);
            }
        }
        __syncthreads();
    }
}

// ---------------- per-column order statistics + contra loss ----------------
__global__ __launch_bounds__(256) void select_kernel(
    const float* __restrict__ dist, double* __restrict__ contra)
{
    __shared__ unsigned ha[2048], hb[2048];
    __shared__ unsigned s_bin[2], s_rem[2];
    __shared__ float rf[256];
    int tid = threadIdx.x;
    const float* col = dist + (size_t)blockIdx.x * NROWS;
    const unsigned RA = NROWS / 2 - 1;
    const unsigned RBK = NROWS - 512;

    for (int i = tid; i < 2048; i += 256) ha[i] = 0;
    __syncthreads();
    for (int i = tid; i < NROWS; i += 256) atomicAdd(&ha[fkey(col[i]) >> 21], 1u);
    __syncthreads();
    if (tid == 0) {
        unsigned c = 0;
        for (unsigned b = 0; b < 2048; b++) {
            unsigned h = ha[b];
            if (c <= RA && c + h > RA) { s_bin[0] = b; s_rem[0] = RA - c; }
            if (c <= RBK && c + h > RBK) { s_bin[1] = b; s_rem[1] = RBK - c; }
            c += h;
        }
    }
    __syncthreads();
    unsigned p0a = s_bin[0], p0b = s_bin[1];
    unsigned rema = s_rem[0], remb = s_rem[1];
    __syncthreads();

    for (int i = tid; i < 2048; i += 256) { ha[i] = 0; hb[i] = 0; }
    __syncthreads();
    for (int i = tid; i < NROWS; i += 256) {
        unsigned u = fkey(col[i]);
        unsigned t = u >> 21, m = (u >> 10) & 2047u;
        if (t == p0a) atomicAdd(&ha[m], 1u);
        if (t == p0b) atomicAdd(&hb[m], 1u);
    }
    __syncthreads();
    if (tid == 0) { unsigned c = 0; for (unsigned b = 0; b < 2048; b++) { unsigned h = ha[b];
        if (c + h > rema) { s_bin[0] = b; s_rem[0] = rema - c; break; } c += h; } }
    if (tid == 1) { unsigned c = 0; for (unsigned b = 0; b < 2048; b++) { unsigned h = hb[b];
        if (c + h > remb) { s_bin[1] = b; s_rem[1] = remb - c; break; } c += h; } }
    __syncthreads();
    unsigned p1a = (p0a << 11) | s_bin[0], p1b = (p0b << 11) | s_bin[1];
    rema = s_rem[0]; remb = s_rem[1];
    __syncthreads();

    for (int i = tid; i < 1024; i += 256) { ha[i] = 0; hb[i] = 0; }
    __syncthreads();
    for (int i = tid; i < NROWS; i += 256) {
        unsigned u = fkey(col[i]);
        if ((u >> 10) == p1a) atomicAdd(&ha[u & 1023u], 1u);
        if ((u >> 10) == p1b) atomicAdd(&hb[u & 1023u], 1u);
    }
    __syncthreads();
    if (tid == 0) { unsigned c = 0; for (unsigned b = 0; b < 1024; b++) { unsigned h = ha[b];
        if (c + h > rema) { s_bin[0] = b; break; } c += h; } }
    if (tid == 1) { unsigned c = 0; for (unsigned b = 0; b < 1024; b++) { unsigned h = hb[b];
        if (c + h > remb) { s_bin[1] = b; break; } c += h; } }
    __syncthreads();
    unsigned km = (p1a << 10) | s_bin[0];
    unsigned kt = (p1b << 10) | s_bin[1];

    float Tmed = finv(km);
    const float INV_TAU = 1.0f / 0.07f;
    int cgt = 0, clt = 0;
    float sgt = 0.f, sexp = 0.f;
    for (int i = tid; i < NROWS; i += 256) {
        float x = col[i];
        unsigned u = fkey(x);
        if (u > kt) { cgt++; sgt += x; }
        if (u < km) { clt++; sexp += expf((x - Tmed) * INV_TAU); }
    }
    float CGT, SGT, CLT, SEXP;
    rf[tid] = (float)cgt; __syncthreads();
    for (int s = 128; s; s >>= 1) { if (tid < s) rf[tid] += rf[tid + s]; __syncthreads(); }
    CGT = rf[0]; __syncthreads();
    rf[tid] = sgt; __syncthreads();
    for (int s = 128; s; s >>= 1) { if (tid < s) rf[tid] += rf[tid + s]; __syncthreads(); }
    SGT = rf[0]; __syncthreads();
    rf[tid] = (float)clt; __syncthreads();
    for (int s = 128; s; s >>= 1) { if (tid < s) rf[tid] += rf[tid + s]; __syncthreads(); }
    CLT = rf[0]; __syncthreads();
    rf[tid] = sexp; __syncthreads();
    for (int s = 128; s; s >>= 1) { if (tid < s) rf[tid] += rf[tid + s]; __syncthreads(); }
    SEXP = rf[0];

    if (tid == 0) {
        float Ttop = finv(kt);
        float dis_pos = (SGT + (512.0f - CGT) * Ttop) * (1.0f / 512.0f);
        float Sx = SEXP + ((float)(NROWS / 2) - CLT);
        float a = dis_pos * INV_TAU, b = Tmed * INV_TAU;
        float m = fmaxf(a, b);
        float lse = m + logf(expf(a - m) + Sx * expf(b - m));
        atomicAdd(contra, (double)(lse - a));
    }
}

// ---------------- finalize scalars ----------------
__global__ void finalize_kernel(const int* __restrict__ counts,
                                const double* __restrict__ qlat,
                                const double* __restrict__ contra,
                                const double* __restrict__ recon,
                                float* __restrict__ out_sc)
{
    __shared__ float rr[256];
    int t = threadIdx.x;
    float p = (float)counts[t] / (float)NROWS;
    rr[t] = p * logf(p + 1e-10f);
    __syncthreads();
    for (int s = 128; s; s >>= 1) { if (t < s) rr[t] += rr[t + s]; __syncthreads(); }
    if (t == 0) {
        float q = (float)(*qlat / ((double)NROWS * ED));
        out_sc[0] = q;
        out_sc[1] = 0.25f * q;
        out_sc[2] = (float)(*contra / (double)KCB);
        out_sc[3] = expf(-rr[0]);
        out_sc[4] = (float)(*recon / ((double)NROWS * ACT_D));
    }
}

// ---------------- launch ----------------
extern "C" void kernel_launch(void* const* d_in, const int* in_sizes, int n_in,
                              void* d_out, int out_size)
{
    const float* actions    = (const float*)d_in[0];
    const float* conditions = (const float*)d_in[1];
    const float* enc_w1 = (const float*)d_in[2];  const float* enc_b1 = (const float*)d_in[3];
    const float* enc_w2 = (const float*)d_in[4];  const float* enc_b2 = (const float*)d_in[5];
    const float* enc_w3 = (const float*)d_in[6];  const float* enc_b3 = (const float*)d_in[7];
    const float* dec_w1 = (const float*)d_in[8];  const float* dec_b1 = (const float*)d_in[9];
    const float* dec_w2 = (const float*)d_in[10]; const float* dec_b2 = (const float*)d_in[11];
    const float* dec_w3 = (const float*)d_in[12]; const float* dec_b3 = (const float*)d_in[13];
    const float* embedding = (const float*)d_in[14];

    float* out = (float*)d_out;
    float* out_rec = out;
    float* out_q   = out + (size_t)NROWS * ACT_D;
    float* out_idx = out_q + (size_t)NROWS * ED;
    float* out_sc  = out_idx + NROWS;

    __nv_bfloat16 *A1, *Ah1, *Aq, *Ad1, *B1, *B2, *B3, *B4;
    float *z, *dist;
    double *qlat, *contra, *recon; int *counts, *ncand, *cand;
    cudaGetSymbolAddress((void**)&A1,  g_A1);
    cudaGetSymbolAddress((void**)&Ah1, g_Ah1);
    cudaGetSymbolAddress((void**)&Aq,  g_Aq);
    cudaGetSymbolAddress((void**)&Ad1, g_Ad1);
    cudaGetSymbolAddress((void**)&B1,  g_B1);
    cudaGetSymbolAddress((void**)&B2,  g_B2);
    cudaGetSymbolAddress((void**)&B3,  g_B3);
    cudaGetSymbolAddress((void**)&B4,  g_B4);
    cudaGetSymbolAddress((void**)&z,   g_z);
    cudaGetSymbolAddress((void**)&dist,g_dist);
    cudaGetSymbolAddress((void**)&qlat,  g_qlat);
    cudaGetSymbolAddress((void**)&contra,g_contra);
    cudaGetSymbolAddress((void**)&recon, g_recon);
    cudaGetSymbolAddress((void**)&counts,g_counts);
    cudaGetSymbolAddress((void**)&ncand, g_ncand);
    cudaGetSymbolAddress((void**)&cand,  g_cand);

    cudaFuncSetAttribute((const void*)tgemm<KP1, 1, false>, cudaFuncAttributeMaxDynamicSharedMemorySize, TG_SMEM);
    cudaFuncSetAttribute((const void*)tgemm<KP2, 2, false>, cudaFuncAttributeMaxDynamicSharedMemorySize, TG_SMEM);
    cudaFuncSetAttribute((const void*)tgemm<KP1, 1, true>,  cudaFuncAttributeMaxDynamicSharedMemorySize, TG_SMEM);
    cudaFuncSetAttribute((const void*)tgemm<KP4, 3, false>, cudaFuncAttributeMaxDynamicSharedMemorySize, TG_SMEM);
    cudaFuncSetAttribute((const void*)refine_kernel, cudaFuncAttributeMaxDynamicSharedMemorySize, RF_SMEM);

    init_kernel<<<1, 256>>>(counts, qlat, contra, recon, ncand);                        // 1
    conv_w_kernel<<<((size_t)H1D * KA1 + 255) / 256, 256>>>(enc_w1, 12, 268, H1D, B1, KP1, KA1); // 2
    conv_cat_kernel<<<((size_t)NROWS * (KP1 / 2) + 255) / 256, 256>>>(
        actions, ACT_D, conditions, COND_D, A1, KP1, KA1);                              // 3
    // enc1: 268 -> 512 ([hi|lo] out)
    tgemm<KP1, 1, false><<<dim3(2, NROWS / 128), 512, TG_SMEM>>>(
        A1, B1, nullptr, enc_b1, nullptr, nullptr, nullptr, Ah1, nullptr, KP2);         // 4
    conv_w_kernel<<<((size_t)H2D * KA2 + 255) / 256, 256>>>(enc_w2, 16, 512, H2D, B2, KP2, KA2); // 5
    // enc2: 512 -> 256, fused enc3 epilogue -> z
    tgemm<KP2, 2, false><<<dim3(1, NROWS / 128), 512, TG_SMEM>>>(
        Ah1, B2, nullptr, enc_b2, enc_w3, enc_b3, z, nullptr, nullptr, 0);              // 6

    quantize_kernel<<<NROWS / 16, 256>>>(z, embedding, out_q, out_idx, dist, Aq,
                                         counts, qlat, ncand, cand);
    refine_kernel<<<2048, 256, RF_SMEM>>>(actions, conditions,
                                 enc_w1, enc_b1, enc_w2, enc_b2, enc_w3, enc_b3,
                                 embedding, z, out_q, out_idx, Aq, counts, qlat, ncand, cand);

    conv_w_kernel<<<((size_t)H2D * KA1 + 255) / 256, 256>>>(dec_w1, 16, 272, H2D, B3, KP1, KA1);
    conv_w_kernel<<<((size_t)H1D * KA4 + 255) / 256, 256>>>(dec_w2, 16, 256, H1D, B4, KP4, KA4);
    rec_init_kernel<<<((size_t)NROWS * ACT_D + 255) / 256, 256>>>(dec_b3, out_rec);
    select_kernel<<<KCB, 256>>>(dist, contra);

    // dec1: 272 -> 256 ([hi|lo] out) — A cols [0,16) from qsplit, rest reuses A1
    tgemm<KP1, 1, true><<<dim3(1, NROWS / 128), 512, TG_SMEM>>>(
        A1, B3, Aq, dec_b1, nullptr, nullptr, nullptr, Ad1, nullptr, KP4);
    // dec2: 256 -> 512, fused dec3 partial epilogue -> out_rec (atomic)
    tgemm<KP4, 3, false><<<dim3(2, NROWS / 128), 512, TG_SMEM>>>(
        Ad1, B4, nullptr, dec_b2, dec_w3, nullptr, nullptr, nullptr, out_rec, 0);
    // reconstruction loss from completed out_rec
    recon_kernel<<<1024, 256>>>(out_rec, actions, recon);

    finalize_kernel<<<1, 256>>>(counts, qlat, contra, recon, out_sc);
}

// round 14
// speedup vs baseline: 1.2269x; 1.0323x over previous
#include <cuda_runtime.h>
#include <cuda_bf16.h>
#include <math.h>
#include <stdint.h>

#define NROWS 131072
#define ACT_D 12
#define COND_D 256
#define KCB 256
#define ED 16
#define H1D 512
#define H2D 256

// Unified K-layout: small block at [0,16), conditions at [16,272).
#define KP1 288
#define KA1 576      // enc1 / dec1 inputs
#define KP2 512
#define KA2 1024     // enc2 input (K=512)
#define KP4 256
#define KA4 512      // dec2 input (K=256)

#define GAP_TAU 2e-3f
#define RB 16        // refine batch rows per block

// ---------------- scratch (static device globals; no allocs) ----------------
__device__ __nv_bfloat16 g_A1 [(size_t)NROWS * KA1];
__device__ __nv_bfloat16 g_Ah1[(size_t)NROWS * KA2];
__device__ __nv_bfloat16 g_Aq [(size_t)NROWS * 32];   // quantized [hi(16)|lo(16)]
__device__ __nv_bfloat16 g_Ad1[(size_t)NROWS * KA4];
__device__ __nv_bfloat16 g_B1 [(size_t)H1D * KA1];
__device__ __nv_bfloat16 g_B2 [(size_t)H2D * KA2];
__device__ __nv_bfloat16 g_B3 [(size_t)H2D * KA1];
__device__ __nv_bfloat16 g_B4 [(size_t)H1D * KA4];
__device__ float g_z   [(size_t)NROWS * ED];
__device__ float g_dist[(size_t)KCB * NROWS];   // transposed: [k][n]
__device__ double g_qlat, g_contra, g_recon;
__device__ int    g_counts[KCB];
__device__ int    g_ncand;
__device__ int    g_cand[NROWS];

// ---------------- helpers ----------------
__device__ __forceinline__ uint32_t smem_u32(const void* p) {
    uint32_t a;
    asm("{ .reg .u64 t; cvta.to.shared.u64 t, %1; cvt.u32.u64 %0, t; }"
        : "=r"(a) : "l"(p));
    return a;
}
__device__ __forceinline__ void cp_async16(uint32_t s, const void* g) {
    asm volatile("cp.async.cg.shared.global [%0], [%1], 16;" :: "r"(s), "l"(g) : "memory");
}
__device__ __forceinline__ void cp_commit() {
    asm volatile("cp.async.commit_group;" ::: "memory");
}
template <int N>
__device__ __forceinline__ void cp_wait() {
    asm volatile("cp.async.wait_group %0;" :: "n"(N) : "memory");
}
__device__ __forceinline__ void ldmx4(uint32_t& r0, uint32_t& r1, uint32_t& r2, uint32_t& r3,
                                      uint32_t addr) {
    asm volatile("ldmatrix.sync.aligned.m8n8.x4.shared.b16 {%0,%1,%2,%3}, [%4];"
                 : "=r"(r0), "=r"(r1), "=r"(r2), "=r"(r3) : "r"(addr));
}
__device__ __forceinline__ void mma_bf16(float* c, const uint32_t* a, const uint32_t* b) {
    asm volatile("mma.sync.aligned.m16n8k16.row.col.f32.bf16.bf16.f32 "
                 "{%0,%1,%2,%3}, {%4,%5,%6,%7}, {%8,%9}, {%0,%1,%2,%3};"
                 : "+f"(c[0]), "+f"(c[1]), "+f"(c[2]), "+f"(c[3])
                 : "r"(a[0]), "r"(a[1]), "r"(a[2]), "r"(a[3]), "r"(b[0]), "r"(b[1]));
}
__device__ __forceinline__ unsigned fkey(float x) {
    unsigned u = __float_as_uint(x);
    return (u & 0x80000000u) ? ~u : (u | 0x80000000u);
}
__device__ __forceinline__ float finv(unsigned k) {
    return (k & 0x80000000u) ? __uint_as_float(k & 0x7fffffffu)
                             : __uint_as_float(~k);
}

// ---------------- init ----------------
__global__ void init_kernel(int* counts, double* a, double* b, double* c, int* ncand) {
    int t = threadIdx.x;
    counts[t] = 0;
    if (t == 0) { *a = 0.0; *b = 0.0; *c = 0.0; *ncand = 0; }
}
__global__ void rec_init_kernel(const float* __restrict__ b3, float* __restrict__ rec) {
    size_t i = (size_t)blockIdx.x * 256 + threadIdx.x;
    if (i < (size_t)NROWS * ACT_D) rec[i] = b3[i % ACT_D];
}
__global__ void recon_kernel(const float* __restrict__ rec, const float* __restrict__ act,
                             double* __restrict__ out) {
    __shared__ float rf[256];
    int tid = threadIdx.x;
    float s = 0.f;
    for (size_t i = (size_t)blockIdx.x * 256 + tid; i < (size_t)NROWS * ACT_D;
         i += (size_t)gridDim.x * 256) {
        float d = rec[i] - act[i];
        s += d * d;
    }
    rf[tid] = s; __syncthreads();
    for (int st = 128; st; st >>= 1) { if (tid < st) rf[tid] += rf[tid + st]; __syncthreads(); }
    if (tid == 0) atomicAdd(out, (double)rf[0]);
}

// ---------------- split conversions (unified layout, 2-segment [hi|lo]) ----------
__global__ void conv_cat_kernel(const float* __restrict__ a, int ad,
                                const float* __restrict__ b, int bd,
                                __nv_bfloat16* __restrict__ o, int KP, int KA)
{
    int pairs = KP >> 1;
    size_t t = (size_t)blockIdx.x * 256 + threadIdx.x;
    size_t row = t / pairs;
    if (row >= NROWS) return;
    int p = (int)(t % pairs);
    int j = p * 2;
    float v0 = 0.f, v1 = 0.f;
    if (j < 16) {
        if (j < ad)     v0 = a[row * ad + j];
        if (j + 1 < ad) v1 = a[row * ad + j + 1];
    } else {
        int c = j - 16;
        if (c < bd)     v0 = b[row * bd + c];
        if (c + 1 < bd) v1 = b[row * bd + c + 1];
    }
    __nv_bfloat162 hh, ll;
    hh.x = __float2bfloat16(v0); hh.y = __float2bfloat16(v1);
    ll.x = __float2bfloat16(v0 - __bfloat162float(hh.x));
    ll.y = __float2bfloat16(v1 - __bfloat162float(hh.y));
    __nv_bfloat16* base = o + row * (size_t)KA;
    ((__nv_bfloat162*)(base))[p]      = hh;
    ((__nv_bfloat162*)(base + KP))[p] = ll;
}
__global__ void conv_w_kernel(const float* __restrict__ W, int ad, int K, int Nn,
                              __nv_bfloat16* __restrict__ o, int KP, int KA)
{
    size_t t = (size_t)blockIdx.x * 256 + threadIdx.x;
    if (t >= (size_t)Nn * KA) return;
    int n  = (int)(t / KA);
    int kt = (int)(t % KA);
    int s  = kt < KP ? 0 : 1;
    int c  = kt - s * KP;
    int k  = (c < 16) ? ((c < ad) ? c : -1) : (c - (16 - ad));
    float v = (k >= 0 && k < K) ? W[(size_t)k * Nn + n] : 0.f;
    __nv_bfloat16 h = __float2bfloat16(v);
    __nv_bfloat16 r = s ? __float2bfloat16(v - __bfloat162float(h)) : h;
    o[(size_t)n * KA + kt] = r;
}

// ---------------- tensor-core GEMM: 128x256 CTA tile, 16 warps, 3-stage pipe ----
#define SROW 80
#define S_AHI 0
#define S_ALO 10240
#define S_BHI 20480
#define S_BLO 40960
#define STAGE 61440
#define NSTG 3
#define TG_SMEM (NSTG * STAGE)
#define ERS 258   // fp32 epilogue smem row stride

template <int KP, int OUTM, bool QSRC>
__global__ __launch_bounds__(512, 1) void tgemm(
    const __nv_bfloat16* __restrict__ Ap,
    const __nv_bfloat16* __restrict__ Bp,
    const __nv_bfloat16* __restrict__ Qs,
    const float* __restrict__ bias,
    const float* __restrict__ W3,
    const float* __restrict__ B3o,
    float* __restrict__ Zf,
    __nv_bfloat16* __restrict__ Cb,
    float* __restrict__ Rf,
    int KPn)
{
    extern __shared__ __align__(16) uint8_t smem[];
    const uint32_t sm = smem_u32(smem);
    const int KA = 2 * KP;

    const int tid = threadIdx.x;
    const int wid = tid >> 5, lane = tid & 31;
    const int wr = wid >> 3, wc = wid & 7;          // warps 2 x 8
    const size_t row0 = (size_t)blockIdx.y * 128;
    const int    col0 = blockIdx.x * 256;

    const int NCH = KP / 32;

    float acc[4][4][4];
#pragma unroll
    for (int i = 0; i < 4; i++)
#pragma unroll
        for (int j = 0; j < 4; j++)
#pragma unroll
            for (int e = 0; e < 4; e++) acc[i][j][e] = 0.f;

    auto load_chunk = [&](int c, int buf) {
        const int kc = c * 32;
        const uint32_t base = sm + buf * STAGE;
        {
            int row = tid >> 2, seg = tid & 3;
            size_t rg = row0 + row;
            int c0 = kc + seg * 8;
            uint32_t so = row * SROW + seg * 16;
            const __nv_bfloat16* hs;
            const __nv_bfloat16* ls;
            if (QSRC && c0 < 16) {
                hs = Qs + rg * 32 + c0;
                ls = Qs + rg * 32 + 16 + c0;
            } else {
                hs = Ap + rg * (size_t)KA + c0;
                ls = hs + KP;
            }
            cp_async16(base + S_AHI + so, hs);
            cp_async16(base + S_ALO + so, ls);
        }
#pragma unroll
        for (int l = 0; l < 2; l++) {
            int L = tid + l * 512;
            int row = L >> 2, seg = L & 3;
            const __nv_bfloat16* gb = Bp + (size_t)(col0 + row) * KA + kc + seg * 8;
            uint32_t so = row * SROW + seg * 16;
            cp_async16(base + S_BHI + so, gb);
            cp_async16(base + S_BLO + so, gb + KP);
        }
        cp_commit();
    };

#pragma unroll
    for (int s = 0; s < NSTG - 1; s++) load_chunk(s, s);

    for (int c = 0; c < NCH; c++) {
        cp_wait<NSTG - 2>();
        __syncthreads();
        int nc = c + NSTG - 1;
        if (nc < NCH) load_chunk(nc, nc % NSTG);
        else          cp_commit();

        const uint32_t st = sm + (c % NSTG) * STAGE;
        const int g = lane >> 3, lr = lane & 7;

#pragma unroll
        for (int ks = 0; ks < 2; ks++) {
            const uint32_t acolo = (ks * 16 + (g >> 1) * 8) * 2;
            const uint32_t bcolo = (ks * 16 + (g & 1) * 8) * 2;
            uint32_t afh[4][4];
#pragma unroll
            for (int mt = 0; mt < 4; mt++) {
                int r = wr * 64 + mt * 16 + (g & 1) * 8 + lr;
                ldmx4(afh[mt][0], afh[mt][1], afh[mt][2], afh[mt][3],
                      st + S_AHI + r * SROW + acolo);
            }
            uint32_t bfh[4][2];
#pragma unroll
            for (int bt = 0; bt < 2; bt++) {
                int r = wc * 32 + bt * 16 + (g >> 1) * 8 + lr;
                uint32_t r0, r1, r2, r3;
                ldmx4(r0, r1, r2, r3, st + S_BHI + r * SROW + bcolo);
                bfh[bt * 2][0] = r0;     bfh[bt * 2][1] = r1;
                bfh[bt * 2 + 1][0] = r2; bfh[bt * 2 + 1][1] = r3;
            }
#pragma unroll
            for (int mt = 0; mt < 4; mt++)
#pragma unroll
                for (int nt = 0; nt < 4; nt++)
                    mma_bf16(acc[mt][nt], afh[mt], bfh[nt]);
#pragma unroll
            for (int mt = 0; mt < 4; mt++) {
                int r = wr * 64 + mt * 16 + (g & 1) * 8 + lr;
                uint32_t al[4];
                ldmx4(al[0], al[1], al[2], al[3], st + S_ALO + r * SROW + acolo);
#pragma unroll
                for (int nt = 0; nt < 4; nt++)
                    mma_bf16(acc[mt][nt], al, bfh[nt]);
            }
#pragma unroll
            for (int bt = 0; bt < 2; bt++) {
                int r = wc * 32 + bt * 16 + (g >> 1) * 8 + lr;
                uint32_t r0, r1, r2, r3;
                ldmx4(r0, r1, r2, r3, st + S_BLO + r * SROW + bcolo);
                uint32_t bl0[2] = {r0, r1}, bl1[2] = {r2, r3};
#pragma unroll
                for (int mt = 0; mt < 4; mt++) {
                    mma_bf16(acc[mt][bt * 2],     afh[mt], bl0);
                    mma_bf16(acc[mt][bt * 2 + 1], afh[mt], bl1);
                }
            }
        }
    }

    if (OUTM == 1) {
#pragma unroll
        for (int mt = 0; mt < 4; mt++) {
            size_t ra = row0 + wr * 64 + mt * 16 + (lane >> 2);
            size_t rb = ra + 8;
#pragma unroll
            for (int nt = 0; nt < 4; nt++) {
                int colg = col0 + wc * 32 + nt * 8 + (lane & 3) * 2;
                float b0 = bias[colg], b1 = bias[colg + 1];
                float v00 = acc[mt][nt][0] + b0, v01 = acc[mt][nt][1] + b1;
                float v10 = acc[mt][nt][2] + b0, v11 = acc[mt][nt][3] + b1;
                v00 = (v00 > 0.f) ? v00 : expm1f(v00);
                v01 = (v01 > 0.f) ? v01 : expm1f(v01);
                v10 = (v10 > 0.f) ? v10 : expm1f(v10);
                v11 = (v11 > 0.f) ? v11 : expm1f(v11);
                const size_t KTn = 2 * (size_t)KPn;
                __nv_bfloat162 hh, ll;
                __nv_bfloat16* pa = Cb + ra * KTn;
                hh.x = __float2bfloat16(v00); hh.y = __float2bfloat16(v01);
                ll.x = __float2bfloat16(v00 - __bfloat162float(hh.x));
                ll.y = __float2bfloat16(v01 - __bfloat162float(hh.y));
                *(__nv_bfloat162*)(pa + colg)       = hh;
                *(__nv_bfloat162*)(pa + KPn + colg) = ll;
                __nv_bfloat16* pb = Cb + rb * KTn;
                hh.x = __float2bfloat16(v10); hh.y = __float2bfloat16(v11);
                ll.x = __float2bfloat16(v10 - __bfloat162float(hh.x));
                ll.y = __float2bfloat16(v11 - __bfloat162float(hh.y));
                *(__nv_bfloat162*)(pb + colg)       = hh;
                *(__nv_bfloat162*)(pb + KPn + colg) = ll;
            }
        }
    } else {
        __syncthreads();
        float* fsm = (float*)smem;
#pragma unroll
        for (int mt = 0; mt < 4; mt++) {
            int ra = wr * 64 + mt * 16 + (lane >> 2);
            int rb = ra + 8;
#pragma unroll
            for (int nt = 0; nt < 4; nt++) {
                int colL = wc * 32 + nt * 8 + (lane & 3) * 2;
                float b0 = bias[col0 + colL], b1 = bias[col0 + colL + 1];
                float v00 = acc[mt][nt][0] + b0, v01 = acc[mt][nt][1] + b1;
                float v10 = acc[mt][nt][2] + b0, v11 = acc[mt][nt][3] + b1;
                v00 = (v00 > 0.f) ? v00 : expm1f(v00);
                v01 = (v01 > 0.f) ? v01 : expm1f(v01);
                v10 = (v10 > 0.f) ? v10 : expm1f(v10);
                v11 = (v11 > 0.f) ? v11 : expm1f(v11);
                *(float2*)(fsm + ra * ERS + colL) = make_float2(v00, v01);
                *(float2*)(fsm + rb * ERS + colL) = make_float2(v10, v11);
            }
        }
        __syncthreads();
        if (OUTM == 2) {
            int r = tid >> 2, jb = (tid & 3) * 4;
            float s0 = B3o[jb], s1 = B3o[jb + 1], s2 = B3o[jb + 2], s3 = B3o[jb + 3];
            const float* fr = fsm + r * ERS;
            for (int k = 0; k < 256; k++) {
                float a = fr[k];
                const float4 w = *(const float4*)(W3 + k * 16 + jb);
                s0 = fmaf(a, w.x, s0); s1 = fmaf(a, w.y, s1);
                s2 = fmaf(a, w.z, s2); s3 = fmaf(a, w.w, s3);
            }
            *(float4*)(Zf + (row0 + r) * 16 + jb) = make_float4(s0, s1, s2, s3);
        } else {
            int r = tid >> 2, jb = (tid & 3) * 3;
            float s0 = 0.f, s1 = 0.f, s2 = 0.f;
            const float* fr = fsm + r * ERS;
            for (int k = 0; k < 256; k++) {
                float a = fr[k];
                const float* w = W3 + (size_t)(col0 + k) * 12 + jb;
                s0 = fmaf(a, w[0], s0); s1 = fmaf(a, w[1], s1); s2 = fmaf(a, w[2], s2);
            }
            float* ro = Rf + (row0 + r) * 12 + jb;
            atomicAdd(ro + 0, s0); atomicAdd(ro + 1, s1); atomicAdd(ro + 2, s2);
        }
    }
}

// ---------------- quantize (+ near-tie candidates + qsplit emit) ----------------
__global__ __launch_bounds__(256) void quantize_kernel(
    const float* __restrict__ z, const float* __restrict__ emb,
    float* __restrict__ out_q, float* __restrict__ out_idx,
    float* __restrict__ dist, __nv_bfloat16* __restrict__ qs,
    int* __restrict__ counts, double* __restrict__ qlat,
    int* __restrict__ ncand, int* __restrict__ cand)
{
    __shared__ float embn[KCB][ED];
    __shared__ float zt[16][ED + 1];
    __shared__ float rinv[16];
    __shared__ float n2[16];
    __shared__ float sd[KCB][17];
    __shared__ int   shist[KCB];
    __shared__ float sq;
    int tid = threadIdx.x;
    size_t row0 = (size_t)blockIdx.x * 16;
    shist[tid] = 0;
    if (tid == 0) sq = 0.f;
    {
        float e[ED], s = 0.f;
#pragma unroll
        for (int j = 0; j < ED; j++) { e[j] = emb[tid * ED + j]; s += e[j] * e[j]; }
        float inv = 1.f / fmaxf(sqrtf(s), 1e-12f);
#pragma unroll
        for (int j = 0; j < ED; j++) embn[tid][j] = e[j] * inv;
    }
    { int r = tid >> 4, j = tid & 15; zt[r][j] = z[(row0 + r) * ED + j]; }
    __syncthreads();
    if (tid < 16) {
        float s = 0.f;
#pragma unroll
        for (int j = 0; j < ED; j++) s += zt[tid][j] * zt[tid][j];
        n2[tid] = s;
        rinv[tid] = 1.f / fmaxf(sqrtf(s), 1e-12f);
    }
    __syncthreads();
    for (int r = 0; r < 16; r++) {
        float s = 0.f;
#pragma unroll
        for (int j = 0; j < ED; j++) s += zt[r][j] * embn[tid][j];
        sd[tid][r] = s * rinv[r];
    }
    __syncthreads();
    int w = tid >> 5, lane = tid & 31;
    for (int c = 0; c < 32; c++) {
        int k = w * 32 + c;
        if (lane < 16) dist[(size_t)k * NROWS + row0 + lane] = sd[k][lane];
    }
    for (int rr = 0; rr < 2; rr++) {
        int r = w * 2 + rr;
        float best = -2.f; int bi = 0;
        for (int kk = lane; kk < KCB; kk += 32) {
            float v = sd[kk][r];
            if (v > best) { best = v; bi = kk; }
        }
#pragma unroll
        for (int o = 16; o > 0; o >>= 1) {
            float ov = __shfl_down_sync(0xffffffffu, best, o);
            int   oi = __shfl_down_sync(0xffffffffu, bi, o);
            if (ov > best || (ov == best && oi < bi)) { best = ov; bi = oi; }
        }
        bi   = __shfl_sync(0xffffffffu, bi, 0);
        best = __shfl_sync(0xffffffffu, best, 0);
        float sec = -2.f;
        for (int kk = lane; kk < KCB; kk += 32)
            if (kk != bi) sec = fmaxf(sec, sd[kk][r]);
#pragma unroll
        for (int o = 16; o > 0; o >>= 1)
            sec = fmaxf(sec, __shfl_down_sync(0xffffffffu, sec, o));
        float dd = 0.f;
        if (lane < ED) {
            float qv = emb[bi * ED + lane];
            float d = qv - zt[r][lane];
            out_q[(row0 + r) * ED + lane] = qv;
            __nv_bfloat16 h = __float2bfloat16(qv);
            qs[(row0 + r) * 32 + lane]      = h;
            qs[(row0 + r) * 32 + 16 + lane] = __float2bfloat16(qv - __bfloat162float(h));
            dd = d * d;
        }
#pragma unroll
        for (int o = 16; o > 0; o >>= 1) dd += __shfl_down_sync(0xffffffffu, dd, o);
        if (lane == 0) {
            atomicAdd(&sq, dd);
            atomicAdd(&shist[bi], 1);
            out_idx[row0 + r] = (float)bi;
            if (best - sec < GAP_TAU || n2[r] < 1e-4f) {
                int s = atomicAdd(ncand, 1);
                cand[s] = (int)(row0 + r);
            }
        }
    }
    __syncthreads();
    if (shist[tid]) atomicAdd(&counts[tid], shist[tid]);
    if (tid == 0) atomicAdd(qlat, (double)sq);
}

// ---------------- batched exact fp32 re-check of near-tie rows ----------------
#define RF_SMEM ((RB * 272 + RB * 512 + RB * 256 + RB * 16 + RB + RB * 256) * 4 + RB * 12)
__global__ __launch_bounds__(256) void refine_kernel(
    const float* __restrict__ actions, const float* __restrict__ conditions,
    const float* __restrict__ ew1, const float* __restrict__ eb1,
    const float* __restrict__ ew2, const float* __restrict__ eb2,
    const float* __restrict__ ew3, const float* __restrict__ eb3,
    const float* __restrict__ emb,
    const float* __restrict__ zbf,
    float* __restrict__ out_q, float* __restrict__ out_idx,
    __nv_bfloat16* __restrict__ qs,
    int* __restrict__ counts, double* __restrict__ qlat,
    const int* __restrict__ ncand, const int* __restrict__ cand)
{
    extern __shared__ float sh[];
    float* xs   = sh;
    float* h1s  = xs + RB * 272;
    float* h2s  = h1s + RB * 512;
    float* zs   = h2s + RB * 256;
    float* zinv = zs + RB * 16;
    float* ds   = zinv + RB;
    int*   ri   = (int*)(ds + RB * 256);
    int*   vl   = ri + RB;
    int*   ni   = vl + RB;

    int tid = threadIdx.x;
    int n = *ncand;
    for (int bi = blockIdx.x; bi * RB < n; bi += gridDim.x) {
        if (tid < RB) {
            int idx = bi * RB + tid;
            vl[tid] = (idx < n);
            ri[tid] = cand[(idx < n) ? idx : (n - 1)];
        }
        __syncthreads();
        for (int e = tid; e < RB * 268; e += 256) {
            int r = e / 268, j = e % 268;
            size_t row = (size_t)ri[r];
            xs[r * 272 + j] = (j < ACT_D) ? actions[row * ACT_D + j]
                                          : conditions[row * COND_D + (j - ACT_D)];
        }
        __syncthreads();
#pragma unroll
        for (int cc = 0; cc < 2; cc++) {
            int c = tid + cc * 256;
            float a0[RB];
            float b = eb1[c];
#pragma unroll
            for (int r = 0; r < RB; r++) a0[r] = b;
            for (int k = 0; k < 268; k++) {
                float w = ew1[(size_t)k * H1D + c];
#pragma unroll
                for (int r = 0; r < RB; r++) a0[r] = fmaf(xs[r * 272 + k], w, a0[r]);
            }
#pragma unroll
            for (int r = 0; r < RB; r++)
                h1s[r * 512 + c] = (a0[r] > 0.f) ? a0[r] : expm1f(a0[r]);
        }
        __syncthreads();
        {
            int c = tid;
            float a0[RB];
            float b = eb2[c];
#pragma unroll
            for (int r = 0; r < RB; r++) a0[r] = b;
            for (int k = 0; k < 512; k++) {
                float w = ew2[(size_t)k * H2D + c];
#pragma unroll
                for (int r = 0; r < RB; r++) a0[r] = fmaf(h1s[r * 512 + k], w, a0[r]);
            }
#pragma unroll
            for (int r = 0; r < RB; r++)
                h2s[r * 256 + c] = (a0[r] > 0.f) ? a0[r] : expm1f(a0[r]);
        }
        __syncthreads();
        {
            int r = tid >> 4, c = tid & 15;
            float s = eb3[c];
            for (int k = 0; k < 256; k++)
                s = fmaf(h2s[r * 256 + k], ew3[(size_t)k * ED + c], s);
            zs[r * 16 + c] = s;
        }
        __syncthreads();
        if (tid < RB) {
            float s = 0.f;
#pragma unroll
            for (int j = 0; j < ED; j++) s += zs[tid * 16 + j] * zs[tid * 16 + j];
            zinv[tid] = 1.f / fmaxf(sqrtf(s), 1e-12f);
        }
        __syncthreads();
        {
            int c = tid;
            float e[ED], s = 0.f;
#pragma unroll
            for (int j = 0; j < ED; j++) { e[j] = emb[c * ED + j]; s += e[j] * e[j]; }
            float inv = 1.f / fmaxf(sqrtf(s), 1e-12f);
#pragma unroll
            for (int r = 0; r < RB; r++) {
                float dot = 0.f;
#pragma unroll
                for (int j = 0; j < ED; j++)
                    dot += (zs[r * 16 + j] * zinv[r]) * (e[j] * inv);
                ds[r * 256 + c] = dot;
            }
        }
        __syncthreads();
        {
            int w = tid >> 5, lane = tid & 31;
#pragma unroll
            for (int rr = 0; rr < 2; rr++) {
                int r = w * 2 + rr;
                float best = -2.f; int bidx = 0;
                for (int kk = lane; kk < KCB; kk += 32) {
                    float v = ds[r * 256 + kk];
                    if (v > best) { best = v; bidx = kk; }
                }
#pragma unroll
                for (int o = 16; o > 0; o >>= 1) {
                    float ov = __shfl_down_sync(0xffffffffu, best, o);
                    int   oi = __shfl_down_sync(0xffffffffu, bidx, o);
                    if (ov > best || (ov == best && oi < bidx)) { best = ov; bidx = oi; }
                }
                if (lane == 0) ni[r] = bidx;
            }
        }
        __syncthreads();
        if (tid < RB && vl[tid]) {
            size_t row = (size_t)ri[tid];
            int oldidx = (int)out_idx[row];
            int newidx = ni[tid];
            if (newidx != oldidx) {
                out_idx[row] = (float)newidx;
                atomicSub(counts + oldidx, 1);
                atomicAdd(counts + newidx, 1);
                float dq = 0.f;
#pragma unroll
                for (int j = 0; j < ED; j++) {
                    float zb = zbf[row * ED + j];
                    float qv = emb[newidx * ED + j];
                    float dn = qv - zb;
                    float dl = emb[oldidx * ED + j] - zb;
                    dq += dn * dn - dl * dl;
                    out_q[row * ED + j] = qv;
                    __nv_bfloat16 h = __float2bfloat16(qv);
                    qs[row * 32 + j]      = h;
                    qs[row * 32 + 16 + j] = __float2bfloat16(qv - __bfloat162float(h));
                }
                atomicAdd(qlat, (double)dq);
            }
        }
        __syncthreads();
    }
}

// ---------------- per-column order statistics + contra loss (3 passes) ---------
__global__ __launch_bounds__(256) void select_kernel(
    const float* __restrict__ dist, double* __restrict__ contra)
{
    __shared__ unsigned ha[2048], hb[2048];
    __shared__ float fa[1024], fb[1024];
    __shared__ unsigned s_bin[2], s_rem[2];
    __shared__ float rf[256];
    __shared__ unsigned s_km, s_kt;
    __shared__ float s_cltP, s_sexP, s_cgtP, s_sgtP;
    int tid = threadIdx.x;
    const float* col = dist + (size_t)blockIdx.x * NROWS;
    const unsigned RA = NROWS / 2 - 1;
    const unsigned RBK = NROWS - 512;
    const float INV_TAU = 1.0f / 0.07f;

    // pass A: bits [31:21], shared histogram for both ranks
    for (int i = tid; i < 2048; i += 256) ha[i] = 0;
    __syncthreads();
    for (int i = tid; i < NROWS; i += 256) atomicAdd(&ha[fkey(col[i]) >> 21], 1u);
    __syncthreads();
    if (tid == 0) {
        unsigned c = 0;
        for (unsigned b = 0; b < 2048; b++) {
            unsigned h = ha[b];
            if (c <= RA && c + h > RA) { s_bin[0] = b; s_rem[0] = RA - c; }
            if (c <= RBK && c + h > RBK) { s_bin[1] = b; s_rem[1] = RBK - c; }
            c += h;
        }
    }
    __syncthreads();
    unsigned p0a = s_bin[0], p0b = s_bin[1];
    unsigned rema = s_rem[0], remb = s_rem[1];
    __syncthreads();

    // pass B: bits [20:10]
    for (int i = tid; i < 2048; i += 256) { ha[i] = 0; hb[i] = 0; }
    __syncthreads();
    for (int i = tid; i < NROWS; i += 256) {
        unsigned u = fkey(col[i]);
        unsigned t = u >> 21, m = (u >> 10) & 2047u;
        if (t == p0a) atomicAdd(&ha[m], 1u);
        if (t == p0b) atomicAdd(&hb[m], 1u);
    }
    __syncthreads();
    if (tid == 0) { unsigned c = 0; for (unsigned b = 0; b < 2048; b++) { unsigned h = ha[b];
        if (c + h > rema) { s_bin[0] = b; s_rem[0] = rema - c; break; } c += h; } }
    if (tid == 1) { unsigned c = 0; for (unsigned b = 0; b < 2048; b++) { unsigned h = hb[b];
        if (c + h > remb) { s_bin[1] = b; s_rem[1] = remb - c; break; } c += h; } }
    __syncthreads();
    unsigned p1a = (p0a << 11) | s_bin[0], p1b = (p0b << 11) | s_bin[1];
    rema = s_rem[0]; remb = s_rem[1];
    __syncthreads();

    // pass C: bits [9:0] histograms within target groups + streaming stats
    for (int i = tid; i < 1024; i += 256) { ha[i] = 0; hb[i] = 0; fa[i] = 0.f; fb[i] = 0.f; }
    __syncthreads();
    float cltS = 0.f, cgtS = 0.f, sexS = 0.f, sgtS = 0.f;
    for (int i = tid; i < NROWS; i += 256) {
        float x = col[i];
        unsigned u = fkey(x);
        unsigned pre = u >> 10;
        if (pre < p1a) { cltS += 1.f; sexS += expf(x * INV_TAU); }
        else if (pre == p1a) {
            atomicAdd(&ha[u & 1023u], 1u);
            atomicAdd(&fa[u & 1023u], expf(x * INV_TAU));
        }
        if (pre > p1b) { cgtS += 1.f; sgtS += x; }
        else if (pre == p1b) {
            atomicAdd(&hb[u & 1023u], 1u);
            atomicAdd(&fb[u & 1023u], x);
        }
    }
    __syncthreads();
    if (tid == 0) {
        unsigned c = 0; float es = 0.f; unsigned b = 0;
        for (; b < 1024; b++) { unsigned h = ha[b];
            if (c + h > rema) break; c += h; es += fa[b]; }
        s_km = (p1a << 10) | b;
        s_cltP = (float)c;
        s_sexP = es;
    }
    if (tid == 1) {
        unsigned c = 0; unsigned b = 0;
        for (; b < 1024; b++) { unsigned h = hb[b]; if (c + h > remb) break; c += h; }
        unsigned cg = 0; float sg = 0.f;
        for (unsigned bb = b + 1; bb < 1024; bb++) { cg += hb[bb]; sg += fb[bb]; }
        s_kt = (p1b << 10) | b;
        s_cgtP = (float)cg; s_sgtP = sg;
    }
    __syncthreads();

    float CGT, SGT, CLT, SEXR;
    rf[tid] = cgtS; __syncthreads();
    for (int s = 128; s; s >>= 1) { if (tid < s) rf[tid] += rf[tid + s]; __syncthreads(); }
    CGT = rf[0]; __syncthreads();
    rf[tid] = sgtS; __syncthreads();
    for (int s = 128; s; s >>= 1) { if (tid < s) rf[tid] += rf[tid + s]; __syncthreads(); }
    SGT = rf[0]; __syncthreads();
    rf[tid] = cltS; __syncthreads();
    for (int s = 128; s; s >>= 1) { if (tid < s) rf[tid] += rf[tid + s]; __syncthreads(); }
    CLT = rf[0]; __syncthreads();
    rf[tid] = sexS; __syncthreads();
    for (int s = 128; s; s >>= 1) { if (tid < s) rf[tid] += rf[tid + s]; __syncthreads(); }
    SEXR = rf[0];

    if (tid == 0) {
        float Tmed = finv(s_km);
        float Ttop = finv(s_kt);
        CGT += s_cgtP; SGT += s_sgtP;
        CLT += s_cltP;
        float SEXP = (SEXR + s_sexP) * expf(-Tmed * INV_TAU);
        float dis_pos = (SGT + (512.0f - CGT) * Ttop) * (1.0f / 512.0f);
        float Sx = SEXP + ((float)(NROWS / 2) - CLT);
        float a = dis_pos * INV_TAU, b = Tmed * INV_TAU;
        float m = fmaxf(a, b);
        float lse = m + logf(expf(a - m) + Sx * expf(b - m));
        atomicAdd(contra, (double)(lse - a));
    }
}

// ---------------- finalize scalars ----------------
__global__ void finalize_kernel(const int* __restrict__ counts,
                                const double* __restrict__ qlat,
                                const double* __restrict__ contra,
                                const double* __restrict__ recon,
                                float* __restrict__ out_sc)
{
    __shared__ float rr[256];
    int t = threadIdx.x;
    float p = (float)counts[t] / (float)NROWS;
    rr[t] = p * logf(p + 1e-10f);
    __syncthreads();
    for (int s = 128; s; s >>= 1) { if (t < s) rr[t] += rr[t + s]; __syncthreads(); }
    if (t == 0) {
        float q = (float)(*qlat / ((double)NROWS * ED));
        out_sc[0] = q;
        out_sc[1] = 0.25f * q;
        out_sc[2] = (float)(*contra / (double)KCB);
        out_sc[3] = expf(-rr[0]);
        out_sc[4] = (float)(*recon / ((double)NROWS * ACT_D));
    }
}

// ---------------- launch ----------------
extern "C" void kernel_launch(void* const* d_in, const int* in_sizes, int n_in,
                              void* d_out, int out_size)
{
    const float* actions    = (const float*)d_in[0];
    const float* conditions = (const float*)d_in[1];
    const float* enc_w1 = (const float*)d_in[2];  const float* enc_b1 = (const float*)d_in[3];
    const float* enc_w2 = (const float*)d_in[4];  const float* enc_b2 = (const float*)d_in[5];
    const float* enc_w3 = (const float*)d_in[6];  const float* enc_b3 = (const float*)d_in[7];
    const float* dec_w1 = (const float*)d_in[8];  const float* dec_b1 = (const float*)d_in[9];
    const float* dec_w2 = (const float*)d_in[10]; const float* dec_b2 = (const float*)d_in[11];
    const float* dec_w3 = (const float*)d_in[12]; const float* dec_b3 = (const float*)d_in[13];
    const float* embedding = (const float*)d_in[14];

    float* out = (float*)d_out;
    float* out_rec = out;
    float* out_q   = out + (size_t)NROWS * ACT_D;
    float* out_idx = out_q + (size_t)NROWS * ED;
    float* out_sc  = out_idx + NROWS;

    __nv_bfloat16 *A1, *Ah1, *Aq, *Ad1, *B1, *B2, *B3, *B4;
    float *z, *dist;
    double *qlat, *contra, *recon; int *counts, *ncand, *cand;
    cudaGetSymbolAddress((void**)&A1,  g_A1);
    cudaGetSymbolAddress((void**)&Ah1, g_Ah1);
    cudaGetSymbolAddress((void**)&Aq,  g_Aq);
    cudaGetSymbolAddress((void**)&Ad1, g_Ad1);
    cudaGetSymbolAddress((void**)&B1,  g_B1);
    cudaGetSymbolAddress((void**)&B2,  g_B2);
    cudaGetSymbolAddress((void**)&B3,  g_B3);
    cudaGetSymbolAddress((void**)&B4,  g_B4);
    cudaGetSymbolAddress((void**)&z,   g_z);
    cudaGetSymbolAddress((void**)&dist,g_dist);
    cudaGetSymbolAddress((void**)&qlat,  g_qlat);
    cudaGetSymbolAddress((void**)&contra,g_contra);
    cudaGetSymbolAddress((void**)&recon, g_recon);
    cudaGetSymbolAddress((void**)&counts,g_counts);
    cudaGetSymbolAddress((void**)&ncand, g_ncand);
    cudaGetSymbolAddress((void**)&cand,  g_cand);

    cudaFuncSetAttribute((const void*)tgemm<KP1, 1, false>, cudaFuncAttributeMaxDynamicSharedMemorySize, TG_SMEM);
    cudaFuncSetAttribute((const void*)tgemm<KP2, 2, false>, cudaFuncAttributeMaxDynamicSharedMemorySize, TG_SMEM);
    cudaFuncSetAttribute((const void*)tgemm<KP1, 1, true>,  cudaFuncAttributeMaxDynamicSharedMemorySize, TG_SMEM);
    cudaFuncSetAttribute((const void*)tgemm<KP4, 3, false>, cudaFuncAttributeMaxDynamicSharedMemorySize, TG_SMEM);
    cudaFuncSetAttribute((const void*)refine_kernel, cudaFuncAttributeMaxDynamicSharedMemorySize, RF_SMEM);

    // side stream + events (created once, outside any capture; the captured
    // work DAG is identical on every call)
    static cudaStream_t s2 = nullptr;
    static cudaEvent_t eF = nullptr, eW2 = nullptr, eWD = nullptr, eQ = nullptr, eS = nullptr;
    if (s2 == nullptr) {
        cudaStreamCreateWithFlags(&s2, cudaStreamNonBlocking);
        cudaEventCreateWithFlags(&eF,  cudaEventDisableTiming);
        cudaEventCreateWithFlags(&eW2, cudaEventDisableTiming);
        cudaEventCreateWithFlags(&eWD, cudaEventDisableTiming);
        cudaEventCreateWithFlags(&eQ,  cudaEventDisableTiming);
        cudaEventCreateWithFlags(&eS,  cudaEventDisableTiming);
    }

    init_kernel<<<1, 256>>>(counts, qlat, contra, recon, ncand);
    cudaEventRecord(eF, 0);
    cudaStreamWaitEvent(s2, eF, 0);

    // side stream: weight conversions + rec seed (hidden under enc1)
    conv_w_kernel<<<((size_t)H2D * KA2 + 255) / 256, 256, 0, s2>>>(enc_w2, 16, 512, H2D, B2, KP2, KA2);
    cudaEventRecord(eW2, s2);
    conv_w_kernel<<<((size_t)H2D * KA1 + 255) / 256, 256, 0, s2>>>(dec_w1, 16, 272, H2D, B3, KP1, KA1);
    conv_w_kernel<<<((size_t)H1D * KA4 + 255) / 256, 256, 0, s2>>>(dec_w2, 16, 256, H1D, B4, KP4, KA4);
    rec_init_kernel<<<((size_t)NROWS * ACT_D + 255) / 256, 256, 0, s2>>>(dec_b3, out_rec);
    cudaEventRecord(eWD, s2);

    // main: encoder
    conv_w_kernel<<<((size_t)H1D * KA1 + 255) / 256, 256>>>(enc_w1, 12, 268, H1D, B1, KP1, KA1);
    conv_cat_kernel<<<((size_t)NROWS * (KP1 / 2) + 255) / 256, 256>>>(
        actions, ACT_D, conditions, COND_D, A1, KP1, KA1);
    tgemm<KP1, 1, false><<<dim3(2, NROWS / 128), 512, TG_SMEM>>>(
        A1, B1, nullptr, enc_b1, nullptr, nullptr, nullptr, Ah1, nullptr, KP2);
    cudaStreamWaitEvent(0, eW2, 0);
    tgemm<KP2, 2, false><<<dim3(1, NROWS / 128), 512, TG_SMEM>>>(
        Ah1, B2, nullptr, enc_b2, enc_w3, enc_b3, z, nullptr, nullptr, 0);

    quantize_kernel<<<NROWS / 16, 256>>>(z, embedding, out_q, out_idx, dist, Aq,
                                         counts, qlat, ncand, cand);
    cudaEventRecord(eQ, 0);
    // side stream: order statistics (overlaps refine + decoder GEMMs)
    cudaStreamWaitEvent(s2, eQ, 0);
    select_kernel<<<KCB, 256, 0, s2>>>(dist, contra);
    cudaEventRecord(eS, s2);

    refine_kernel<<<2048, 256, RF_SMEM>>>(actions, conditions,
                                 enc_w1, enc_b1, enc_w2, enc_b2, enc_w3, enc_b3,
                                 embedding, z, out_q, out_idx, Aq, counts, qlat, ncand, cand);

    cudaStreamWaitEvent(0, eWD, 0);
    tgemm<KP1, 1, true><<<dim3(1, NROWS / 128), 512, TG_SMEM>>>(
        A1, B3, Aq, dec_b1, nullptr, nullptr, nullptr, Ad1, nullptr, KP4);
    tgemm<KP4, 3, false><<<dim3(2, NROWS / 128), 512, TG_SMEM>>>(
        Ad1, B4, nullptr, dec_b2, dec_w3, nullptr, nullptr, nullptr, out_rec, 0);
    recon_kernel<<<1024, 256>>>(out_rec, actions, recon);

    cudaStreamWaitEvent(0, eS, 0);
    finalize_kernel<<<1, 256>>>(counts, qlat, contra, recon, out_sc);
}

// round 15
// speedup vs baseline: 1.4557x; 1.1864x over previous
#include <cuda_runtime.h>
#include <cuda_bf16.h>
#include <math.h>
#include <stdint.h>

#define NROWS 131072
#define ACT_D 12
#define COND_D 256
#define KCB 256
#define ED 16
#define H1D 512
#define H2D 256

// Unified K-layout: small block at [0,16), conditions at [16,272).
#define KP1 288
#define KA1 576      // enc1 / dec1 inputs
#define KP2 512
#define KA2 1024     // enc2 input (K=512)
#define KP4 256
#define KA4 512      // dec2 input (K=256)

#define GAP_TAU 2e-3f
#define RB 16        // refine batch rows per block

// ---------------- scratch (static device globals; no allocs) ----------------
__device__ __nv_bfloat16 g_A1 [(size_t)NROWS * KA1];
__device__ __nv_bfloat16 g_Ah1[(size_t)NROWS * KA2];
__device__ __nv_bfloat16 g_Aq [(size_t)NROWS * 32];   // quantized [hi(16)|lo(16)]
__device__ __nv_bfloat16 g_Ad1[(size_t)NROWS * KA4];
__device__ __nv_bfloat16 g_B1 [(size_t)H1D * KA1];
__device__ __nv_bfloat16 g_B2 [(size_t)H2D * KA2];
__device__ __nv_bfloat16 g_B3 [(size_t)H2D * KA1];
__device__ __nv_bfloat16 g_B4 [(size_t)H1D * KA4];
__device__ float g_z   [(size_t)NROWS * ED];
__device__ float g_dist[(size_t)KCB * NROWS];   // transposed: [k][n]
__device__ double g_qlat, g_contra, g_recon;
__device__ int    g_counts[KCB];
__device__ int    g_ncand;
__device__ int    g_cand[NROWS];

// ---------------- helpers ----------------
__device__ __forceinline__ uint32_t smem_u32(const void* p) {
    uint32_t a;
    asm("{ .reg .u64 t; cvta.to.shared.u64 t, %1; cvt.u32.u64 %0, t; }"
        : "=r"(a) : "l"(p));
    return a;
}
__device__ __forceinline__ void cp_async16(uint32_t s, const void* g) {
    asm volatile("cp.async.cg.shared.global [%0], [%1], 16;" :: "r"(s), "l"(g) : "memory");
}
__device__ __forceinline__ void cp_commit() {
    asm volatile("cp.async.commit_group;" ::: "memory");
}
template <int N>
__device__ __forceinline__ void cp_wait() {
    asm volatile("cp.async.wait_group %0;" :: "n"(N) : "memory");
}
__device__ __forceinline__ void ldmx4(uint32_t& r0, uint32_t& r1, uint32_t& r2, uint32_t& r3,
                                      uint32_t addr) {
    asm volatile("ldmatrix.sync.aligned.m8n8.x4.shared.b16 {%0,%1,%2,%3}, [%4];"
                 : "=r"(r0), "=r"(r1), "=r"(r2), "=r"(r3) : "r"(addr));
}
__device__ __forceinline__ void mma_bf16(float* c, const uint32_t* a, const uint32_t* b) {
    asm volatile("mma.sync.aligned.m16n8k16.row.col.f32.bf16.bf16.f32 "
                 "{%0,%1,%2,%3}, {%4,%5,%6,%7}, {%8,%9}, {%0,%1,%2,%3};"
                 : "+f"(c[0]), "+f"(c[1]), "+f"(c[2]), "+f"(c[3])
                 : "r"(a[0]), "r"(a[1]), "r"(a[2]), "r"(a[3]), "r"(b[0]), "r"(b[1]));
}
__device__ __forceinline__ unsigned fkey(float x) {
    unsigned u = __float_as_uint(x);
    return (u & 0x80000000u) ? ~u : (u | 0x80000000u);
}
__device__ __forceinline__ float finv(unsigned k) {
    return (k & 0x80000000u) ? __uint_as_float(k & 0x7fffffffu)
                             : __uint_as_float(~k);
}

// ---------------- init ----------------
__global__ void init_kernel(int* counts, double* a, double* b, double* c, int* ncand) {
    int t = threadIdx.x;
    counts[t] = 0;
    if (t == 0) { *a = 0.0; *b = 0.0; *c = 0.0; *ncand = 0; }
}
__global__ void rec_init_kernel(const float* __restrict__ b3, float* __restrict__ rec) {
    size_t i = (size_t)blockIdx.x * 256 + threadIdx.x;
    if (i < (size_t)NROWS * ACT_D) rec[i] = b3[i % ACT_D];
}
__global__ void z_init_kernel(const float* __restrict__ b3, float* __restrict__ z) {
    size_t i = (size_t)blockIdx.x * 256 + threadIdx.x;
    if (i < (size_t)NROWS * ED) z[i] = b3[i & 15];
}
__global__ void recon_kernel(const float* __restrict__ rec, const float* __restrict__ act,
                             double* __restrict__ out) {
    __shared__ float rf[256];
    int tid = threadIdx.x;
    float s = 0.f;
    for (size_t i = (size_t)blockIdx.x * 256 + tid; i < (size_t)NROWS * ACT_D;
         i += (size_t)gridDim.x * 256) {
        float d = rec[i] - act[i];
        s += d * d;
    }
    rf[tid] = s; __syncthreads();
    for (int st = 128; st; st >>= 1) { if (tid < st) rf[tid] += rf[tid + st]; __syncthreads(); }
    if (tid == 0) atomicAdd(out, (double)rf[0]);
}

// ---------------- split conversions (unified layout, 2-segment [hi|lo]) ----------
__global__ void conv_cat_kernel(const float* __restrict__ a, int ad,
                                const float* __restrict__ b, int bd,
                                __nv_bfloat16* __restrict__ o, int KP, int KA)
{
    int pairs = KP >> 1;
    size_t t = (size_t)blockIdx.x * 256 + threadIdx.x;
    size_t row = t / pairs;
    if (row >= NROWS) return;
    int p = (int)(t % pairs);
    int j = p * 2;
    float v0 = 0.f, v1 = 0.f;
    if (j < 16) {
        if (j < ad)     v0 = a[row * ad + j];
        if (j + 1 < ad) v1 = a[row * ad + j + 1];
    } else {
        int c = j - 16;
        if (c < bd)     v0 = b[row * bd + c];
        if (c + 1 < bd) v1 = b[row * bd + c + 1];
    }
    __nv_bfloat162 hh, ll;
    hh.x = __float2bfloat16(v0); hh.y = __float2bfloat16(v1);
    ll.x = __float2bfloat16(v0 - __bfloat162float(hh.x));
    ll.y = __float2bfloat16(v1 - __bfloat162float(hh.y));
    __nv_bfloat16* base = o + row * (size_t)KA;
    ((__nv_bfloat162*)(base))[p]      = hh;
    ((__nv_bfloat162*)(base + KP))[p] = ll;
}
__global__ void conv_w_kernel(const float* __restrict__ W, int ad, int K, int Nn,
                              __nv_bfloat16* __restrict__ o, int KP, int KA)
{
    size_t t = (size_t)blockIdx.x * 256 + threadIdx.x;
    if (t >= (size_t)Nn * KA) return;
    int n  = (int)(t / KA);
    int kt = (int)(t % KA);
    int s  = kt < KP ? 0 : 1;
    int c  = kt - s * KP;
    int k  = (c < 16) ? ((c < ad) ? c : -1) : (c - (16 - ad));
    float v = (k >= 0 && k < K) ? W[(size_t)k * Nn + n] : 0.f;
    __nv_bfloat16 h = __float2bfloat16(v);
    __nv_bfloat16 r = s ? __float2bfloat16(v - __bfloat162float(h)) : h;
    o[(size_t)n * KA + kt] = r;
}

// ---------------- tensor-core GEMM: 128x128 CTA, 8 warps, 2 CTAs/SM, 2-stage ---
// OUTM 1: bf16 [hi|lo] out (segment KPn)
// OUTM 2: fused z partial: atomicAdd(Zf, elu(tile) @ W3[col0..col0+128, 16])
// OUTM 3: fused rec partial: atomicAdd(Rf, elu(tile) @ W3[col0..col0+128, 12])
#define SROW 80
#define S_AHI 0
#define S_ALO 10240
#define S_BHI 20480
#define S_BLO 30720
#define STAGE 40960
#define NSTG 2
#define TG_SMEM (NSTG * STAGE)
#define ERS 132   // fp32 epilogue smem row stride

template <int KP, int OUTM, bool QSRC>
__global__ __launch_bounds__(256, 2) void tgemm(
    const __nv_bfloat16* __restrict__ Ap,
    const __nv_bfloat16* __restrict__ Bp,
    const __nv_bfloat16* __restrict__ Qs,
    const float* __restrict__ bias,
    const float* __restrict__ W3,
    float* __restrict__ Zf,
    __nv_bfloat16* __restrict__ Cb,
    float* __restrict__ Rf,
    int KPn)
{
    extern __shared__ __align__(16) uint8_t smem[];
    const uint32_t sm = smem_u32(smem);
    const int KA = 2 * KP;

    const int tid = threadIdx.x;
    const int wid = tid >> 5, lane = tid & 31;
    const int wr = wid >> 2, wc = wid & 3;          // warps 2 x 4
    const size_t row0 = (size_t)blockIdx.y * 128;
    const int    col0 = blockIdx.x * 128;

    const int NCH = KP / 32;

    float acc[4][4][4];
#pragma unroll
    for (int i = 0; i < 4; i++)
#pragma unroll
        for (int j = 0; j < 4; j++)
#pragma unroll
            for (int e = 0; e < 4; e++) acc[i][j][e] = 0.f;

    auto load_chunk = [&](int c, int buf) {
        const int kc = c * 32;
        const uint32_t base = sm + buf * STAGE;
#pragma unroll
        for (int l = 0; l < 2; l++) {
            int L = tid + l * 256;
            int row = L >> 2, seg = L & 3;
            size_t rg = row0 + row;
            int c0 = kc + seg * 8;
            uint32_t so = row * SROW + seg * 16;
            const __nv_bfloat16* hs;
            const __nv_bfloat16* ls;
            if (QSRC && c0 < 16) {
                hs = Qs + rg * 32 + c0;
                ls = Qs + rg * 32 + 16 + c0;
            } else {
                hs = Ap + rg * (size_t)KA + c0;
                ls = hs + KP;
            }
            cp_async16(base + S_AHI + so, hs);
            cp_async16(base + S_ALO + so, ls);
        }
#pragma unroll
        for (int l = 0; l < 2; l++) {
            int L = tid + l * 256;
            int row = L >> 2, seg = L & 3;
            const __nv_bfloat16* gb = Bp + (size_t)(col0 + row) * KA + kc + seg * 8;
            uint32_t so = row * SROW + seg * 16;
            cp_async16(base + S_BHI + so, gb);
            cp_async16(base + S_BLO + so, gb + KP);
        }
        cp_commit();
    };

    load_chunk(0, 0);

    for (int c = 0; c < NCH; c++) {
        cp_wait<0>();
        __syncthreads();
        int nc = c + 1;
        if (nc < NCH) load_chunk(nc, nc & 1);
        else          cp_commit();

        const uint32_t st = sm + (c & 1) * STAGE;
        const int g = lane >> 3, lr = lane & 7;

#pragma unroll
        for (int ks = 0; ks < 2; ks++) {
            const uint32_t acolo = (ks * 16 + (g >> 1) * 8) * 2;
            const uint32_t bcolo = (ks * 16 + (g & 1) * 8) * 2;
            uint32_t afh[4][4];
#pragma unroll
            for (int mt = 0; mt < 4; mt++) {
                int r = wr * 64 + mt * 16 + (g & 1) * 8 + lr;
                ldmx4(afh[mt][0], afh[mt][1], afh[mt][2], afh[mt][3],
                      st + S_AHI + r * SROW + acolo);
            }
            uint32_t bfh[4][2];
#pragma unroll
            for (int bt = 0; bt < 2; bt++) {
                int r = wc * 32 + bt * 16 + (g >> 1) * 8 + lr;
                uint32_t r0, r1, r2, r3;
                ldmx4(r0, r1, r2, r3, st + S_BHI + r * SROW + bcolo);
                bfh[bt * 2][0] = r0;     bfh[bt * 2][1] = r1;
                bfh[bt * 2 + 1][0] = r2; bfh[bt * 2 + 1][1] = r3;
            }
#pragma unroll
            for (int mt = 0; mt < 4; mt++)
#pragma unroll
                for (int nt = 0; nt < 4; nt++)
                    mma_bf16(acc[mt][nt], afh[mt], bfh[nt]);
#pragma unroll
            for (int mt = 0; mt < 4; mt++) {
                int r = wr * 64 + mt * 16 + (g & 1) * 8 + lr;
                uint32_t al[4];
                ldmx4(al[0], al[1], al[2], al[3], st + S_ALO + r * SROW + acolo);
#pragma unroll
                for (int nt = 0; nt < 4; nt++)
                    mma_bf16(acc[mt][nt], al, bfh[nt]);
            }
#pragma unroll
            for (int bt = 0; bt < 2; bt++) {
                int r = wc * 32 + bt * 16 + (g >> 1) * 8 + lr;
                uint32_t r0, r1, r2, r3;
                ldmx4(r0, r1, r2, r3, st + S_BLO + r * SROW + bcolo);
                uint32_t bl0[2] = {r0, r1}, bl1[2] = {r2, r3};
#pragma unroll
                for (int mt = 0; mt < 4; mt++) {
                    mma_bf16(acc[mt][bt * 2],     afh[mt], bl0);
                    mma_bf16(acc[mt][bt * 2 + 1], afh[mt], bl1);
                }
            }
        }
    }

    if (OUTM == 1) {
#pragma unroll
        for (int mt = 0; mt < 4; mt++) {
            size_t ra = row0 + wr * 64 + mt * 16 + (lane >> 2);
            size_t rb = ra + 8;
#pragma unroll
            for (int nt = 0; nt < 4; nt++) {
                int colg = col0 + wc * 32 + nt * 8 + (lane & 3) * 2;
                float b0 = bias[colg], b1 = bias[colg + 1];
                float v00 = acc[mt][nt][0] + b0, v01 = acc[mt][nt][1] + b1;
                float v10 = acc[mt][nt][2] + b0, v11 = acc[mt][nt][3] + b1;
                v00 = (v00 > 0.f) ? v00 : expm1f(v00);
                v01 = (v01 > 0.f) ? v01 : expm1f(v01);
                v10 = (v10 > 0.f) ? v10 : expm1f(v10);
                v11 = (v11 > 0.f) ? v11 : expm1f(v11);
                const size_t KTn = 2 * (size_t)KPn;
                __nv_bfloat162 hh, ll;
                __nv_bfloat16* pa = Cb + ra * KTn;
                hh.x = __float2bfloat16(v00); hh.y = __float2bfloat16(v01);
                ll.x = __float2bfloat16(v00 - __bfloat162float(hh.x));
                ll.y = __float2bfloat16(v01 - __bfloat162float(hh.y));
                *(__nv_bfloat162*)(pa + colg)       = hh;
                *(__nv_bfloat162*)(pa + KPn + colg) = ll;
                __nv_bfloat16* pb = Cb + rb * KTn;
                hh.x = __float2bfloat16(v10); hh.y = __float2bfloat16(v11);
                ll.x = __float2bfloat16(v10 - __bfloat162float(hh.x));
                ll.y = __float2bfloat16(v11 - __bfloat162float(hh.y));
                *(__nv_bfloat162*)(pb + colg)       = hh;
                *(__nv_bfloat162*)(pb + KPn + colg) = ll;
            }
        }
    } else {
        __syncthreads();
        float* fsm = (float*)smem;
#pragma unroll
        for (int mt = 0; mt < 4; mt++) {
            int ra = wr * 64 + mt * 16 + (lane >> 2);
            int rb = ra + 8;
#pragma unroll
            for (int nt = 0; nt < 4; nt++) {
                int colL = wc * 32 + nt * 8 + (lane & 3) * 2;
                float b0 = bias[col0 + colL], b1 = bias[col0 + colL + 1];
                float v00 = acc[mt][nt][0] + b0, v01 = acc[mt][nt][1] + b1;
                float v10 = acc[mt][nt][2] + b0, v11 = acc[mt][nt][3] + b1;
                v00 = (v00 > 0.f) ? v00 : expm1f(v00);
                v01 = (v01 > 0.f) ? v01 : expm1f(v01);
                v10 = (v10 > 0.f) ? v10 : expm1f(v10);
                v11 = (v11 > 0.f) ? v11 : expm1f(v11);
                *(float2*)(fsm + ra * ERS + colL) = make_float2(v00, v01);
                *(float2*)(fsm + rb * ERS + colL) = make_float2(v10, v11);
            }
        }
        __syncthreads();
        if (OUTM == 2) {
            // z partial: 128 rows x 16 cols, K-slice [col0, col0+128)
            int r = tid >> 1, jb = (tid & 1) * 8;
            float s[8];
#pragma unroll
            for (int i = 0; i < 8; i++) s[i] = 0.f;
            const float* fr = fsm + r * ERS;
            for (int k = 0; k < 128; k++) {
                float a = fr[k];
                const float* w = W3 + (size_t)(col0 + k) * 16 + jb;
#pragma unroll
                for (int i = 0; i < 8; i++) s[i] = fmaf(a, w[i], s[i]);
            }
            float* zo = Zf + (row0 + r) * 16 + jb;
#pragma unroll
            for (int i = 0; i < 8; i++) atomicAdd(zo + i, s[i]);
        } else {
            // rec partial: 128 rows x 12 cols, K-slice [col0, col0+128)
            int r = tid >> 1, jb = (tid & 1) * 6;
            float s[6];
#pragma unroll
            for (int i = 0; i < 6; i++) s[i] = 0.f;
            const float* fr = fsm + r * ERS;
            for (int k = 0; k < 128; k++) {
                float a = fr[k];
                const float* w = W3 + (size_t)(col0 + k) * 12 + jb;
#pragma unroll
                for (int i = 0; i < 6; i++) s[i] = fmaf(a, w[i], s[i]);
            }
            float* ro = Rf + (row0 + r) * 12 + jb;
#pragma unroll
            for (int i = 0; i < 6; i++) atomicAdd(ro + i, s[i]);
        }
    }
}

// ---------------- quantize (+ near-tie candidates + qsplit emit) ----------------
__global__ __launch_bounds__(256) void quantize_kernel(
    const float* __restrict__ z, const float* __restrict__ emb,
    float* __restrict__ out_q, float* __restrict__ out_idx,
    float* __restrict__ dist, __nv_bfloat16* __restrict__ qs,
    int* __restrict__ counts, double* __restrict__ qlat,
    int* __restrict__ ncand, int* __restrict__ cand)
{
    __shared__ float embn[KCB][ED];
    __shared__ float zt[16][ED + 1];
    __shared__ float rinv[16];
    __shared__ float n2[16];
    __shared__ float sd[KCB][17];
    __shared__ int   shist[KCB];
    __shared__ float sq;
    int tid = threadIdx.x;
    size_t row0 = (size_t)blockIdx.x * 16;
    shist[tid] = 0;
    if (tid == 0) sq = 0.f;
    {
        float e[ED], s = 0.f;
#pragma unroll
        for (int j = 0; j < ED; j++) { e[j] = emb[tid * ED + j]; s += e[j] * e[j]; }
        float inv = 1.f / fmaxf(sqrtf(s), 1e-12f);
#pragma unroll
        for (int j = 0; j < ED; j++) embn[tid][j] = e[j] * inv;
    }
    { int r = tid >> 4, j = tid & 15; zt[r][j] = z[(row0 + r) * ED + j]; }
    __syncthreads();
    if (tid < 16) {
        float s = 0.f;
#pragma unroll
        for (int j = 0; j < ED; j++) s += zt[tid][j] * zt[tid][j];
        n2[tid] = s;
        rinv[tid] = 1.f / fmaxf(sqrtf(s), 1e-12f);
    }
    __syncthreads();
    for (int r = 0; r < 16; r++) {
        float s = 0.f;
#pragma unroll
        for (int j = 0; j < ED; j++) s += zt[r][j] * embn[tid][j];
        sd[tid][r] = s * rinv[r];
    }
    __syncthreads();
    int w = tid >> 5, lane = tid & 31;
    for (int c = 0; c < 32; c++) {
        int k = w * 32 + c;
        if (lane < 16) dist[(size_t)k * NROWS + row0 + lane] = sd[k][lane];
    }
    for (int rr = 0; rr < 2; rr++) {
        int r = w * 2 + rr;
        float best = -2.f; int bi = 0;
        for (int kk = lane; kk < KCB; kk += 32) {
            float v = sd[kk][r];
            if (v > best) { best = v; bi = kk; }
        }
#pragma unroll
        for (int o = 16; o > 0; o >>= 1) {
            float ov = __shfl_down_sync(0xffffffffu, best, o);
            int   oi = __shfl_down_sync(0xffffffffu, bi, o);
            if (ov > best || (ov == best && oi < bi)) { best = ov; bi = oi; }
        }
        bi   = __shfl_sync(0xffffffffu, bi, 0);
        best = __shfl_sync(0xffffffffu, best, 0);
        float sec = -2.f;
        for (int kk = lane; kk < KCB; kk += 32)
            if (kk != bi) sec = fmaxf(sec, sd[kk][r]);
#pragma unroll
        for (int o = 16; o > 0; o >>= 1)
            sec = fmaxf(sec, __shfl_down_sync(0xffffffffu, sec, o));
        float dd = 0.f;
        if (lane < ED) {
            float qv = emb[bi * ED + lane];
            float d = qv - zt[r][lane];
            out_q[(row0 + r) * ED + lane] = qv;
            __nv_bfloat16 h = __float2bfloat16(qv);
            qs[(row0 + r) * 32 + lane]      = h;
            qs[(row0 + r) * 32 + 16 + lane] = __float2bfloat16(qv - __bfloat162float(h));
            dd = d * d;
        }
#pragma unroll
        for (int o = 16; o > 0; o >>= 1) dd += __shfl_down_sync(0xffffffffu, dd, o);
        if (lane == 0) {
            atomicAdd(&sq, dd);
            atomicAdd(&shist[bi], 1);
            out_idx[row0 + r] = (float)bi;
            if (best - sec < GAP_TAU || n2[r] < 1e-4f) {
                int s = atomicAdd(ncand, 1);
                cand[s] = (int)(row0 + r);
            }
        }
    }
    __syncthreads();
    if (shist[tid]) atomicAdd(&counts[tid], shist[tid]);
    if (tid == 0) atomicAdd(qlat, (double)sq);
}

// ---------------- batched exact fp32 re-check of near-tie rows ----------------
#define RF_SMEM ((RB * 272 + RB * 512 + RB * 256 + RB * 16 + RB + RB * 256) * 4 + RB * 12)
__global__ __launch_bounds__(256) void refine_kernel(
    const float* __restrict__ actions, const float* __restrict__ conditions,
    const float* __restrict__ ew1, const float* __restrict__ eb1,
    const float* __restrict__ ew2, const float* __restrict__ eb2,
    const float* __restrict__ ew3, const float* __restrict__ eb3,
    const float* __restrict__ emb,
    const float* __restrict__ zbf,
    float* __restrict__ out_q, float* __restrict__ out_idx,
    __nv_bfloat16* __restrict__ qs,
    int* __restrict__ counts, double* __restrict__ qlat,
    const int* __restrict__ ncand, const int* __restrict__ cand)
{
    extern __shared__ float sh[];
    float* xs   = sh;
    float* h1s  = xs + RB * 272;
    float* h2s  = h1s + RB * 512;
    float* zs   = h2s + RB * 256;
    float* zinv = zs + RB * 16;
    float* ds   = zinv + RB;
    int*   ri   = (int*)(ds + RB * 256);
    int*   vl   = ri + RB;
    int*   ni   = vl + RB;

    int tid = threadIdx.x;
    int n = *ncand;
    for (int bi = blockIdx.x; bi * RB < n; bi += gridDim.x) {
        if (tid < RB) {
            int idx = bi * RB + tid;
            vl[tid] = (idx < n);
            ri[tid] = cand[(idx < n) ? idx : (n - 1)];
        }
        __syncthreads();
        for (int e = tid; e < RB * 268; e += 256) {
            int r = e / 268, j = e % 268;
            size_t row = (size_t)ri[r];
            xs[r * 272 + j] = (j < ACT_D) ? actions[row * ACT_D + j]
                                          : conditions[row * COND_D + (j - ACT_D)];
        }
        __syncthreads();
#pragma unroll
        for (int cc = 0; cc < 2; cc++) {
            int c = tid + cc * 256;
            float a0[RB];
            float b = eb1[c];
#pragma unroll
            for (int r = 0; r < RB; r++) a0[r] = b;
            for (int k = 0; k < 268; k++) {
                float w = ew1[(size_t)k * H1D + c];
#pragma unroll
                for (int r = 0; r < RB; r++) a0[r] = fmaf(xs[r * 272 + k], w, a0[r]);
            }
#pragma unroll
            for (int r = 0; r < RB; r++)
                h1s[r * 512 + c] = (a0[r] > 0.f) ? a0[r] : expm1f(a0[r]);
        }
        __syncthreads();
        {
            int c = tid;
            float a0[RB];
            float b = eb2[c];
#pragma unroll
            for (int r = 0; r < RB; r++) a0[r] = b;
            for (int k = 0; k < 512; k++) {
                float w = ew2[(size_t)k * H2D + c];
#pragma unroll
                for (int r = 0; r < RB; r++) a0[r] = fmaf(h1s[r * 512 + k], w, a0[r]);
            }
#pragma unroll
            for (int r = 0; r < RB; r++)
                h2s[r * 256 + c] = (a0[r] > 0.f) ? a0[r] : expm1f(a0[r]);
        }
        __syncthreads();
        {
            int r = tid >> 4, c = tid & 15;
            float s = eb3[c];
            for (int k = 0; k < 256; k++)
                s = fmaf(h2s[r * 256 + k], ew3[(size_t)k * ED + c], s);
            zs[r * 16 + c] = s;
        }
        __syncthreads();
        if (tid < RB) {
            float s = 0.f;
#pragma unroll
            for (int j = 0; j < ED; j++) s += zs[tid * 16 + j] * zs[tid * 16 + j];
            zinv[tid] = 1.f / fmaxf(sqrtf(s), 1e-12f);
        }
        __syncthreads();
        {
            int c = tid;
            float e[ED], s = 0.f;
#pragma unroll
            for (int j = 0; j < ED; j++) { e[j] = emb[c * ED + j]; s += e[j] * e[j]; }
            float inv = 1.f / fmaxf(sqrtf(s), 1e-12f);
#pragma unroll
            for (int r = 0; r < RB; r++) {
                float dot = 0.f;
#pragma unroll
                for (int j = 0; j < ED; j++)
                    dot += (zs[r * 16 + j] * zinv[r]) * (e[j] * inv);
                ds[r * 256 + c] = dot;
            }
        }
        __syncthreads();
        {
            int w = tid >> 5, lane = tid & 31;
#pragma unroll
            for (int rr = 0; rr < 2; rr++) {
                int r = w * 2 + rr;
                float best = -2.f; int bidx = 0;
                for (int kk = lane; kk < KCB; kk += 32) {
                    float v = ds[r * 256 + kk];
                    if (v > best) { best = v; bidx = kk; }
                }
#pragma unroll
                for (int o = 16; o > 0; o >>= 1) {
                    float ov = __shfl_down_sync(0xffffffffu, best, o);
                    int   oi = __shfl_down_sync(0xffffffffu, bidx, o);
                    if (ov > best || (ov == best && oi < bidx)) { best = ov; bidx = oi; }
                }
                if (lane == 0) ni[r] = bidx;
            }
        }
        __syncthreads();
        if (tid < RB && vl[tid]) {
            size_t row = (size_t)ri[tid];
            int oldidx = (int)out_idx[row];
            int newidx = ni[tid];
            if (newidx != oldidx) {
                out_idx[row] = (float)newidx;
                atomicSub(counts + oldidx, 1);
                atomicAdd(counts + newidx, 1);
                float dq = 0.f;
#pragma unroll
                for (int j = 0; j < ED; j++) {
                    float zb = zbf[row * ED + j];
                    float qv = emb[newidx * ED + j];
                    float dn = qv - zb;
                    float dl = emb[oldidx * ED + j] - zb;
                    dq += dn * dn - dl * dl;
                    out_q[row * ED + j] = qv;
                    __nv_bfloat16 h = __float2bfloat16(qv);
                    qs[row * 32 + j]      = h;
                    qs[row * 32 + 16 + j] = __float2bfloat16(qv - __bfloat162float(h));
                }
                atomicAdd(qlat, (double)dq);
            }
        }
        __syncthreads();
    }
}

// ---------------- per-column order statistics + contra loss (3 passes) ---------
__global__ __launch_bounds__(256) void select_kernel(
    const float* __restrict__ dist, double* __restrict__ contra)
{
    __shared__ unsigned ha[2048], hb[2048];
    __shared__ float fa[1024], fb[1024];
    __shared__ unsigned s_bin[2], s_rem[2];
    __shared__ float rf[256];
    __shared__ unsigned s_km, s_kt;
    __shared__ float s_cltP, s_sexP, s_cgtP, s_sgtP;
    int tid = threadIdx.x;
    const float* col = dist + (size_t)blockIdx.x * NROWS;
    const unsigned RA = NROWS / 2 - 1;
    const unsigned RBK = NROWS - 512;
    const float INV_TAU = 1.0f / 0.07f;

    for (int i = tid; i < 2048; i += 256) ha[i] = 0;
    __syncthreads();
    for (int i = tid; i < NROWS; i += 256) atomicAdd(&ha[fkey(col[i]) >> 21], 1u);
    __syncthreads();
    if (tid == 0) {
        unsigned c = 0;
        for (unsigned b = 0; b < 2048; b++) {
            unsigned h = ha[b];
            if (c <= RA && c + h > RA) { s_bin[0] = b; s_rem[0] = RA - c; }
            if (c <= RBK && c + h > RBK) { s_bin[1] = b; s_rem[1] = RBK - c; }
            c += h;
        }
    }
    __syncthreads();
    unsigned p0a = s_bin[0], p0b = s_bin[1];
    unsigned rema = s_rem[0], remb = s_rem[1];
    __syncthreads();

    for (int i = tid; i < 2048; i += 256) { ha[i] = 0; hb[i] = 0; }
    __syncthreads();
    for (int i = tid; i < NROWS; i += 256) {
        unsigned u = fkey(col[i]);
        unsigned t = u >> 21, m = (u >> 10) & 2047u;
        if (t == p0a) atomicAdd(&ha[m], 1u);
        if (t == p0b) atomicAdd(&hb[m], 1u);
    }
    __syncthreads();
    if (tid == 0) { unsigned c = 0; for (unsigned b = 0; b < 2048; b++) { unsigned h = ha[b];
        if (c + h > rema) { s_bin[0] = b; s_rem[0] = rema - c; break; } c += h; } }
    if (tid == 1) { unsigned c = 0; for (unsigned b = 0; b < 2048; b++) { unsigned h = hb[b];
        if (c + h > remb) { s_bin[1] = b; s_rem[1] = remb - c; break; } c += h; } }
    __syncthreads();
    unsigned p1a = (p0a << 11) | s_bin[0], p1b = (p0b << 11) | s_bin[1];
    rema = s_rem[0]; remb = s_rem[1];
    __syncthreads();

    for (int i = tid; i < 1024; i += 256) { ha[i] = 0; hb[i] = 0; fa[i] = 0.f; fb[i] = 0.f; }
    __syncthreads();
    float cltS = 0.f, cgtS = 0.f, sexS = 0.f, sgtS = 0.f;
    for (int i = tid; i < NROWS; i += 256) {
        float x = col[i];
        unsigned u = fkey(x);
        unsigned pre = u >> 10;
        if (pre < p1a) { cltS += 1.f; sexS += expf(x * INV_TAU); }
        else if (pre == p1a) {
            atomicAdd(&ha[u & 1023u], 1u);
            atomicAdd(&fa[u & 1023u], expf(x * INV_TAU));
        }
        if (pre > p1b) { cgtS += 1.f; sgtS += x; }
        else if (pre == p1b) {
            atomicAdd(&hb[u & 1023u], 1u);
            atomicAdd(&fb[u & 1023u], x);
        }
    }
    __syncthreads();
    if (tid == 0) {
        unsigned c = 0; float es = 0.f; unsigned b = 0;
        for (; b < 1024; b++) { unsigned h = ha[b];
            if (c + h > rema) break; c += h; es += fa[b]; }
        s_km = (p1a << 10) | b;
        s_cltP = (float)c;
        s_sexP = es;
    }
    if (tid == 1) {
        unsigned c = 0; unsigned b = 0;
        for (; b < 1024; b++) { unsigned h = hb[b]; if (c + h > remb) break; c += h; }
        unsigned cg = 0; float sg = 0.f;
        for (unsigned bb = b + 1; bb < 1024; bb++) { cg += hb[bb]; sg += fb[bb]; }
        s_kt = (p1b << 10) | b;
        s_cgtP = (float)cg; s_sgtP = sg;
    }
    __syncthreads();

    float CGT, SGT, CLT, SEXR;
    rf[tid] = cgtS; __syncthreads();
    for (int s = 128; s; s >>= 1) { if (tid < s) rf[tid] += rf[tid + s]; __syncthreads(); }
    CGT = rf[0]; __syncthreads();
    rf[tid] = sgtS; __syncthreads();
    for (int s = 128; s; s >>= 1) { if (tid < s) rf[tid] += rf[tid + s]; __syncthreads(); }
    SGT = rf[0]; __syncthreads();
    rf[tid] = cltS; __syncthreads();
    for (int s = 128; s; s >>= 1) { if (tid < s) rf[tid] += rf[tid + s]; __syncthreads(); }
    CLT = rf[0]; __syncthreads();
    rf[tid] = sexS; __syncthreads();
    for (int s = 128; s; s >>= 1) { if (tid < s) rf[tid] += rf[tid + s]; __syncthreads(); }
    SEXR = rf[0];

    if (tid == 0) {
        float Tmed = finv(s_km);
        float Ttop = finv(s_kt);
        CGT += s_cgtP; SGT += s_sgtP;
        CLT += s_cltP;
        float SEXP = (SEXR + s_sexP) * expf(-Tmed * INV_TAU);
        float dis_pos = (SGT + (512.0f - CGT) * Ttop) * (1.0f / 512.0f);
        float Sx = SEXP + ((float)(NROWS / 2) - CLT);
        float a = dis_pos * INV_TAU, b = Tmed * INV_TAU;
        float m = fmaxf(a, b);
        float lse = m + logf(expf(a - m) + Sx * expf(b - m));
        atomicAdd(contra, (double)(lse - a));
    }
}

// ---------------- finalize scalars ----------------
__global__ void finalize_kernel(const int* __restrict__ counts,
                                const double* __restrict__ qlat,
                                const double* __restrict__ contra,
                                const double* __restrict__ recon,
                                float* __restrict__ out_sc)
{
    __shared__ float rr[256];
    int t = threadIdx.x;
    float p = (float)counts[t] / (float)NROWS;
    rr[t] = p * logf(p + 1e-10f);
    __syncthreads();
    for (int s = 128; s; s >>= 1) { if (t < s) rr[t] += rr[t + s]; __syncthreads(); }
    if (t == 0) {
        float q = (float)(*qlat / ((double)NROWS * ED));
        out_sc[0] = q;
        out_sc[1] = 0.25f * q;
        out_sc[2] = (float)(*contra / (double)KCB);
        out_sc[3] = expf(-rr[0]);
        out_sc[4] = (float)(*recon / ((double)NROWS * ACT_D));
    }
}

// ---------------- launch ----------------
extern "C" void kernel_launch(void* const* d_in, const int* in_sizes, int n_in,
                              void* d_out, int out_size)
{
    const float* actions    = (const float*)d_in[0];
    const float* conditions = (const float*)d_in[1];
    const float* enc_w1 = (const float*)d_in[2];  const float* enc_b1 = (const float*)d_in[3];
    const float* enc_w2 = (const float*)d_in[4];  const float* enc_b2 = (const float*)d_in[5];
    const float* enc_w3 = (const float*)d_in[6];  const float* enc_b3 = (const float*)d_in[7];
    const float* dec_w1 = (const float*)d_in[8];  const float* dec_b1 = (const float*)d_in[9];
    const float* dec_w2 = (const float*)d_in[10]; const float* dec_b2 = (const float*)d_in[11];
    const float* dec_w3 = (const float*)d_in[12]; const float* dec_b3 = (const float*)d_in[13];
    const float* embedding = (const float*)d_in[14];

    float* out = (float*)d_out;
    float* out_rec = out;
    float* out_q   = out + (size_t)NROWS * ACT_D;
    float* out_idx = out_q + (size_t)NROWS * ED;
    float* out_sc  = out_idx + NROWS;

    __nv_bfloat16 *A1, *Ah1, *Aq, *Ad1, *B1, *B2, *B3, *B4;
    float *z, *dist;
    double *qlat, *contra, *recon; int *counts, *ncand, *cand;
    cudaGetSymbolAddress((void**)&A1,  g_A1);
    cudaGetSymbolAddress((void**)&Ah1, g_Ah1);
    cudaGetSymbolAddress((void**)&Aq,  g_Aq);
    cudaGetSymbolAddress((void**)&Ad1, g_Ad1);
    cudaGetSymbolAddress((void**)&B1,  g_B1);
    cudaGetSymbolAddress((void**)&B2,  g_B2);
    cudaGetSymbolAddress((void**)&B3,  g_B3);
    cudaGetSymbolAddress((void**)&B4,  g_B4);
    cudaGetSymbolAddress((void**)&z,   g_z);
    cudaGetSymbolAddress((void**)&dist,g_dist);
    cudaGetSymbolAddress((void**)&qlat,  g_qlat);
    cudaGetSymbolAddress((void**)&contra,g_contra);
    cudaGetSymbolAddress((void**)&recon, g_recon);
    cudaGetSymbolAddress((void**)&counts,g_counts);
    cudaGetSymbolAddress((void**)&ncand, g_ncand);
    cudaGetSymbolAddress((void**)&cand,  g_cand);

    cudaFuncSetAttribute((const void*)tgemm<KP1, 1, false>, cudaFuncAttributeMaxDynamicSharedMemorySize, TG_SMEM);
    cudaFuncSetAttribute((const void*)tgemm<KP2, 2, false>, cudaFuncAttributeMaxDynamicSharedMemorySize, TG_SMEM);
    cudaFuncSetAttribute((const void*)tgemm<KP1, 1, true>,  cudaFuncAttributeMaxDynamicSharedMemorySize, TG_SMEM);
    cudaFuncSetAttribute((const void*)tgemm<KP4, 3, false>, cudaFuncAttributeMaxDynamicSharedMemorySize, TG_SMEM);
    cudaFuncSetAttribute((const void*)refine_kernel, cudaFuncAttributeMaxDynamicSharedMemorySize, RF_SMEM);

    static cudaStream_t s2 = nullptr;
    static cudaEvent_t eF = nullptr, eW2 = nullptr, eWD = nullptr, eQ = nullptr, eS = nullptr;
    if (s2 == nullptr) {
        cudaStreamCreateWithFlags(&s2, cudaStreamNonBlocking);
        cudaEventCreateWithFlags(&eF,  cudaEventDisableTiming);
        cudaEventCreateWithFlags(&eW2, cudaEventDisableTiming);
        cudaEventCreateWithFlags(&eWD, cudaEventDisableTiming);
        cudaEventCreateWithFlags(&eQ,  cudaEventDisableTiming);
        cudaEventCreateWithFlags(&eS,  cudaEventDisableTiming);
    }

    init_kernel<<<1, 256>>>(counts, qlat, contra, recon, ncand);
    cudaEventRecord(eF, 0);
    cudaStreamWaitEvent(s2, eF, 0);

    // side stream: weight conversions + seeds (hidden under enc1)
    conv_w_kernel<<<((size_t)H2D * KA2 + 255) / 256, 256, 0, s2>>>(enc_w2, 16, 512, H2D, B2, KP2, KA2);
    z_init_kernel<<<((size_t)NROWS * ED + 255) / 256, 256, 0, s2>>>(enc_b3, z);
    cudaEventRecord(eW2, s2);
    conv_w_kernel<<<((size_t)H2D * KA1 + 255) / 256, 256, 0, s2>>>(dec_w1, 16, 272, H2D, B3, KP1, KA1);
    conv_w_kernel<<<((size_t)H1D * KA4 + 255) / 256, 256, 0, s2>>>(dec_w2, 16, 256, H1D, B4, KP4, KA4);
    rec_init_kernel<<<((size_t)NROWS * ACT_D + 255) / 256, 256, 0, s2>>>(dec_b3, out_rec);
    cudaEventRecord(eWD, s2);

    // main: encoder
    conv_w_kernel<<<((size_t)H1D * KA1 + 255) / 256, 256>>>(enc_w1, 12, 268, H1D, B1, KP1, KA1);
    conv_cat_kernel<<<((size_t)NROWS * (KP1 / 2) + 255) / 256, 256>>>(
        actions, ACT_D, conditions, COND_D, A1, KP1, KA1);
    tgemm<KP1, 1, false><<<dim3(4, NROWS / 128), 256, TG_SMEM>>>(
        A1, B1, nullptr, enc_b1, nullptr, nullptr, Ah1, nullptr, KP2);
    cudaStreamWaitEvent(0, eW2, 0);
    tgemm<KP2, 2, false><<<dim3(2, NROWS / 128), 256, TG_SMEM>>>(
        Ah1, B2, nullptr, enc_b2, enc_w3, z, nullptr, nullptr, 0);

    quantize_kernel<<<NROWS / 16, 256>>>(z, embedding, out_q, out_idx, dist, Aq,
                                         counts, qlat, ncand, cand);
    cudaEventRecord(eQ, 0);
    cudaStreamWaitEvent(s2, eQ, 0);
    select_kernel<<<KCB, 256, 0, s2>>>(dist, contra);
    cudaEventRecord(eS, s2);

    refine_kernel<<<2048, 256, RF_SMEM>>>(actions, conditions,
                                 enc_w1, enc_b1, enc_w2, enc_b2, enc_w3, enc_b3,
                                 embedding, z, out_q, out_idx, Aq, counts, qlat, ncand, cand);

    cudaStreamWaitEvent(0, eWD, 0);
    tgemm<KP1, 1, true><<<dim3(2, NROWS / 128), 256, TG_SMEM>>>(
        A1, B3, Aq, dec_b1, nullptr, nullptr, Ad1, nullptr, KP4);
    tgemm<KP4, 3, false><<<dim3(4, NROWS / 128), 256, TG_SMEM>>>(
        Ad1, B4, nullptr, dec_b2, dec_w3, nullptr, nullptr, out_rec, 0);
    recon_kernel<<<1024, 256>>>(out_rec, actions, recon);

    cudaStreamWaitEvent(0, eS, 0);
    finalize_kernel<<<1, 256>>>(counts, qlat, contra, recon, out_sc);
}